// round 8
// baseline (speedup 1.0000x reference)
#include <cuda_runtime.h>
#include <cuda_bf16.h>
#include <cstdint>

#define NN 65536      // nodes
#define NB 128        // graphs
#define NE 65536      // raw directed edges
#define E2 131072     // TD + BU
#define ETOT 196608   // + self loops
#define DIN 512

// ------------------------- scratch (device globals; no allocs) ---------------
__device__ float g_h1 [NN * 128];   // PLA1 output
__device__ float g_hf [NN * 256];   // GAT lin output (reused layer1 & layer2)
__device__ float g_xr [NN * 256];   // relu(GAT1 out)
__device__ float g_x3 [NN * 512];   // PLA2 output
__device__ float g_xr2[NN * 64];    // relu(GAT2 out)
__device__ float g_asrc[NN * 4];
__device__ float g_adst[NN * 4];
__device__ float g_hc1[NB * 64];
__device__ float g_hc2[NB * 64];
__device__ float g_gsum[NB * 128];
__device__ int   g_deg[NN];
__device__ int   g_rp [NN + 1];
__device__ int   g_cursor[NN];
__device__ int   g_col[ETOT];
__device__ int   g_bsum[64];

// ------------------------- helpers -------------------------------------------
__device__ __forceinline__ uint32_t smem_u32(const void* p) {
    uint32_t a;
    asm("{ .reg .u64 t; cvta.to.shared.u64 t, %1; cvt.u32.u64 %0, t; }" : "=r"(a) : "l"(p));
    return a;
}
__device__ __forceinline__ void ldmat4(uint32_t& r0, uint32_t& r1, uint32_t& r2,
                                       uint32_t& r3, uint32_t addr) {
    asm volatile("ldmatrix.sync.aligned.m8n8.x4.shared.b16 {%0,%1,%2,%3}, [%4];"
        : "=r"(r0), "=r"(r1), "=r"(r2), "=r"(r3) : "r"(addr));
}
__device__ __forceinline__ void mma_bf16(float* c, const uint32_t* a, const uint32_t* b) {
    asm volatile("mma.sync.aligned.m16n8k16.row.col.f32.bf16.bf16.f32 "
        "{%0,%1,%2,%3}, {%4,%5,%6,%7}, {%8,%9}, {%0,%1,%2,%3};"
        : "+f"(c[0]), "+f"(c[1]), "+f"(c[2]), "+f"(c[3])
        : "r"(a[0]), "r"(a[1]), "r"(a[2]), "r"(a[3]), "r"(b[0]), "r"(b[1]));
}
__device__ __forceinline__ uint32_t pack_hi(float a, float b) {
    __nv_bfloat162 t = __floats2bfloat162_rn(a, b);
    return *reinterpret_cast<uint32_t*>(&t);
}
__device__ __forceinline__ uint32_t pack_lo(float a, float b) {
    float ra = a - __bfloat162float(__float2bfloat16(a));
    float rb = b - __bfloat162float(__float2bfloat16(b));
    __nv_bfloat162 t = __floats2bfloat162_rn(ra, rb);
    return *reinterpret_cast<uint32_t*>(&t);
}

// ------------------------- CSR build -----------------------------------------
__global__ void k_deg_init() { g_deg[blockIdx.x * 256 + threadIdx.x] = 1; }

__global__ void k_deg(const int* __restrict__ ei) {
    int i = blockIdx.x * 256 + threadIdx.x;
    int d = (i < NE) ? ei[NE + i] : ei[i - NE];
    atomicAdd(&g_deg[d], 1);
}

__global__ void k_scan1() {
    __shared__ int wsum[32];
    int tid = threadIdx.x, lane = tid & 31, wid = tid >> 5;
    int i = blockIdx.x * 1024 + tid;
    int v = g_deg[i];
    int x = v;
#pragma unroll
    for (int o = 1; o < 32; o <<= 1) {
        int y = __shfl_up_sync(0xffffffffu, x, o);
        if (lane >= o) x += y;
    }
    if (lane == 31) wsum[wid] = x;
    __syncthreads();
    if (wid == 0) {
        int s = wsum[lane];
#pragma unroll
        for (int o = 1; o < 32; o <<= 1) {
            int y = __shfl_up_sync(0xffffffffu, s, o);
            if (lane >= o) s += y;
        }
        wsum[lane] = s;
    }
    __syncthreads();
    int base = wid ? wsum[wid - 1] : 0;
    g_rp[i] = base + x - v;
    if (tid == 1023) g_bsum[blockIdx.x] = wsum[31];
}

__global__ void k_scan2() {
    __shared__ int s[64];
    int t = threadIdx.x;
    s[t] = g_bsum[t];
    __syncthreads();
    if (t == 0) {
        int acc = 0;
        for (int i = 0; i < 64; i++) { int v = s[i]; s[i] = acc; acc += v; }
    }
    __syncthreads();
    g_bsum[t] = s[t];
}

__global__ void k_scan3() {
    int i = blockIdx.x * 256 + threadIdx.x;
    int v = g_rp[i] + g_bsum[i >> 10];
    g_rp[i] = v;
    g_cursor[i] = v;
    if (i == 0) g_rp[NN] = ETOT;
}

__global__ void k_scatter(const int* __restrict__ ei) {
    int i = blockIdx.x * 256 + threadIdx.x;
    int s, d;
    if (i < NE)        { s = ei[i];          d = ei[NE + i]; }
    else if (i < E2)   { int e = i - NE; s = ei[NE + e]; d = ei[e]; }
    else               { s = d = i - E2; }
    int pos = atomicAdd(&g_cursor[d], 1);
    g_col[pos] = s;
}

// ------------------------- root projections ----------------------------------
__global__ void k_rootproj(const float* __restrict__ root,
                           const float* __restrict__ Wc1,
                           const float* __restrict__ Wc2) {
    int b = blockIdx.x, c = threadIdx.x;
    float a1 = 0.f, a2 = 0.f;
    for (int k = 0; k < DIN; k++) {
        float rv = root[b * DIN + k];
        a1 += rv * Wc1[k * 64 + c];
        a2 += rv * Wc2[k * 64 + c];
    }
    g_hc1[b * 64 + c] = a1;
    g_hc2[b * 64 + c] = a2;
}

// ------------------------- split-bf16 mma.sync GEMM --------------------------
// MODE 0: x    @ W_post1 [512->64]  -> PLA1 gate -> g_h1  (NT=64)
// MODE 1: g_h1 @ W1      [128->256] -> g_hf              (NT=128)
// MODE 2: g_xr @ W_post2 [64->64]   -> PLA2 gate -> g_x3 (NT=64)
// MODE 3: g_x3 @ W2      [512->256] -> g_hf              (NT=128)
// Block tile 128 x NT; warp tile 64 x (NT/4); 2x4 warps; K staged 64/iter;
// 3-pass split-bf16 (hi*hi + hi*lo + lo*hi), fp32 register accumulators.
#define LDS 72            // padded smem row stride (bf16 elems): 144B

template <int MODE>
__launch_bounds__(256, ((MODE == 1 || MODE == 3) ? 1 : 2))
__global__ void k_mm(const float* __restrict__ Aarg, const float* __restrict__ Bw) {
    constexpr int K   = (MODE == 0 || MODE == 3) ? 512 : (MODE == 1 ? 128 : 64);
    constexpr int LDB = (MODE == 1 || MODE == 3) ? 256 : 64;
    constexpr int NT  = (MODE == 1 || MODE == 3) ? 128 : 64;
    constexpr int NF  = NT / 32;         // n-frags per warp (2 or 4)
    constexpr int NP  = NF / 2;          // ldmatrix.x4 pair loads (1 or 2)

    extern __shared__ __align__(16) char sm[];
    __nv_bfloat16* Ah = (__nv_bfloat16*)sm;     // [128][LDS]
    __nv_bfloat16* Al = Ah + 128 * LDS;
    __nv_bfloat16* Bh = Al + 128 * LDS;         // [NT][LDS] (n-major)
    __nv_bfloat16* Bl = Bh + NT * LDS;

    int tid = threadIdx.x, lane = tid & 31, w = tid >> 5;
    int wm = (w & 1) * 64, wn = (w >> 1) * (NT / 4);

    const float* Ap = (MODE == 0) ? Aarg
                    : (MODE == 1) ? (const float*)g_h1
                    : (MODE == 2) ? (const float*)g_xr
                                  : (const float*)g_x3;
    const float* Arow = Ap + (size_t)blockIdx.y * 128 * K;
    int n0 = blockIdx.x * NT;

    float acc[4][NF][4];
#pragma unroll
    for (int a = 0; a < 4; a++)
#pragma unroll
        for (int b = 0; b < NF; b++)
#pragma unroll
            for (int c = 0; c < 4; c++) acc[a][b][c] = 0.f;

    for (int k0 = 0; k0 < K; k0 += 64) {
        if (k0) __syncthreads();
        // --- A stage: 128 rows x 64 k, fp32 -> hi/lo bf16 ---
#pragma unroll
        for (int i = 0; i < 8; i++) {
            int idx = i * 256 + tid;              // 2048 float4s
            int r = idx >> 4, c4 = (idx & 15) << 2;
            float4 v = *(const float4*)(Arow + (size_t)r * K + k0 + c4);
            *(uint2*)&Ah[r * LDS + c4] = make_uint2(pack_hi(v.x, v.y), pack_hi(v.z, v.w));
            *(uint2*)&Al[r * LDS + c4] = make_uint2(pack_lo(v.x, v.y), pack_lo(v.z, v.w));
        }
        // --- B stage: 64 k x NT n from W[k][n] -> smem [n][k] ---
#pragma unroll
        for (int i = 0; i < NT / 16; i++) {
            int idx = i * 256 + tid;              // 16*NT float4s
            int kk = idx / (NT / 4);
            int n4 = (idx % (NT / 4)) << 2;
            float4 v = *(const float4*)(Bw + (size_t)(k0 + kk) * LDB + n0 + n4);
            float e[4] = {v.x, v.y, v.z, v.w};
#pragma unroll
            for (int j = 0; j < 4; j++) {
                __nv_bfloat16 h = __float2bfloat16(e[j]);
                Bh[(n4 + j) * LDS + kk] = h;
                Bl[(n4 + j) * LDS + kk] = __float2bfloat16(e[j] - __bfloat162float(h));
            }
        }
        __syncthreads();

#pragma unroll
        for (int ks = 0; ks < 4; ks++) {
            int kb = ks * 16;
            uint32_t ah[4][4], al[4][4], bh[NF][2], bl[NF][2];
            int arow = wm + (lane & 15);
            int acol = kb + (lane >> 4) * 8;
#pragma unroll
            for (int mf = 0; mf < 4; mf++) {
                ldmat4(ah[mf][0], ah[mf][1], ah[mf][2], ah[mf][3],
                       smem_u32(&Ah[(arow + mf * 16) * LDS + acol]));
                ldmat4(al[mf][0], al[mf][1], al[mf][2], al[mf][3],
                       smem_u32(&Al[(arow + mf * 16) * LDS + acol]));
            }
            // B pairs: x4 covers 2 n8-frags; lane groups g=0..3 -> (frag, col-half)
            int g  = lane >> 3;
            int fb = g >> 1;          // 0 or 1 within pair
            int ch = (g & 1) * 8;     // col half
            int rr = lane & 7;
#pragma unroll
            for (int p = 0; p < NP; p++) {
                int frow = wn + (p * 2 + fb) * 8 + rr;
                ldmat4(bh[p * 2][0], bh[p * 2][1], bh[p * 2 + 1][0], bh[p * 2 + 1][1],
                       smem_u32(&Bh[frow * LDS + kb + ch]));
                ldmat4(bl[p * 2][0], bl[p * 2][1], bl[p * 2 + 1][0], bl[p * 2 + 1][1],
                       smem_u32(&Bl[frow * LDS + kb + ch]));
            }
#pragma unroll
            for (int mf = 0; mf < 4; mf++)
#pragma unroll
                for (int nf = 0; nf < NF; nf++) {
                    mma_bf16(acc[mf][nf], ah[mf], bh[nf]);
                    mma_bf16(acc[mf][nf], ah[mf], bl[nf]);
                    mma_bf16(acc[mf][nf], al[mf], bh[nf]);
                }
        }
    }

    // --- epilogue from register accumulators ---
#pragma unroll
    for (int mf = 0; mf < 4; mf++)
#pragma unroll
        for (int nf = 0; nf < NF; nf++)
#pragma unroll
            for (int p = 0; p < 2; p++) {
                int row = blockIdx.y * 128 + wm + mf * 16 + (lane >> 2) + p * 8;
                int c   = wn + nf * 8 + (lane & 3) * 2;
                float v0 = acc[mf][nf][p * 2 + 0];
                float v1 = acc[mf][nf][p * 2 + 1];
                if (MODE == 1 || MODE == 3) {
                    g_hf[(size_t)row * 256 + n0 + c]     = v0;
                    g_hf[(size_t)row * 256 + n0 + c + 1] = v1;
                } else {
                    const float* hcp = (MODE == 0) ? g_hc1 : g_hc2;
                    int gid = row >> ((MODE == 0) ? 9 : 11);
                    float* Cp = (MODE == 0) ? g_h1 : g_x3;
                    float hc0 = hcp[gid * 64 + c];
                    float hc1 = hcp[gid * 64 + c + 1];
                    float gs0 = 1.f / (1.f + __expf(-(v0 + hc0)));
                    float gs1 = 1.f / (1.f + __expf(-(v1 + hc1)));
                    Cp[(size_t)row * 128 + c]          = gs0 * v0 + (1.f - gs0) * hc0;
                    Cp[(size_t)row * 128 + c + 1]      = gs1 * v1 + (1.f - gs1) * hc1;
                    Cp[(size_t)row * 128 + 64 + c]     = v0;
                    Cp[(size_t)row * 128 + 64 + c + 1] = v1;
                }
            }
}

// ------------------------- attention scores ----------------------------------
__launch_bounds__(256)
__global__ void k_scores(const float* __restrict__ as_, const float* __restrict__ ad_) {
    int gw = (blockIdx.x * 256 + threadIdx.x) >> 5;
    int lane = threadIdx.x & 31;
    const float* hr = g_hf + (size_t)gw * 256;
    float ps[4] = {0, 0, 0, 0}, pd[4] = {0, 0, 0, 0};
#pragma unroll
    for (int k = 0; k < 8; k++) {
        int c = lane + 32 * k;
        float v = hr[c];
        ps[k >> 1] += v * as_[c];
        pd[k >> 1] += v * ad_[c];
    }
#pragma unroll
    for (int h = 0; h < 4; h++)
#pragma unroll
        for (int o = 16; o; o >>= 1) {
            ps[h] += __shfl_xor_sync(0xffffffffu, ps[h], o);
            pd[h] += __shfl_xor_sync(0xffffffffu, pd[h], o);
        }
    if (lane == 0) {
#pragma unroll
        for (int h = 0; h < 4; h++) {
            g_asrc[gw * 4 + h] = ps[h];
            g_adst[gw * 4 + h] = pd[h];
        }
    }
}

// ------------------------- GAT aggregation (warp per dst) --------------------
__device__ __forceinline__ float lrelu(float x) { return x > 0.f ? x : 0.2f * x; }

template <int CONCAT>
__launch_bounds__(256)
__global__ void k_agg(const float* __restrict__ bias) {
    int n = (blockIdx.x * 256 + threadIdx.x) >> 5;
    int lane = threadIdx.x & 31;
    int rs = g_rp[n], re = g_rp[n + 1];
    float ad0 = g_adst[n * 4 + 0], ad1 = g_adst[n * 4 + 1];
    float ad2 = g_adst[n * 4 + 2], ad3 = g_adst[n * 4 + 3];

    float m0 = -1e30f, m1 = -1e30f, m2 = -1e30f, m3 = -1e30f;
    for (int j = rs + lane; j < re; j += 32) {
        int s = g_col[j];
        m0 = fmaxf(m0, lrelu(g_asrc[s * 4 + 0] + ad0));
        m1 = fmaxf(m1, lrelu(g_asrc[s * 4 + 1] + ad1));
        m2 = fmaxf(m2, lrelu(g_asrc[s * 4 + 2] + ad2));
        m3 = fmaxf(m3, lrelu(g_asrc[s * 4 + 3] + ad3));
    }
#pragma unroll
    for (int o = 16; o; o >>= 1) {
        m0 = fmaxf(m0, __shfl_xor_sync(0xffffffffu, m0, o));
        m1 = fmaxf(m1, __shfl_xor_sync(0xffffffffu, m1, o));
        m2 = fmaxf(m2, __shfl_xor_sync(0xffffffffu, m2, o));
        m3 = fmaxf(m3, __shfl_xor_sync(0xffffffffu, m3, o));
    }
    float d0 = 0.f, d1 = 0.f, d2 = 0.f, d3 = 0.f;
    for (int j = rs + lane; j < re; j += 32) {
        int s = g_col[j];
        d0 += __expf(lrelu(g_asrc[s * 4 + 0] + ad0) - m0);
        d1 += __expf(lrelu(g_asrc[s * 4 + 1] + ad1) - m1);
        d2 += __expf(lrelu(g_asrc[s * 4 + 2] + ad2) - m2);
        d3 += __expf(lrelu(g_asrc[s * 4 + 3] + ad3) - m3);
    }
#pragma unroll
    for (int o = 16; o; o >>= 1) {
        d0 += __shfl_xor_sync(0xffffffffu, d0, o);
        d1 += __shfl_xor_sync(0xffffffffu, d1, o);
        d2 += __shfl_xor_sync(0xffffffffu, d2, o);
        d3 += __shfl_xor_sync(0xffffffffu, d3, o);
    }
    float i0 = 1.f / d0, i1 = 1.f / d1, i2 = 1.f / d2, i3 = 1.f / d3;

    float acc[8] = {0, 0, 0, 0, 0, 0, 0, 0};
    for (int j = rs; j < re; j++) {
        int s = g_col[j];
        float w0 = __expf(lrelu(g_asrc[s * 4 + 0] + ad0) - m0) * i0;
        float w1 = __expf(lrelu(g_asrc[s * 4 + 1] + ad1) - m1) * i1;
        float w2 = __expf(lrelu(g_asrc[s * 4 + 2] + ad2) - m2) * i2;
        float w3 = __expf(lrelu(g_asrc[s * 4 + 3] + ad3) - m3) * i3;
        const float* hr = g_hf + (size_t)s * 256;
        acc[0] += w0 * hr[lane];       acc[1] += w0 * hr[lane + 32];
        acc[2] += w1 * hr[lane + 64];  acc[3] += w1 * hr[lane + 96];
        acc[4] += w2 * hr[lane + 128]; acc[5] += w2 * hr[lane + 160];
        acc[6] += w3 * hr[lane + 192]; acc[7] += w3 * hr[lane + 224];
    }
    if (CONCAT) {
#pragma unroll
        for (int k = 0; k < 8; k++) {
            int c = lane + 32 * k;
            g_xr[(size_t)n * 256 + c] = fmaxf(acc[k] + bias[c], 0.f);
        }
    } else {
        float o0 = 0.25f * (acc[0] + acc[2] + acc[4] + acc[6]) + bias[lane];
        float o1 = 0.25f * (acc[1] + acc[3] + acc[5] + acc[7]) + bias[lane + 32];
        g_xr2[(size_t)n * 64 + lane]      = fmaxf(o0, 0.f);
        g_xr2[(size_t)n * 64 + lane + 32] = fmaxf(o1, 0.f);
    }
}

// ------------------------- scorer head + pooling -----------------------------
__global__ void k_zero() { g_gsum[blockIdx.x * 256 + threadIdx.x] = 0.f; }

__launch_bounds__(256)
__global__ void k_final(const float* __restrict__ Wfc, const float* __restrict__ bfc) {
    extern __shared__ float Ws[];
    __shared__ float s_hc3[64];
    __shared__ float part_sh[8][64];
    __shared__ float part_ss[8][64];
    int tid = threadIdx.x, lane = tid & 31, w = tid >> 5;
    int g = blockIdx.x >> 1;

    for (int i = tid; i < 4096; i += 256)
        ((float4*)Ws)[i] = ((const float4*)Wfc)[i];
    if (tid < 64) s_hc3[tid] = g_xr2[((size_t)g << 9) * 64 + tid];
    __syncthreads();

    float bL = bfc[lane], bH = bfc[lane + 32];
    float shL = 0.f, shH = 0.f, ssL = 0.f, ssH = 0.f;
    int nbase = blockIdx.x * 256 + w * 32;

    for (int g4 = 0; g4 < 8; g4++) {
        int n0 = nbase + g4 * 4;
        float xl[4], xh[4], aL[4], aH[4];
#pragma unroll
        for (int u = 0; u < 4; u++) {
            xl[u] = g_xr2[(size_t)(n0 + u) * 64 + lane];
            xh[u] = g_xr2[(size_t)(n0 + u) * 64 + lane + 32];
            aL[u] = bL; aH[u] = bH;
        }
#pragma unroll 4
        for (int j = 0; j < 64; j++) {
            float h3 = s_hc3[j];
            float w0 = Ws[j * 64 + lane];
            float w1 = Ws[(64 + j) * 64 + lane];
            float w2 = Ws[(128 + j) * 64 + lane];
            float w3 = Ws[(192 + j) * 64 + lane];
            float v0 = Ws[j * 64 + lane + 32];
            float v1 = Ws[(64 + j) * 64 + lane + 32];
            float v2 = Ws[(128 + j) * 64 + lane + 32];
            float v3 = Ws[(192 + j) * 64 + lane + 32];
#pragma unroll
            for (int u = 0; u < 4; u++) {
                float xj = (j < 32) ? __shfl_sync(0xffffffffu, xl[u], j)
                                    : __shfl_sync(0xffffffffu, xh[u], j - 32);
                float p = xj * h3;
                float q = fabsf(h3 - xj);
                aL[u] += h3 * w0 + xj * w1 + p * w2 + q * w3;
                aH[u] += h3 * v0 + xj * v1 + p * v2 + q * v3;
            }
        }
#pragma unroll
        for (int u = 0; u < 4; u++) {
            float tL = tanhf(aL[u]), tH = tanhf(aH[u]);
            float mx = fmaxf(tL, tH);
#pragma unroll
            for (int o = 16; o; o >>= 1) mx = fmaxf(mx, __shfl_xor_sync(0xffffffffu, mx, o));
            float eL = __expf(tL - mx), eH = __expf(tH - mx);
            float sm = eL + eH;
#pragma unroll
            for (int o = 16; o; o >>= 1) sm += __shfl_xor_sync(0xffffffffu, sm, o);
            float inv = 1.f / sm;
            shL += eL * inv * xl[u]; shH += eH * inv * xh[u];
            ssL += xl[u];            ssH += xh[u];
        }
    }
    part_sh[w][lane] = shL; part_sh[w][lane + 32] = shH;
    part_ss[w][lane] = ssL; part_ss[w][lane + 32] = ssH;
    __syncthreads();
    if (tid < 128) {
        int c = tid & 63;
        float s = 0.f;
        if (tid < 64) {
            for (int ww = 0; ww < 8; ww++) s += part_sh[ww][c];
            atomicAdd(&g_gsum[g * 128 + c], s);
        } else {
            for (int ww = 0; ww < 8; ww++) s += part_ss[ww][c];
            atomicAdd(&g_gsum[g * 128 + 64 + c], s);
        }
    }
}

__global__ void k_logits(const float* __restrict__ Wc, const float* __restrict__ bc,
                         float* __restrict__ out) {
    int b = threadIdx.x;
    float l[4] = {bc[0], bc[1], bc[2], bc[3]};
    const float inv = 1.f / 512.f;
    for (int j = 0; j < 128; j++) {
        float v = g_gsum[b * 128 + j] * inv;
#pragma unroll
        for (int c = 0; c < 4; c++) l[c] += v * Wc[j * 4 + c];
    }
    float mx = fmaxf(fmaxf(l[0], l[1]), fmaxf(l[2], l[3]));
    float s = expf(l[0] - mx) + expf(l[1] - mx) + expf(l[2] - mx) + expf(l[3] - mx);
    float lse = mx + logf(s);
#pragma unroll
    for (int c = 0; c < 4; c++) out[b * 4 + c] = l[c] - lse;
}

// ------------------------- launch --------------------------------------------
extern "C" void kernel_launch(void* const* d_in, const int* in_sizes, int n_in,
                              void* d_out, int out_size) {
    const float* x        = (const float*)d_in[0];
    const float* root     = (const float*)d_in[1];
    const int*   ei       = (const int*)d_in[2];
    const float* W_post1  = (const float*)d_in[5];
    const float* W_claim1 = (const float*)d_in[6];
    const float* W1       = (const float*)d_in[7];
    const float* att_src1 = (const float*)d_in[8];
    const float* att_dst1 = (const float*)d_in[9];
    const float* b1       = (const float*)d_in[10];
    const float* W_post2  = (const float*)d_in[11];
    const float* W_claim2 = (const float*)d_in[12];
    const float* W2       = (const float*)d_in[13];
    const float* att_src2 = (const float*)d_in[14];
    const float* att_dst2 = (const float*)d_in[15];
    const float* b2       = (const float*)d_in[16];
    const float* W_fc     = (const float*)d_in[17];
    const float* b_fc     = (const float*)d_in[18];
    const float* W_clf    = (const float*)d_in[19];
    const float* b_clf    = (const float*)d_in[20];
    float* out = (float*)d_out;

    const int SM64  = (128 * LDS * 2 + 64 * LDS * 2) * 2;    // 55296
    const int SM128 = (128 * LDS * 2 + 128 * LDS * 2) * 2;   // 73728
    cudaFuncSetAttribute(k_final, cudaFuncAttributeMaxDynamicSharedMemorySize, 65536);
    cudaFuncSetAttribute(k_mm<0>, cudaFuncAttributeMaxDynamicSharedMemorySize, SM64);
    cudaFuncSetAttribute(k_mm<1>, cudaFuncAttributeMaxDynamicSharedMemorySize, SM128);
    cudaFuncSetAttribute(k_mm<2>, cudaFuncAttributeMaxDynamicSharedMemorySize, SM64);
    cudaFuncSetAttribute(k_mm<3>, cudaFuncAttributeMaxDynamicSharedMemorySize, SM128);

    // CSR build
    k_deg_init<<<NN / 256, 256>>>();
    k_deg<<<E2 / 256, 256>>>(ei);
    k_scan1<<<64, 1024>>>();
    k_scan2<<<1, 64>>>();
    k_scan3<<<NN / 256, 256>>>();
    k_scatter<<<ETOT / 256, 256>>>(ei);

    k_rootproj<<<NB, 64>>>(root, W_claim1, W_claim2);

    // PLA1 (fused sigmoid gate)
    k_mm<0><<<dim3(1, NN / 128), 256, SM64>>>(x, W_post1);
    // GAT1 linear (128x128 tiles)
    k_mm<1><<<dim3(2, NN / 128), 256, SM128>>>(nullptr, W1);
    k_scores<<<NN * 32 / 256, 256>>>(att_src1, att_dst1);
    k_agg<1><<<NN * 32 / 256, 256>>>(b1);
    // PLA2 (block-diagonal, fused gate)
    k_mm<2><<<dim3(1, NN * 4 / 128), 256, SM64>>>(nullptr, W_post2);
    // GAT2 linear (128x128 tiles)
    k_mm<3><<<dim3(2, NN / 128), 256, SM128>>>(nullptr, W2);
    k_scores<<<NN * 32 / 256, 256>>>(att_src2, att_dst2);
    k_agg<0><<<NN * 32 / 256, 256>>>(b2);

    // scorer head + pooling + classifier
    k_zero<<<NB * 128 / 256, 256>>>();
    k_final<<<NN / 256, 256, 65536>>>(W_fc, b_fc);
    k_logits<<<1, 128>>>(W_clf, b_clf, out);
}

// round 9
// speedup vs baseline: 1.1932x; 1.1932x over previous
#include <cuda_runtime.h>
#include <cuda_bf16.h>
#include <cstdint>

#define NN 65536      // nodes
#define NB 128        // graphs
#define NE 65536      // raw directed edges
#define E2 131072     // TD + BU
#define ETOT 196608   // + self loops
#define DIN 512
#define WTOT 200704   // total weight elements (all 4 matrices)

// ------------------------- scratch (device globals; no allocs) ---------------
__device__ float g_hf [NN * 256];   // GAT lin output (reused layer1 & layer2)
__device__ float g_xr [NN * 256];   // relu(GAT1 out)
__device__ float g_xr2[NN * 64];    // relu(GAT2 out)
__device__ float g_asrc[NN * 4];
__device__ float g_adst[NN * 4];
__device__ float g_hc1[NB * 64];
__device__ float g_hc2[NB * 64];
__device__ float g_gsum[NB * 128];
__device__ int   g_deg[NN];
__device__ int   g_rp [NN + 1];
__device__ int   g_cursor[NN];
__device__ int   g_col[ETOT];
// bf16 hi/lo planes (split-precision operands, converted exactly once)
__device__ __nv_bfloat16 g_h1h[NN * 128], g_h1l[NN * 128];   // PLA1 out (MODE1 A)
__device__ __nv_bfloat16 g_x3h[NN * 512], g_x3l[NN * 512];   // PLA2 out (MODE3 A)
__device__ __nv_bfloat16 g_wth[WTOT],     g_wtl[WTOT];       // transposed weights

// ------------------------- helpers -------------------------------------------
__device__ __forceinline__ uint32_t smem_u32(const void* p) {
    uint32_t a;
    asm("{ .reg .u64 t; cvta.to.shared.u64 t, %1; cvt.u32.u64 %0, t; }" : "=r"(a) : "l"(p));
    return a;
}
__device__ __forceinline__ void ldmat4(uint32_t& r0, uint32_t& r1, uint32_t& r2,
                                       uint32_t& r3, uint32_t addr) {
    asm volatile("ldmatrix.sync.aligned.m8n8.x4.shared.b16 {%0,%1,%2,%3}, [%4];"
        : "=r"(r0), "=r"(r1), "=r"(r2), "=r"(r3) : "r"(addr));
}
__device__ __forceinline__ void ldmat2(uint32_t& r0, uint32_t& r1, uint32_t addr) {
    asm volatile("ldmatrix.sync.aligned.m8n8.x2.shared.b16 {%0,%1}, [%2];"
        : "=r"(r0), "=r"(r1) : "r"(addr));
}
__device__ __forceinline__ void mma_bf16(float* c, const uint32_t* a, const uint32_t* b) {
    asm volatile("mma.sync.aligned.m16n8k16.row.col.f32.bf16.bf16.f32 "
        "{%0,%1,%2,%3}, {%4,%5,%6,%7}, {%8,%9}, {%0,%1,%2,%3};"
        : "+f"(c[0]), "+f"(c[1]), "+f"(c[2]), "+f"(c[3])
        : "r"(a[0]), "r"(a[1]), "r"(a[2]), "r"(a[3]), "r"(b[0]), "r"(b[1]));
}
__device__ __forceinline__ uint32_t pack_hi(float a, float b) {
    __nv_bfloat162 t = __floats2bfloat162_rn(a, b);
    return *reinterpret_cast<uint32_t*>(&t);
}
__device__ __forceinline__ uint32_t pack_lo(float a, float b) {
    float ra = a - __bfloat162float(__float2bfloat16(a));
    float rb = b - __bfloat162float(__float2bfloat16(b));
    __nv_bfloat162 t = __floats2bfloat162_rn(ra, rb);
    return *reinterpret_cast<uint32_t*>(&t);
}

// ------------------------- weight pre-conversion ------------------------------
// Transposed n-major planes: dst = off + n*K + k
//   W_post1 [512][64]  -> off 0      (K=512, N=64)
//   W1      [128][256] -> off 32768  (K=128, N=256)
//   W_post2 [64][64]   -> off 65536  (K=64,  N=64)
//   W2      [512][256] -> off 69632  (K=512, N=256)
__global__ void k_convW(const float* __restrict__ Wa, const float* __restrict__ Wb,
                        const float* __restrict__ Wc, const float* __restrict__ Wd) {
    int idx = blockIdx.x * 256 + threadIdx.x;   // < WTOT exactly
    const float* W; int K, N, local;
    if (idx < 32768)      { W = Wa; K = 512; N = 64;  local = idx; }
    else if (idx < 65536) { W = Wb; K = 128; N = 256; local = idx - 32768; }
    else if (idx < 69632) { W = Wc; K = 64;  N = 64;  local = idx - 65536; }
    else                  { W = Wd; K = 512; N = 256; local = idx - 69632; }
    int n = local / K, k = local - n * K;
    float v = W[(size_t)k * N + n];
    __nv_bfloat16 h = __float2bfloat16(v);
    g_wth[idx] = h;
    g_wtl[idx] = __float2bfloat16(v - __bfloat162float(h));
}

// ------------------------- CSR build -----------------------------------------
__global__ void k_deg_init() { g_deg[blockIdx.x * 256 + threadIdx.x] = 1; }

__global__ void k_deg(const int* __restrict__ ei) {
    int i = blockIdx.x * 256 + threadIdx.x;
    int d = (i < NE) ? ei[NE + i] : ei[i - NE];
    atomicAdd(&g_deg[d], 1);
}

__global__ void k_scan_all() {   // 1 block x 1024; 64 elements per thread
    __shared__ int wsum[32];
    int tid = threadIdx.x, lane = tid & 31, wid = tid >> 5;
    int base = tid * 64;
    int s = 0;
    for (int i = 0; i < 64; i++) s += g_deg[base + i];
    int x = s;
#pragma unroll
    for (int o = 1; o < 32; o <<= 1) {
        int y = __shfl_up_sync(0xffffffffu, x, o);
        if (lane >= o) x += y;
    }
    if (lane == 31) wsum[wid] = x;
    __syncthreads();
    if (wid == 0) {
        int t = wsum[lane];
#pragma unroll
        for (int o = 1; o < 32; o <<= 1) {
            int y = __shfl_up_sync(0xffffffffu, t, o);
            if (lane >= o) t += y;
        }
        wsum[lane] = t;
    }
    __syncthreads();
    int run = (wid ? wsum[wid - 1] : 0) + x - s;
    for (int i = 0; i < 64; i++) {
        int v = g_deg[base + i];
        g_rp[base + i] = run;
        g_cursor[base + i] = run;
        run += v;
    }
    if (tid == 0) g_rp[NN] = ETOT;
}

__global__ void k_scatter(const int* __restrict__ ei) {
    int i = blockIdx.x * 256 + threadIdx.x;
    int s, d;
    if (i < NE)        { s = ei[i];          d = ei[NE + i]; }
    else if (i < E2)   { int e = i - NE; s = ei[NE + e]; d = ei[e]; }
    else               { s = d = i - E2; }
    int pos = atomicAdd(&g_cursor[d], 1);
    g_col[pos] = s;
}

// ------------------------- root projections ----------------------------------
__global__ void k_rootproj(const float* __restrict__ root,
                           const float* __restrict__ Wc1,
                           const float* __restrict__ Wc2) {
    int b = blockIdx.x, c = threadIdx.x;
    float a1 = 0.f, a2 = 0.f;
    for (int k = 0; k < DIN; k++) {
        float rv = root[b * DIN + k];
        a1 += rv * Wc1[k * 64 + c];
        a2 += rv * Wc2[k * 64 + c];
    }
    g_hc1[b * 64 + c] = a1;
    g_hc2[b * 64 + c] = a2;
}

// ------------------------- split-bf16 mma.sync GEMM --------------------------
// MODE 0: x      @ W_post1 -> PLA1 gate -> g_h1 planes   (K=512, NT=64)
// MODE 1: g_h1   @ W1      -> g_hf                       (K=128, NT=64, grid.x=4)
// MODE 2: g_xr   @ W_post2 -> PLA2 gate -> g_x3 planes   (K=64,  NT=64)
// MODE 3: g_x3   @ W2      -> g_hf                       (K=512, NT=64, grid.x=4)
// Block 128x64, warps 2x4 (warp tile 64x16), K staged 64/iter.
// B staging = pure copy from pre-converted planes; A copy for MODE1/3.
#define LDS 72            // padded smem row stride (bf16): 144B

template <int MODE>
__launch_bounds__(256, 2)
__global__ void k_mm(const float* __restrict__ Aarg) {
    constexpr int K    = (MODE == 0 || MODE == 3) ? 512 : (MODE == 1 ? 128 : 64);
    constexpr int WOFF = (MODE == 0) ? 0 : (MODE == 1) ? 32768 : (MODE == 2) ? 65536 : 69632;

    extern __shared__ __align__(16) char sm[];
    __nv_bfloat16* Ah = (__nv_bfloat16*)sm;     // [128][LDS]
    __nv_bfloat16* Al = Ah + 128 * LDS;
    __nv_bfloat16* Bh = Al + 128 * LDS;         // [64][LDS] (n-major)
    __nv_bfloat16* Bl = Bh + 64 * LDS;

    int tid = threadIdx.x, lane = tid & 31, w = tid >> 5;
    int wm = (w & 1) * 64, wn = (w >> 1) * 16;
    int n0 = blockIdx.x * 64;

    float acc[4][2][4];
#pragma unroll
    for (int a = 0; a < 4; a++)
#pragma unroll
        for (int b = 0; b < 2; b++)
#pragma unroll
            for (int c = 0; c < 4; c++) acc[a][b][c] = 0.f;

    for (int k0 = 0; k0 < K; k0 += 64) {
        if (k0) __syncthreads();
        if (MODE == 0 || MODE == 2) {
            // fp32 -> hi/lo conversion (grid.x == 1, so done exactly once)
            const float* Arow = ((MODE == 0) ? Aarg : (const float*)g_xr)
                              + (size_t)blockIdx.y * 128 * K;
#pragma unroll
            for (int i = 0; i < 8; i++) {
                int idx = i * 256 + tid;
                int r = idx >> 4, c4 = (idx & 15) << 2;
                float4 v = *(const float4*)(Arow + (size_t)r * K + k0 + c4);
                *(uint2*)&Ah[r * LDS + c4] = make_uint2(pack_hi(v.x, v.y), pack_hi(v.z, v.w));
                *(uint2*)&Al[r * LDS + c4] = make_uint2(pack_lo(v.x, v.y), pack_lo(v.z, v.w));
            }
        } else {
            // pure copy from producer-written planes
            const __nv_bfloat16* Aph = ((MODE == 1) ? g_h1h : g_x3h)
                                     + (size_t)blockIdx.y * 128 * K;
            const __nv_bfloat16* Apl = ((MODE == 1) ? g_h1l : g_x3l)
                                     + (size_t)blockIdx.y * 128 * K;
#pragma unroll
            for (int i = 0; i < 4; i++) {
                int idx = i * 256 + tid;             // 1024 uint4s per plane
                int r = idx >> 3, c8 = (idx & 7) << 3;
                size_t so = (size_t)r * K + k0 + c8;
                *(uint4*)&Ah[r * LDS + c8] = *(const uint4*)&Aph[so];
                *(uint4*)&Al[r * LDS + c8] = *(const uint4*)&Apl[so];
            }
        }
        // B: pure copy from transposed weight planes [n][K]
#pragma unroll
        for (int i = 0; i < 2; i++) {
            int idx = i * 256 + tid;                 // 512 uint4s per plane
            int n = idx >> 3, c8 = (idx & 7) << 3;
            size_t so = (size_t)WOFF + (size_t)(n0 + n) * K + k0 + c8;
            *(uint4*)&Bh[n * LDS + c8] = *(const uint4*)&g_wth[so];
            *(uint4*)&Bl[n * LDS + c8] = *(const uint4*)&g_wtl[so];
        }
        __syncthreads();

#pragma unroll
        for (int ks = 0; ks < 4; ks++) {
            int kb = ks * 16;
            uint32_t ah[4][4], al[4][4], bh[2][2], bl[2][2];
            int arow = wm + (lane & 15);
            int acol = kb + (lane >> 4) * 8;
#pragma unroll
            for (int mf = 0; mf < 4; mf++) {
                ldmat4(ah[mf][0], ah[mf][1], ah[mf][2], ah[mf][3],
                       smem_u32(&Ah[(arow + mf * 16) * LDS + acol]));
                ldmat4(al[mf][0], al[mf][1], al[mf][2], al[mf][3],
                       smem_u32(&Al[(arow + mf * 16) * LDS + acol]));
            }
            int brow = wn + (lane & 7);
            int bcol = kb + ((lane >> 3) & 1) * 8;
#pragma unroll
            for (int nf = 0; nf < 2; nf++) {
                ldmat2(bh[nf][0], bh[nf][1], smem_u32(&Bh[(brow + nf * 8) * LDS + bcol]));
                ldmat2(bl[nf][0], bl[nf][1], smem_u32(&Bl[(brow + nf * 8) * LDS + bcol]));
            }
#pragma unroll
            for (int mf = 0; mf < 4; mf++)
#pragma unroll
                for (int nf = 0; nf < 2; nf++) {
                    mma_bf16(acc[mf][nf], ah[mf], bh[nf]);
                    mma_bf16(acc[mf][nf], ah[mf], bl[nf]);
                    mma_bf16(acc[mf][nf], al[mf], bh[nf]);
                }
        }
    }

    // --- epilogue ---
#pragma unroll
    for (int mf = 0; mf < 4; mf++)
#pragma unroll
        for (int nf = 0; nf < 2; nf++)
#pragma unroll
            for (int p = 0; p < 2; p++) {
                int row = blockIdx.y * 128 + wm + mf * 16 + (lane >> 2) + p * 8;
                int c   = wn + nf * 8 + (lane & 3) * 2;
                float v0 = acc[mf][nf][p * 2 + 0];
                float v1 = acc[mf][nf][p * 2 + 1];
                if (MODE == 1 || MODE == 3) {
                    g_hf[(size_t)row * 256 + n0 + c]     = v0;
                    g_hf[(size_t)row * 256 + n0 + c + 1] = v1;
                } else {
                    const float* hcp = (MODE == 0) ? g_hc1 : g_hc2;
                    int gid = row >> ((MODE == 0) ? 9 : 11);
                    float hc0 = hcp[gid * 64 + c];
                    float hc1 = hcp[gid * 64 + c + 1];
                    float gs0 = 1.f / (1.f + __expf(-(v0 + hc0)));
                    float gs1 = 1.f / (1.f + __expf(-(v1 + hc1)));
                    float gv0 = gs0 * v0 + (1.f - gs0) * hc0;
                    float gv1 = gs1 * v1 + (1.f - gs1) * hc1;
                    __nv_bfloat16* Ph = (MODE == 0) ? g_h1h : g_x3h;
                    __nv_bfloat16* Pl = (MODE == 0) ? g_h1l : g_x3l;
                    size_t b0 = (size_t)row * 128 + c;
                    *(uint32_t*)&Ph[b0]      = pack_hi(gv0, gv1);
                    *(uint32_t*)&Pl[b0]      = pack_lo(gv0, gv1);
                    *(uint32_t*)&Ph[b0 + 64] = pack_hi(v0, v1);
                    *(uint32_t*)&Pl[b0 + 64] = pack_lo(v0, v1);
                }
            }
}

// ------------------------- attention scores ----------------------------------
__launch_bounds__(256)
__global__ void k_scores(const float* __restrict__ as_, const float* __restrict__ ad_) {
    int gw = (blockIdx.x * 256 + threadIdx.x) >> 5;
    int lane = threadIdx.x & 31;
    const float* hr = g_hf + (size_t)gw * 256;
    float ps[4] = {0, 0, 0, 0}, pd[4] = {0, 0, 0, 0};
#pragma unroll
    for (int k = 0; k < 8; k++) {
        int c = lane + 32 * k;
        float v = hr[c];
        ps[k >> 1] += v * as_[c];
        pd[k >> 1] += v * ad_[c];
    }
#pragma unroll
    for (int h = 0; h < 4; h++)
#pragma unroll
        for (int o = 16; o; o >>= 1) {
            ps[h] += __shfl_xor_sync(0xffffffffu, ps[h], o);
            pd[h] += __shfl_xor_sync(0xffffffffu, pd[h], o);
        }
    if (lane == 0) {
#pragma unroll
        for (int h = 0; h < 4; h++) {
            g_asrc[gw * 4 + h] = ps[h];
            g_adst[gw * 4 + h] = pd[h];
        }
    }
}

// ------------------------- GAT aggregation (warp per dst) --------------------
__device__ __forceinline__ float lrelu(float x) { return x > 0.f ? x : 0.2f * x; }

template <int CONCAT>
__launch_bounds__(256)
__global__ void k_agg(const float* __restrict__ bias) {
    int n = (blockIdx.x * 256 + threadIdx.x) >> 5;
    int lane = threadIdx.x & 31;
    int rs = g_rp[n], re = g_rp[n + 1];
    float ad0 = g_adst[n * 4 + 0], ad1 = g_adst[n * 4 + 1];
    float ad2 = g_adst[n * 4 + 2], ad3 = g_adst[n * 4 + 3];

    float m0 = -1e30f, m1 = -1e30f, m2 = -1e30f, m3 = -1e30f;
    for (int j = rs + lane; j < re; j += 32) {
        int s = g_col[j];
        m0 = fmaxf(m0, lrelu(g_asrc[s * 4 + 0] + ad0));
        m1 = fmaxf(m1, lrelu(g_asrc[s * 4 + 1] + ad1));
        m2 = fmaxf(m2, lrelu(g_asrc[s * 4 + 2] + ad2));
        m3 = fmaxf(m3, lrelu(g_asrc[s * 4 + 3] + ad3));
    }
#pragma unroll
    for (int o = 16; o; o >>= 1) {
        m0 = fmaxf(m0, __shfl_xor_sync(0xffffffffu, m0, o));
        m1 = fmaxf(m1, __shfl_xor_sync(0xffffffffu, m1, o));
        m2 = fmaxf(m2, __shfl_xor_sync(0xffffffffu, m2, o));
        m3 = fmaxf(m3, __shfl_xor_sync(0xffffffffu, m3, o));
    }
    float d0 = 0.f, d1 = 0.f, d2 = 0.f, d3 = 0.f;
    for (int j = rs + lane; j < re; j += 32) {
        int s = g_col[j];
        d0 += __expf(lrelu(g_asrc[s * 4 + 0] + ad0) - m0);
        d1 += __expf(lrelu(g_asrc[s * 4 + 1] + ad1) - m1);
        d2 += __expf(lrelu(g_asrc[s * 4 + 2] + ad2) - m2);
        d3 += __expf(lrelu(g_asrc[s * 4 + 3] + ad3) - m3);
    }
#pragma unroll
    for (int o = 16; o; o >>= 1) {
        d0 += __shfl_xor_sync(0xffffffffu, d0, o);
        d1 += __shfl_xor_sync(0xffffffffu, d1, o);
        d2 += __shfl_xor_sync(0xffffffffu, d2, o);
        d3 += __shfl_xor_sync(0xffffffffu, d3, o);
    }
    float i0 = 1.f / d0, i1 = 1.f / d1, i2 = 1.f / d2, i3 = 1.f / d3;

    float acc[8] = {0, 0, 0, 0, 0, 0, 0, 0};
    for (int j = rs; j < re; j++) {
        int s = g_col[j];
        float w0 = __expf(lrelu(g_asrc[s * 4 + 0] + ad0) - m0) * i0;
        float w1 = __expf(lrelu(g_asrc[s * 4 + 1] + ad1) - m1) * i1;
        float w2 = __expf(lrelu(g_asrc[s * 4 + 2] + ad2) - m2) * i2;
        float w3 = __expf(lrelu(g_asrc[s * 4 + 3] + ad3) - m3) * i3;
        const float* hr = g_hf + (size_t)s * 256;
        acc[0] += w0 * hr[lane];       acc[1] += w0 * hr[lane + 32];
        acc[2] += w1 * hr[lane + 64];  acc[3] += w1 * hr[lane + 96];
        acc[4] += w2 * hr[lane + 128]; acc[5] += w2 * hr[lane + 160];
        acc[6] += w3 * hr[lane + 192]; acc[7] += w3 * hr[lane + 224];
    }
    if (CONCAT) {
#pragma unroll
        for (int k = 0; k < 8; k++) {
            int c = lane + 32 * k;
            g_xr[(size_t)n * 256 + c] = fmaxf(acc[k] + bias[c], 0.f);
        }
    } else {
        float o0 = 0.25f * (acc[0] + acc[2] + acc[4] + acc[6]) + bias[lane];
        float o1 = 0.25f * (acc[1] + acc[3] + acc[5] + acc[7]) + bias[lane + 32];
        g_xr2[(size_t)n * 64 + lane]      = fmaxf(o0, 0.f);
        g_xr2[(size_t)n * 64 + lane + 32] = fmaxf(o1, 0.f);
    }
}

// ------------------------- scorer head + pooling -----------------------------
__global__ void k_zero() { g_gsum[blockIdx.x * 256 + threadIdx.x] = 0.f; }

__launch_bounds__(256)
__global__ void k_final(const float* __restrict__ Wfc, const float* __restrict__ bfc) {
    extern __shared__ float Ws[];
    __shared__ float s_hc3[64];
    __shared__ float part_sh[8][64];
    __shared__ float part_ss[8][64];
    int tid = threadIdx.x, lane = tid & 31, w = tid >> 5;
    int g = blockIdx.x >> 1;

    for (int i = tid; i < 4096; i += 256)
        ((float4*)Ws)[i] = ((const float4*)Wfc)[i];
    if (tid < 64) s_hc3[tid] = g_xr2[((size_t)g << 9) * 64 + tid];
    __syncthreads();

    float bL = bfc[lane], bH = bfc[lane + 32];
    float shL = 0.f, shH = 0.f, ssL = 0.f, ssH = 0.f;
    int nbase = blockIdx.x * 256 + w * 32;

    for (int g4 = 0; g4 < 8; g4++) {
        int n0 = nbase + g4 * 4;
        float xl[4], xh[4], aL[4], aH[4];
#pragma unroll
        for (int u = 0; u < 4; u++) {
            xl[u] = g_xr2[(size_t)(n0 + u) * 64 + lane];
            xh[u] = g_xr2[(size_t)(n0 + u) * 64 + lane + 32];
            aL[u] = bL; aH[u] = bH;
        }
#pragma unroll 4
        for (int j = 0; j < 64; j++) {
            float h3 = s_hc3[j];
            float w0 = Ws[j * 64 + lane];
            float w1 = Ws[(64 + j) * 64 + lane];
            float w2 = Ws[(128 + j) * 64 + lane];
            float w3 = Ws[(192 + j) * 64 + lane];
            float v0 = Ws[j * 64 + lane + 32];
            float v1 = Ws[(64 + j) * 64 + lane + 32];
            float v2 = Ws[(128 + j) * 64 + lane + 32];
            float v3 = Ws[(192 + j) * 64 + lane + 32];
#pragma unroll
            for (int u = 0; u < 4; u++) {
                float xj = (j < 32) ? __shfl_sync(0xffffffffu, xl[u], j)
                                    : __shfl_sync(0xffffffffu, xh[u], j - 32);
                float p = xj * h3;
                float q = fabsf(h3 - xj);
                aL[u] += h3 * w0 + xj * w1 + p * w2 + q * w3;
                aH[u] += h3 * v0 + xj * v1 + p * v2 + q * v3;
            }
        }
#pragma unroll
        for (int u = 0; u < 4; u++) {
            float tL = tanhf(aL[u]), tH = tanhf(aH[u]);
            float mx = fmaxf(tL, tH);
#pragma unroll
            for (int o = 16; o; o >>= 1) mx = fmaxf(mx, __shfl_xor_sync(0xffffffffu, mx, o));
            float eL = __expf(tL - mx), eH = __expf(tH - mx);
            float sm = eL + eH;
#pragma unroll
            for (int o = 16; o; o >>= 1) sm += __shfl_xor_sync(0xffffffffu, sm, o);
            float inv = 1.f / sm;
            shL += eL * inv * xl[u]; shH += eH * inv * xh[u];
            ssL += xl[u];            ssH += xh[u];
        }
    }
    part_sh[w][lane] = shL; part_sh[w][lane + 32] = shH;
    part_ss[w][lane] = ssL; part_ss[w][lane + 32] = ssH;
    __syncthreads();
    if (tid < 128) {
        int c = tid & 63;
        float s = 0.f;
        if (tid < 64) {
            for (int ww = 0; ww < 8; ww++) s += part_sh[ww][c];
            atomicAdd(&g_gsum[g * 128 + c], s);
        } else {
            for (int ww = 0; ww < 8; ww++) s += part_ss[ww][c];
            atomicAdd(&g_gsum[g * 128 + 64 + c], s);
        }
    }
}

__global__ void k_logits(const float* __restrict__ Wc, const float* __restrict__ bc,
                         float* __restrict__ out) {
    int b = threadIdx.x;
    float l[4] = {bc[0], bc[1], bc[2], bc[3]};
    const float inv = 1.f / 512.f;
    for (int j = 0; j < 128; j++) {
        float v = g_gsum[b * 128 + j] * inv;
#pragma unroll
        for (int c = 0; c < 4; c++) l[c] += v * Wc[j * 4 + c];
    }
    float mx = fmaxf(fmaxf(l[0], l[1]), fmaxf(l[2], l[3]));
    float s = expf(l[0] - mx) + expf(l[1] - mx) + expf(l[2] - mx) + expf(l[3] - mx);
    float lse = mx + logf(s);
#pragma unroll
    for (int c = 0; c < 4; c++) out[b * 4 + c] = l[c] - lse;
}

// ------------------------- launch --------------------------------------------
extern "C" void kernel_launch(void* const* d_in, const int* in_sizes, int n_in,
                              void* d_out, int out_size) {
    const float* x        = (const float*)d_in[0];
    const float* root     = (const float*)d_in[1];
    const int*   ei       = (const int*)d_in[2];
    const float* W_post1  = (const float*)d_in[5];
    const float* W_claim1 = (const float*)d_in[6];
    const float* W1       = (const float*)d_in[7];
    const float* att_src1 = (const float*)d_in[8];
    const float* att_dst1 = (const float*)d_in[9];
    const float* b1       = (const float*)d_in[10];
    const float* W_post2  = (const float*)d_in[11];
    const float* W_claim2 = (const float*)d_in[12];
    const float* W2       = (const float*)d_in[13];
    const float* att_src2 = (const float*)d_in[14];
    const float* att_dst2 = (const float*)d_in[15];
    const float* b2       = (const float*)d_in[16];
    const float* W_fc     = (const float*)d_in[17];
    const float* b_fc     = (const float*)d_in[18];
    const float* W_clf    = (const float*)d_in[19];
    const float* b_clf    = (const float*)d_in[20];
    float* out = (float*)d_out;

    const int SMM = (128 * LDS * 2 + 64 * LDS * 2) * 2;   // 55296 bytes
    cudaFuncSetAttribute(k_final, cudaFuncAttributeMaxDynamicSharedMemorySize, 65536);
    cudaFuncSetAttribute(k_mm<0>, cudaFuncAttributeMaxDynamicSharedMemorySize, SMM);
    cudaFuncSetAttribute(k_mm<1>, cudaFuncAttributeMaxDynamicSharedMemorySize, SMM);
    cudaFuncSetAttribute(k_mm<2>, cudaFuncAttributeMaxDynamicSharedMemorySize, SMM);
    cudaFuncSetAttribute(k_mm<3>, cudaFuncAttributeMaxDynamicSharedMemorySize, SMM);

    // ordered so launch index 3 (ncu capture slot) is k_mm<0>
    k_rootproj<<<NB, 64>>>(root, W_claim1, W_claim2);            // 0
    k_deg_init<<<NN / 256, 256>>>();                             // 1
    k_convW<<<WTOT / 256, 256>>>(W_post1, W1, W_post2, W2);      // 2
    k_mm<0><<<dim3(1, NN / 128), 256, SMM>>>(x);                 // 3  PLA1
    k_deg<<<E2 / 256, 256>>>(ei);                                // 4
    k_scan_all<<<1, 1024>>>();                                   // 5
    k_scatter<<<ETOT / 256, 256>>>(ei);                          // 6

    k_mm<1><<<dim3(4, NN / 128), 256, SMM>>>(nullptr);           // GAT1 lin
    k_scores<<<NN * 32 / 256, 256>>>(att_src1, att_dst1);
    k_agg<1><<<NN * 32 / 256, 256>>>(b1);
    k_mm<2><<<dim3(1, NN * 4 / 128), 256, SMM>>>(nullptr);       // PLA2
    k_mm<3><<<dim3(4, NN / 128), 256, SMM>>>(nullptr);           // GAT2 lin
    k_scores<<<NN * 32 / 256, 256>>>(att_src2, att_dst2);
    k_agg<0><<<NN * 32 / 256, 256>>>(b2);

    k_zero<<<NB * 128 / 256, 256>>>();
    k_final<<<NN / 256, 256, 65536>>>(W_fc, b_fc);
    k_logits<<<1, 128>>>(W_clf, b_clf, out);
}

// round 10
// speedup vs baseline: 1.2054x; 1.0102x over previous
#include <cuda_runtime.h>
#include <cuda_bf16.h>
#include <cstdint>

#define NN 65536      // nodes
#define NB 128        // graphs
#define NE 65536      // raw directed edges
#define E2 131072     // TD + BU
#define ETOT 196608   // + self loops
#define DIN 512
#define WTOT 200704   // total weight elements (all 4 matrices)

// ------------------------- scratch (device globals; no allocs) ---------------
__device__ float g_hf [NN * 256];   // GAT lin output (reused layer1 & layer2)
__device__ float g_xr2[NN * 64];    // relu(GAT2 out)
__device__ float g_asrc[NN * 4];
__device__ float g_adst[NN * 4];
__device__ float g_hc1[NB * 64];
__device__ float g_hc2[NB * 64];
__device__ float g_gsum[NB * 128];
__device__ int   g_deg[NN];
__device__ int   g_rp [NN + 1];
__device__ int   g_cursor[NN];
__device__ int   g_col[ETOT];
// bf16 hi/lo planes (split-precision operands, converted exactly once)
__device__ __nv_bfloat16 g_h1h[NN * 128], g_h1l[NN * 128];   // PLA1 out (MODE1 A)
__device__ __nv_bfloat16 g_xrh[NN * 256], g_xrl[NN * 256];   // relu(GAT1) (MODE2 A)
__device__ __nv_bfloat16 g_x3h[NN * 512], g_x3l[NN * 512];   // PLA2 out (MODE3 A)
__device__ __nv_bfloat16 g_wth[WTOT],     g_wtl[WTOT];       // transposed weights

// ------------------------- helpers -------------------------------------------
__device__ __forceinline__ uint32_t smem_u32(const void* p) {
    uint32_t a;
    asm("{ .reg .u64 t; cvta.to.shared.u64 t, %1; cvt.u32.u64 %0, t; }" : "=r"(a) : "l"(p));
    return a;
}
__device__ __forceinline__ void ldmat4(uint32_t& r0, uint32_t& r1, uint32_t& r2,
                                       uint32_t& r3, uint32_t addr) {
    asm volatile("ldmatrix.sync.aligned.m8n8.x4.shared.b16 {%0,%1,%2,%3}, [%4];"
        : "=r"(r0), "=r"(r1), "=r"(r2), "=r"(r3) : "r"(addr));
}
__device__ __forceinline__ void ldmat2(uint32_t& r0, uint32_t& r1, uint32_t addr) {
    asm volatile("ldmatrix.sync.aligned.m8n8.x2.shared.b16 {%0,%1}, [%2];"
        : "=r"(r0), "=r"(r1) : "r"(addr));
}
__device__ __forceinline__ void mma_bf16(float* c, const uint32_t* a, const uint32_t* b) {
    asm volatile("mma.sync.aligned.m16n8k16.row.col.f32.bf16.bf16.f32 "
        "{%0,%1,%2,%3}, {%4,%5,%6,%7}, {%8,%9}, {%0,%1,%2,%3};"
        : "+f"(c[0]), "+f"(c[1]), "+f"(c[2]), "+f"(c[3])
        : "r"(a[0]), "r"(a[1]), "r"(a[2]), "r"(a[3]), "r"(b[0]), "r"(b[1]));
}
__device__ __forceinline__ uint32_t pack_hi(float a, float b) {
    __nv_bfloat162 t = __floats2bfloat162_rn(a, b);
    return *reinterpret_cast<uint32_t*>(&t);
}
__device__ __forceinline__ uint32_t pack_lo(float a, float b) {
    float ra = a - __bfloat162float(__float2bfloat16(a));
    float rb = b - __bfloat162float(__float2bfloat16(b));
    __nv_bfloat162 t = __floats2bfloat162_rn(ra, rb);
    return *reinterpret_cast<uint32_t*>(&t);
}
#define CP16(dst, src) \
    asm volatile("cp.async.cg.shared.global [%0], [%1], 16;" :: "r"(dst), "l"(src))
#define CPCOMMIT() asm volatile("cp.async.commit_group;" ::: "memory")
#define CPWAIT0()  asm volatile("cp.async.wait_group 0;" ::: "memory")
#define CPWAIT1()  asm volatile("cp.async.wait_group 1;" ::: "memory")

// ------------------------- weight pre-conversion ------------------------------
// Transposed n-major planes: dst = off + n*K + k
//   W_post1 [512][64]  -> off 0      | W1 [128][256] -> off 32768
//   W_post2 [64][64]   -> off 65536  | W2 [512][256] -> off 69632
__global__ void k_convW(const float* __restrict__ Wa, const float* __restrict__ Wb,
                        const float* __restrict__ Wc, const float* __restrict__ Wd) {
    int idx = blockIdx.x * 256 + threadIdx.x;
    const float* W; int K, N, local;
    if (idx < 32768)      { W = Wa; K = 512; N = 64;  local = idx; }
    else if (idx < 65536) { W = Wb; K = 128; N = 256; local = idx - 32768; }
    else if (idx < 69632) { W = Wc; K = 64;  N = 64;  local = idx - 65536; }
    else                  { W = Wd; K = 512; N = 256; local = idx - 69632; }
    int n = local / K, k = local - n * K;
    float v = W[(size_t)k * N + n];
    __nv_bfloat16 h = __float2bfloat16(v);
    g_wth[idx] = h;
    g_wtl[idx] = __float2bfloat16(v - __bfloat162float(h));
}

// ------------------------- CSR build -----------------------------------------
__global__ void k_deg_init() { g_deg[blockIdx.x * 256 + threadIdx.x] = 1; }

__global__ void k_deg(const int* __restrict__ ei) {
    int i = blockIdx.x * 256 + threadIdx.x;
    int d = (i < NE) ? ei[NE + i] : ei[i - NE];
    atomicAdd(&g_deg[d], 1);
}

__global__ void k_scan_all() {   // 1 block x 1024; 64 elems/thread
    __shared__ int wsum[32];
    int tid = threadIdx.x, lane = tid & 31, wid = tid >> 5;
    int base = tid * 64;
    int s = 0;
    for (int i = 0; i < 64; i++) s += g_deg[base + i];
    int x = s;
#pragma unroll
    for (int o = 1; o < 32; o <<= 1) {
        int y = __shfl_up_sync(0xffffffffu, x, o);
        if (lane >= o) x += y;
    }
    if (lane == 31) wsum[wid] = x;
    __syncthreads();
    if (wid == 0) {
        int t = wsum[lane];
#pragma unroll
        for (int o = 1; o < 32; o <<= 1) {
            int y = __shfl_up_sync(0xffffffffu, t, o);
            if (lane >= o) t += y;
        }
        wsum[lane] = t;
    }
    __syncthreads();
    int run = (wid ? wsum[wid - 1] : 0) + x - s;
    for (int i = 0; i < 64; i++) {
        int v = g_deg[base + i];
        g_rp[base + i] = run;
        g_cursor[base + i] = run;
        run += v;
    }
    if (tid == 0) g_rp[NN] = ETOT;
}

__global__ void k_scatter(const int* __restrict__ ei) {
    int i = blockIdx.x * 256 + threadIdx.x;
    int s, d;
    if (i < NE)        { s = ei[i];          d = ei[NE + i]; }
    else if (i < E2)   { int e = i - NE; s = ei[NE + e]; d = ei[e]; }
    else               { s = d = i - E2; }
    int pos = atomicAdd(&g_cursor[d], 1);
    g_col[pos] = s;
}

// ------------------------- root projections ----------------------------------
__global__ void k_rootproj(const float* __restrict__ root,
                           const float* __restrict__ Wc1,
                           const float* __restrict__ Wc2) {
    int b = blockIdx.x, c = threadIdx.x;
    float a1 = 0.f, a2 = 0.f;
    for (int k = 0; k < DIN; k++) {
        float rv = root[b * DIN + k];
        a1 += rv * Wc1[k * 64 + c];
        a2 += rv * Wc2[k * 64 + c];
    }
    g_hc1[b * 64 + c] = a1;
    g_hc2[b * 64 + c] = a2;
}

#define LDS 72            // padded smem row stride (bf16): 144B

// ------------------------- MODE0: x @ W_post1 (conversion path) ---------------
__launch_bounds__(256, 2)
__global__ void k_mm0(const float* __restrict__ Aarg) {
    constexpr int K = 512;
    extern __shared__ __align__(16) char sm[];
    __nv_bfloat16* Ah = (__nv_bfloat16*)sm;
    __nv_bfloat16* Al = Ah + 128 * LDS;
    __nv_bfloat16* Bh = Al + 128 * LDS;
    __nv_bfloat16* Bl = Bh + 64 * LDS;

    int tid = threadIdx.x, lane = tid & 31, w = tid >> 5;
    int wm = (w & 1) * 64, wn = (w >> 1) * 16;
    const float* Arow = Aarg + (size_t)blockIdx.y * 128 * K;

    float acc[4][2][4];
#pragma unroll
    for (int a = 0; a < 4; a++)
#pragma unroll
        for (int b = 0; b < 2; b++)
#pragma unroll
            for (int c = 0; c < 4; c++) acc[a][b][c] = 0.f;

    for (int k0 = 0; k0 < K; k0 += 64) {
        if (k0) __syncthreads();
#pragma unroll
        for (int i = 0; i < 8; i++) {
            int idx = i * 256 + tid;
            int r = idx >> 4, c4 = (idx & 15) << 2;
            float4 v = *(const float4*)(Arow + (size_t)r * K + k0 + c4);
            *(uint2*)&Ah[r * LDS + c4] = make_uint2(pack_hi(v.x, v.y), pack_hi(v.z, v.w));
            *(uint2*)&Al[r * LDS + c4] = make_uint2(pack_lo(v.x, v.y), pack_lo(v.z, v.w));
        }
#pragma unroll
        for (int i = 0; i < 2; i++) {
            int idx = i * 256 + tid;
            int n = idx >> 3, c8 = (idx & 7) << 3;
            size_t so = (size_t)n * K + k0 + c8;   // WOFF = 0
            *(uint4*)&Bh[n * LDS + c8] = *(const uint4*)&g_wth[so];
            *(uint4*)&Bl[n * LDS + c8] = *(const uint4*)&g_wtl[so];
        }
        __syncthreads();
#pragma unroll
        for (int ks = 0; ks < 4; ks++) {
            int kb = ks * 16;
            uint32_t ah[4][4], al[4][4], bh[2][2], bl[2][2];
            int arow = wm + (lane & 15);
            int acol = kb + (lane >> 4) * 8;
#pragma unroll
            for (int mf = 0; mf < 4; mf++) {
                ldmat4(ah[mf][0], ah[mf][1], ah[mf][2], ah[mf][3],
                       smem_u32(&Ah[(arow + mf * 16) * LDS + acol]));
                ldmat4(al[mf][0], al[mf][1], al[mf][2], al[mf][3],
                       smem_u32(&Al[(arow + mf * 16) * LDS + acol]));
            }
            int brow = wn + (lane & 7);
            int bcol = kb + ((lane >> 3) & 1) * 8;
#pragma unroll
            for (int nf = 0; nf < 2; nf++) {
                ldmat2(bh[nf][0], bh[nf][1], smem_u32(&Bh[(brow + nf * 8) * LDS + bcol]));
                ldmat2(bl[nf][0], bl[nf][1], smem_u32(&Bl[(brow + nf * 8) * LDS + bcol]));
            }
#pragma unroll
            for (int mf = 0; mf < 4; mf++)
#pragma unroll
                for (int nf = 0; nf < 2; nf++) {
                    mma_bf16(acc[mf][nf], ah[mf], bh[nf]);
                    mma_bf16(acc[mf][nf], ah[mf], bl[nf]);
                    mma_bf16(acc[mf][nf], al[mf], bh[nf]);
                }
        }
    }
#pragma unroll
    for (int mf = 0; mf < 4; mf++)
#pragma unroll
        for (int nf = 0; nf < 2; nf++)
#pragma unroll
            for (int p = 0; p < 2; p++) {
                int row = blockIdx.y * 128 + wm + mf * 16 + (lane >> 2) + p * 8;
                int c   = wn + nf * 8 + (lane & 3) * 2;
                float v0 = acc[mf][nf][p * 2 + 0];
                float v1 = acc[mf][nf][p * 2 + 1];
                int gid = row >> 9;
                float hc0 = g_hc1[gid * 64 + c];
                float hc1 = g_hc1[gid * 64 + c + 1];
                float gs0 = 1.f / (1.f + __expf(-(v0 + hc0)));
                float gs1 = 1.f / (1.f + __expf(-(v1 + hc1)));
                float gv0 = gs0 * v0 + (1.f - gs0) * hc0;
                float gv1 = gs1 * v1 + (1.f - gs1) * hc1;
                size_t b0 = (size_t)row * 128 + c;
                *(uint32_t*)&g_h1h[b0]      = pack_hi(gv0, gv1);
                *(uint32_t*)&g_h1l[b0]      = pack_lo(gv0, gv1);
                *(uint32_t*)&g_h1h[b0 + 64] = pack_hi(v0, v1);
                *(uint32_t*)&g_h1l[b0 + 64] = pack_lo(v0, v1);
            }
}

// ------------------- MODE 1/2/3: pure-copy, cp.async double-buffered ----------
// MODE 1: g_h1 @ W1      (K=128) -> g_hf            grid(4, 512)
// MODE 2: g_xr @ W_post2 (K=64)  -> PLA2 -> g_x3    grid(1, 2048)
// MODE 3: g_x3 @ W2      (K=512) -> g_hf            grid(4, 512)
template <int MODE>
__launch_bounds__(256, 2)
__global__ void k_mmc() {
    constexpr int K    = (MODE == 3) ? 512 : (MODE == 1 ? 128 : 64);
    constexpr int KT   = K / 64;
    constexpr int WOFF = (MODE == 1) ? 32768 : (MODE == 2) ? 65536 : 69632;
    constexpr int ASZ  = 128 * LDS;
    constexpr int BSZ  = 64 * LDS;
    constexpr int STG  = 2 * ASZ + 2 * BSZ;

    extern __shared__ __align__(16) char sm[];
    __nv_bfloat16* base = (__nv_bfloat16*)sm;

    int tid = threadIdx.x, lane = tid & 31, w = tid >> 5;
    int wm = (w & 1) * 64, wn = (w >> 1) * 16;
    int n0 = blockIdx.x * 64;

    const __nv_bfloat16* Aph = ((MODE == 1) ? g_h1h : (MODE == 2) ? g_xrh : g_x3h)
                             + (size_t)blockIdx.y * 128 * K;
    const __nv_bfloat16* Apl = ((MODE == 1) ? g_h1l : (MODE == 2) ? g_xrl : g_x3l)
                             + (size_t)blockIdx.y * 128 * K;

    float acc[4][2][4];
#pragma unroll
    for (int a = 0; a < 4; a++)
#pragma unroll
        for (int b = 0; b < 2; b++)
#pragma unroll
            for (int c = 0; c < 4; c++) acc[a][b][c] = 0.f;

    auto stage = [&](int k0, int buf) {
        __nv_bfloat16* Ah = base + buf * STG;
        __nv_bfloat16* Al = Ah + ASZ;
        __nv_bfloat16* Bh = Al + ASZ;
        __nv_bfloat16* Bl = Bh + BSZ;
#pragma unroll
        for (int i = 0; i < 4; i++) {
            int idx = i * 256 + tid;
            int r = idx >> 3, c8 = (idx & 7) << 3;
            size_t so = (size_t)r * K + k0 + c8;
            CP16(smem_u32(&Ah[r * LDS + c8]), &Aph[so]);
            CP16(smem_u32(&Al[r * LDS + c8]), &Apl[so]);
        }
#pragma unroll
        for (int i = 0; i < 2; i++) {
            int idx = i * 256 + tid;
            int n = idx >> 3, c8 = (idx & 7) << 3;
            size_t so = (size_t)WOFF + (size_t)(n0 + n) * K + k0 + c8;
            CP16(smem_u32(&Bh[n * LDS + c8]), &g_wth[so]);
            CP16(smem_u32(&Bl[n * LDS + c8]), &g_wtl[so]);
        }
        CPCOMMIT();
    };

    stage(0, 0);
    int buf = 0;
    for (int it = 0; it < KT; it++) {
        if (it + 1 < KT) { stage((it + 1) * 64, buf ^ 1); CPWAIT1(); }
        else             { CPWAIT0(); }
        __syncthreads();
        __nv_bfloat16* Ah = base + buf * STG;
        __nv_bfloat16* Al = Ah + ASZ;
        __nv_bfloat16* Bh = Al + ASZ;
        __nv_bfloat16* Bl = Bh + BSZ;
#pragma unroll
        for (int ks = 0; ks < 4; ks++) {
            int kb = ks * 16;
            uint32_t ah[4][4], al[4][4], bh[2][2], bl[2][2];
            int arow = wm + (lane & 15);
            int acol = kb + (lane >> 4) * 8;
#pragma unroll
            for (int mf = 0; mf < 4; mf++) {
                ldmat4(ah[mf][0], ah[mf][1], ah[mf][2], ah[mf][3],
                       smem_u32(&Ah[(arow + mf * 16) * LDS + acol]));
                ldmat4(al[mf][0], al[mf][1], al[mf][2], al[mf][3],
                       smem_u32(&Al[(arow + mf * 16) * LDS + acol]));
            }
            int brow = wn + (lane & 7);
            int bcol = kb + ((lane >> 3) & 1) * 8;
#pragma unroll
            for (int nf = 0; nf < 2; nf++) {
                ldmat2(bh[nf][0], bh[nf][1], smem_u32(&Bh[(brow + nf * 8) * LDS + bcol]));
                ldmat2(bl[nf][0], bl[nf][1], smem_u32(&Bl[(brow + nf * 8) * LDS + bcol]));
            }
#pragma unroll
            for (int mf = 0; mf < 4; mf++)
#pragma unroll
                for (int nf = 0; nf < 2; nf++) {
                    mma_bf16(acc[mf][nf], ah[mf], bh[nf]);
                    mma_bf16(acc[mf][nf], ah[mf], bl[nf]);
                    mma_bf16(acc[mf][nf], al[mf], bh[nf]);
                }
        }
        __syncthreads();
        buf ^= 1;
    }

#pragma unroll
    for (int mf = 0; mf < 4; mf++)
#pragma unroll
        for (int nf = 0; nf < 2; nf++)
#pragma unroll
            for (int p = 0; p < 2; p++) {
                int row = blockIdx.y * 128 + wm + mf * 16 + (lane >> 2) + p * 8;
                int c   = wn + nf * 8 + (lane & 3) * 2;
                float v0 = acc[mf][nf][p * 2 + 0];
                float v1 = acc[mf][nf][p * 2 + 1];
                if (MODE == 1 || MODE == 3) {
                    g_hf[(size_t)row * 256 + n0 + c]     = v0;
                    g_hf[(size_t)row * 256 + n0 + c + 1] = v1;
                } else {
                    int gid = row >> 11;
                    float hc0 = g_hc2[gid * 64 + c];
                    float hc1 = g_hc2[gid * 64 + c + 1];
                    float gs0 = 1.f / (1.f + __expf(-(v0 + hc0)));
                    float gs1 = 1.f / (1.f + __expf(-(v1 + hc1)));
                    float gv0 = gs0 * v0 + (1.f - gs0) * hc0;
                    float gv1 = gs1 * v1 + (1.f - gs1) * hc1;
                    size_t b0 = (size_t)row * 128 + c;
                    *(uint32_t*)&g_x3h[b0]      = pack_hi(gv0, gv1);
                    *(uint32_t*)&g_x3l[b0]      = pack_lo(gv0, gv1);
                    *(uint32_t*)&g_x3h[b0 + 64] = pack_hi(v0, v1);
                    *(uint32_t*)&g_x3l[b0 + 64] = pack_lo(v0, v1);
                }
            }
}

// ------------------------- attention scores ----------------------------------
__launch_bounds__(256)
__global__ void k_scores(const float* __restrict__ as_, const float* __restrict__ ad_) {
    int gw = (blockIdx.x * 256 + threadIdx.x) >> 5;
    int lane = threadIdx.x & 31;
    const float* hr = g_hf + (size_t)gw * 256;
    float ps[4] = {0, 0, 0, 0}, pd[4] = {0, 0, 0, 0};
#pragma unroll
    for (int k = 0; k < 8; k++) {
        int c = lane + 32 * k;
        float v = hr[c];
        ps[k >> 1] += v * as_[c];
        pd[k >> 1] += v * ad_[c];
    }
#pragma unroll
    for (int h = 0; h < 4; h++)
#pragma unroll
        for (int o = 16; o; o >>= 1) {
            ps[h] += __shfl_xor_sync(0xffffffffu, ps[h], o);
            pd[h] += __shfl_xor_sync(0xffffffffu, pd[h], o);
        }
    if (lane == 0) {
#pragma unroll
        for (int h = 0; h < 4; h++) {
            g_asrc[gw * 4 + h] = ps[h];
            g_adst[gw * 4 + h] = pd[h];
        }
    }
}

// ------------------------- GAT aggregation (warp per dst) --------------------
__device__ __forceinline__ float lrelu(float x) { return x > 0.f ? x : 0.2f * x; }

template <int CONCAT>
__launch_bounds__(256)
__global__ void k_agg(const float* __restrict__ bias) {
    int n = (blockIdx.x * 256 + threadIdx.x) >> 5;
    int lane = threadIdx.x & 31;
    int rs = g_rp[n], re = g_rp[n + 1];
    float ad0 = g_adst[n * 4 + 0], ad1 = g_adst[n * 4 + 1];
    float ad2 = g_adst[n * 4 + 2], ad3 = g_adst[n * 4 + 3];

    float m0 = -1e30f, m1 = -1e30f, m2 = -1e30f, m3 = -1e30f;
    for (int j = rs + lane; j < re; j += 32) {
        int s = g_col[j];
        m0 = fmaxf(m0, lrelu(g_asrc[s * 4 + 0] + ad0));
        m1 = fmaxf(m1, lrelu(g_asrc[s * 4 + 1] + ad1));
        m2 = fmaxf(m2, lrelu(g_asrc[s * 4 + 2] + ad2));
        m3 = fmaxf(m3, lrelu(g_asrc[s * 4 + 3] + ad3));
    }
#pragma unroll
    for (int o = 16; o; o >>= 1) {
        m0 = fmaxf(m0, __shfl_xor_sync(0xffffffffu, m0, o));
        m1 = fmaxf(m1, __shfl_xor_sync(0xffffffffu, m1, o));
        m2 = fmaxf(m2, __shfl_xor_sync(0xffffffffu, m2, o));
        m3 = fmaxf(m3, __shfl_xor_sync(0xffffffffu, m3, o));
    }
    float d0 = 0.f, d1 = 0.f, d2 = 0.f, d3 = 0.f;
    for (int j = rs + lane; j < re; j += 32) {
        int s = g_col[j];
        d0 += __expf(lrelu(g_asrc[s * 4 + 0] + ad0) - m0);
        d1 += __expf(lrelu(g_asrc[s * 4 + 1] + ad1) - m1);
        d2 += __expf(lrelu(g_asrc[s * 4 + 2] + ad2) - m2);
        d3 += __expf(lrelu(g_asrc[s * 4 + 3] + ad3) - m3);
    }
#pragma unroll
    for (int o = 16; o; o >>= 1) {
        d0 += __shfl_xor_sync(0xffffffffu, d0, o);
        d1 += __shfl_xor_sync(0xffffffffu, d1, o);
        d2 += __shfl_xor_sync(0xffffffffu, d2, o);
        d3 += __shfl_xor_sync(0xffffffffu, d3, o);
    }
    float i0 = 1.f / d0, i1 = 1.f / d1, i2 = 1.f / d2, i3 = 1.f / d3;

    float acc[8] = {0, 0, 0, 0, 0, 0, 0, 0};
    for (int j = rs; j < re; j++) {
        int s = g_col[j];
        float w0 = __expf(lrelu(g_asrc[s * 4 + 0] + ad0) - m0) * i0;
        float w1 = __expf(lrelu(g_asrc[s * 4 + 1] + ad1) - m1) * i1;
        float w2 = __expf(lrelu(g_asrc[s * 4 + 2] + ad2) - m2) * i2;
        float w3 = __expf(lrelu(g_asrc[s * 4 + 3] + ad3) - m3) * i3;
        const float* hr = g_hf + (size_t)s * 256;
        acc[0] += w0 * hr[lane];       acc[1] += w0 * hr[lane + 32];
        acc[2] += w1 * hr[lane + 64];  acc[3] += w1 * hr[lane + 96];
        acc[4] += w2 * hr[lane + 128]; acc[5] += w2 * hr[lane + 160];
        acc[6] += w3 * hr[lane + 192]; acc[7] += w3 * hr[lane + 224];
    }
    if (CONCAT) {
#pragma unroll
        for (int k = 0; k < 8; k++) {
            int c = lane + 32 * k;
            float v = fmaxf(acc[k] + bias[c], 0.f);
            __nv_bfloat16 h = __float2bfloat16(v);
            g_xrh[(size_t)n * 256 + c] = h;
            g_xrl[(size_t)n * 256 + c] = __float2bfloat16(v - __bfloat162float(h));
        }
    } else {
        float o0 = 0.25f * (acc[0] + acc[2] + acc[4] + acc[6]) + bias[lane];
        float o1 = 0.25f * (acc[1] + acc[3] + acc[5] + acc[7]) + bias[lane + 32];
        g_xr2[(size_t)n * 64 + lane]      = fmaxf(o0, 0.f);
        g_xr2[(size_t)n * 64 + lane + 32] = fmaxf(o1, 0.f);
    }
}

// ------------------------- scorer head + pooling -----------------------------
__global__ void k_zero() { g_gsum[blockIdx.x * 256 + threadIdx.x] = 0.f; }

__launch_bounds__(256)
__global__ void k_final(const float* __restrict__ Wfc, const float* __restrict__ bfc) {
    extern __shared__ float Ws[];
    __shared__ float s_hc3[64];
    __shared__ float part_sh[8][64];
    __shared__ float part_ss[8][64];
    int tid = threadIdx.x, lane = tid & 31, w = tid >> 5;
    int g = blockIdx.x >> 1;

    for (int i = tid; i < 4096; i += 256)
        ((float4*)Ws)[i] = ((const float4*)Wfc)[i];
    if (tid < 64) s_hc3[tid] = g_xr2[((size_t)g << 9) * 64 + tid];
    __syncthreads();

    float bL = bfc[lane], bH = bfc[lane + 32];
    float shL = 0.f, shH = 0.f, ssL = 0.f, ssH = 0.f;
    int nbase = blockIdx.x * 256 + w * 32;

    for (int g4 = 0; g4 < 8; g4++) {
        int n0 = nbase + g4 * 4;
        float xl[4], xh[4], aL[4], aH[4];
#pragma unroll
        for (int u = 0; u < 4; u++) {
            xl[u] = g_xr2[(size_t)(n0 + u) * 64 + lane];
            xh[u] = g_xr2[(size_t)(n0 + u) * 64 + lane + 32];
            aL[u] = bL; aH[u] = bH;
        }
#pragma unroll 4
        for (int j = 0; j < 64; j++) {
            float h3 = s_hc3[j];
            float w0 = Ws[j * 64 + lane];
            float w1 = Ws[(64 + j) * 64 + lane];
            float w2 = Ws[(128 + j) * 64 + lane];
            float w3 = Ws[(192 + j) * 64 + lane];
            float v0 = Ws[j * 64 + lane + 32];
            float v1 = Ws[(64 + j) * 64 + lane + 32];
            float v2 = Ws[(128 + j) * 64 + lane + 32];
            float v3 = Ws[(192 + j) * 64 + lane + 32];
#pragma unroll
            for (int u = 0; u < 4; u++) {
                float xj = (j < 32) ? __shfl_sync(0xffffffffu, xl[u], j)
                                    : __shfl_sync(0xffffffffu, xh[u], j - 32);
                float p = xj * h3;
                float q = fabsf(h3 - xj);
                aL[u] += h3 * w0 + xj * w1 + p * w2 + q * w3;
                aH[u] += h3 * v0 + xj * v1 + p * v2 + q * v3;
            }
        }
#pragma unroll
        for (int u = 0; u < 4; u++) {
            float tL = tanhf(aL[u]), tH = tanhf(aH[u]);
            float mx = fmaxf(tL, tH);
#pragma unroll
            for (int o = 16; o; o >>= 1) mx = fmaxf(mx, __shfl_xor_sync(0xffffffffu, mx, o));
            float eL = __expf(tL - mx), eH = __expf(tH - mx);
            float sm = eL + eH;
#pragma unroll
            for (int o = 16; o; o >>= 1) sm += __shfl_xor_sync(0xffffffffu, sm, o);
            float inv = 1.f / sm;
            shL += eL * inv * xl[u]; shH += eH * inv * xh[u];
            ssL += xl[u];            ssH += xh[u];
        }
    }
    part_sh[w][lane] = shL; part_sh[w][lane + 32] = shH;
    part_ss[w][lane] = ssL; part_ss[w][lane + 32] = ssH;
    __syncthreads();
    if (tid < 128) {
        int c = tid & 63;
        float s = 0.f;
        if (tid < 64) {
            for (int ww = 0; ww < 8; ww++) s += part_sh[ww][c];
            atomicAdd(&g_gsum[g * 128 + c], s);
        } else {
            for (int ww = 0; ww < 8; ww++) s += part_ss[ww][c];
            atomicAdd(&g_gsum[g * 128 + 64 + c], s);
        }
    }
}

__global__ void k_logits(const float* __restrict__ Wc, const float* __restrict__ bc,
                         float* __restrict__ out) {
    int b = threadIdx.x;
    float l[4] = {bc[0], bc[1], bc[2], bc[3]};
    const float inv = 1.f / 512.f;
    for (int j = 0; j < 128; j++) {
        float v = g_gsum[b * 128 + j] * inv;
#pragma unroll
        for (int c = 0; c < 4; c++) l[c] += v * Wc[j * 4 + c];
    }
    float mx = fmaxf(fmaxf(l[0], l[1]), fmaxf(l[2], l[3]));
    float s = expf(l[0] - mx) + expf(l[1] - mx) + expf(l[2] - mx) + expf(l[3] - mx);
    float lse = mx + logf(s);
#pragma unroll
    for (int c = 0; c < 4; c++) out[b * 4 + c] = l[c] - lse;
}

// ------------------------- launch --------------------------------------------
extern "C" void kernel_launch(void* const* d_in, const int* in_sizes, int n_in,
                              void* d_out, int out_size) {
    const float* x        = (const float*)d_in[0];
    const float* root     = (const float*)d_in[1];
    const int*   ei       = (const int*)d_in[2];
    const float* W_post1  = (const float*)d_in[5];
    const float* W_claim1 = (const float*)d_in[6];
    const float* W1       = (const float*)d_in[7];
    const float* att_src1 = (const float*)d_in[8];
    const float* att_dst1 = (const float*)d_in[9];
    const float* b1       = (const float*)d_in[10];
    const float* W_post2  = (const float*)d_in[11];
    const float* W_claim2 = (const float*)d_in[12];
    const float* W2       = (const float*)d_in[13];
    const float* att_src2 = (const float*)d_in[14];
    const float* att_dst2 = (const float*)d_in[15];
    const float* b2       = (const float*)d_in[16];
    const float* W_fc     = (const float*)d_in[17];
    const float* b_fc     = (const float*)d_in[18];
    const float* W_clf    = (const float*)d_in[19];
    const float* b_clf    = (const float*)d_in[20];
    float* out = (float*)d_out;

    const int SMM0 = (128 * LDS * 2 + 64 * LDS * 2) * 2;   // 55296
    const int SMMC = SMM0 * 2;                             // 110592 (double buffer)
    cudaFuncSetAttribute(k_final,  cudaFuncAttributeMaxDynamicSharedMemorySize, 65536);
    cudaFuncSetAttribute(k_mm0,    cudaFuncAttributeMaxDynamicSharedMemorySize, SMM0);
    cudaFuncSetAttribute(k_mmc<1>, cudaFuncAttributeMaxDynamicSharedMemorySize, SMMC);
    cudaFuncSetAttribute(k_mmc<2>, cudaFuncAttributeMaxDynamicSharedMemorySize, SMMC);
    cudaFuncSetAttribute(k_mmc<3>, cudaFuncAttributeMaxDynamicSharedMemorySize, SMMC);

    // ordered so launch index 3 (ncu capture slot) is k_mmc<1>
    k_rootproj<<<NB, 64>>>(root, W_claim1, W_claim2);            // 0
    k_convW<<<WTOT / 256, 256>>>(W_post1, W1, W_post2, W2);      // 1
    k_mm0<<<dim3(1, NN / 128), 256, SMM0>>>(x);                  // 2  PLA1
    k_mmc<1><<<dim3(4, NN / 128), 256, SMMC>>>();                // 3  GAT1 lin
    k_deg_init<<<NN / 256, 256>>>();                             // 4
    k_deg<<<E2 / 256, 256>>>(ei);                                // 5
    k_scan_all<<<1, 1024>>>();                                   // 6
    k_scatter<<<ETOT / 256, 256>>>(ei);                          // 7

    k_scores<<<NN * 32 / 256, 256>>>(att_src1, att_dst1);
    k_agg<1><<<NN * 32 / 256, 256>>>(b1);
    k_mmc<2><<<dim3(1, NN * 4 / 128), 256, SMMC>>>();            // PLA2
    k_mmc<3><<<dim3(4, NN / 128), 256, SMMC>>>();                // GAT2 lin
    k_scores<<<NN * 32 / 256, 256>>>(att_src2, att_dst2);
    k_agg<0><<<NN * 32 / 256, 256>>>(b2);

    k_zero<<<NB * 128 / 256, 256>>>();
    k_final<<<NN / 256, 256, 65536>>>(W_fc, b_fc);
    k_logits<<<1, 128>>>(W_clf, b_clf, out);
}

// round 11
// speedup vs baseline: 1.2113x; 1.0049x over previous
#include <cuda_runtime.h>
#include <cuda_bf16.h>
#include <cstdint>

#define NN 65536      // nodes
#define NB 128        // graphs
#define NE 65536      // raw directed edges
#define E2 131072     // TD + BU
#define ETOT 196608   // + self loops
#define DIN 512
#define WTOT 200704   // total weight elements (all 4 matrices)

// ------------------------- scratch (device globals; no allocs) ---------------
__device__ float g_hf [NN * 256];   // GAT lin output (reused layer1 & layer2)
__device__ float g_xr2[NN * 64];    // relu(GAT2 out)
__device__ float g_asrc[NN * 4];
__device__ float g_adst[NN * 4];
__device__ float g_hc1[NB * 64];
__device__ float g_hc2[NB * 64];
__device__ float g_gsum[NB * 128];
__device__ int   g_deg[NN];
__device__ int   g_rp [NN + 1];
__device__ int   g_cursor[NN];
__device__ int   g_col[ETOT];
// bf16 hi/lo planes (split-precision operands, converted exactly once)
__device__ __nv_bfloat16 g_h1h[NN * 128], g_h1l[NN * 128];   // PLA1 out (MODE1 A)
__device__ __nv_bfloat16 g_xrh[NN * 256], g_xrl[NN * 256];   // relu(GAT1) (MODE2 A)
__device__ __nv_bfloat16 g_x3h[NN * 512], g_x3l[NN * 512];   // PLA2 out (MODE3 A)
__device__ __nv_bfloat16 g_wth[WTOT],     g_wtl[WTOT];       // transposed weights

// ------------------------- helpers -------------------------------------------
__device__ __forceinline__ uint32_t smem_u32(const void* p) {
    uint32_t a;
    asm("{ .reg .u64 t; cvta.to.shared.u64 t, %1; cvt.u32.u64 %0, t; }" : "=r"(a) : "l"(p));
    return a;
}
__device__ __forceinline__ void ldmat4(uint32_t& r0, uint32_t& r1, uint32_t& r2,
                                       uint32_t& r3, uint32_t addr) {
    asm volatile("ldmatrix.sync.aligned.m8n8.x4.shared.b16 {%0,%1,%2,%3}, [%4];"
        : "=r"(r0), "=r"(r1), "=r"(r2), "=r"(r3) : "r"(addr));
}
__device__ __forceinline__ void ldmat2(uint32_t& r0, uint32_t& r1, uint32_t addr) {
    asm volatile("ldmatrix.sync.aligned.m8n8.x2.shared.b16 {%0,%1}, [%2];"
        : "=r"(r0), "=r"(r1) : "r"(addr));
}
__device__ __forceinline__ void mma_bf16(float* c, const uint32_t* a, const uint32_t* b) {
    asm volatile("mma.sync.aligned.m16n8k16.row.col.f32.bf16.bf16.f32 "
        "{%0,%1,%2,%3}, {%4,%5,%6,%7}, {%8,%9}, {%0,%1,%2,%3};"
        : "+f"(c[0]), "+f"(c[1]), "+f"(c[2]), "+f"(c[3])
        : "r"(a[0]), "r"(a[1]), "r"(a[2]), "r"(a[3]), "r"(b[0]), "r"(b[1]));
}
__device__ __forceinline__ uint32_t pack_hi(float a, float b) {
    __nv_bfloat162 t = __floats2bfloat162_rn(a, b);
    return *reinterpret_cast<uint32_t*>(&t);
}
__device__ __forceinline__ uint32_t pack_lo(float a, float b) {
    float ra = a - __bfloat162float(__float2bfloat16(a));
    float rb = b - __bfloat162float(__float2bfloat16(b));
    __nv_bfloat162 t = __floats2bfloat162_rn(ra, rb);
    return *reinterpret_cast<uint32_t*>(&t);
}
#define CP16(dst, src) \
    asm volatile("cp.async.cg.shared.global [%0], [%1], 16;" :: "r"(dst), "l"(src))
#define CPCOMMIT() asm volatile("cp.async.commit_group;" ::: "memory")
#define CPWAIT0()  asm volatile("cp.async.wait_group 0;" ::: "memory")
#define CPWAIT1()  asm volatile("cp.async.wait_group 1;" ::: "memory")

// ------------------------- weight pre-conversion + score zeroing --------------
// Transposed n-major planes: dst = off + n*K + k
//   W_post1 [512][64]  -> off 0      | W1 [128][256] -> off 32768
//   W_post2 [64][64]   -> off 65536  | W2 [512][256] -> off 69632
__global__ void k_convW(const float* __restrict__ Wa, const float* __restrict__ Wb,
                        const float* __restrict__ Wc, const float* __restrict__ Wd) {
    int idx = blockIdx.x * 256 + threadIdx.x;
    const float* W; int K, N, local;
    if (idx < 32768)      { W = Wa; K = 512; N = 64;  local = idx; }
    else if (idx < 65536) { W = Wb; K = 128; N = 256; local = idx - 32768; }
    else if (idx < 69632) { W = Wc; K = 64;  N = 64;  local = idx - 65536; }
    else                  { W = Wd; K = 512; N = 256; local = idx - 69632; }
    int n = local / K, k = local - n * K;
    float v = W[(size_t)k * N + n];
    __nv_bfloat16 h = __float2bfloat16(v);
    g_wth[idx] = h;
    g_wtl[idx] = __float2bfloat16(v - __bfloat162float(h));
    // zero layer-1 attention score accumulators (atomicAdd targets)
    for (int z = idx; z < NN * 4; z += WTOT) { g_asrc[z] = 0.f; g_adst[z] = 0.f; }
}

__global__ void k_zs() {   // zero scores before layer-2 GEMM (grid 2048 x 256)
    int i = blockIdx.x * 256 + threadIdx.x;
    if (i < NN * 4) g_asrc[i] = 0.f;
    else            g_adst[i - NN * 4] = 0.f;
}

// ------------------------- CSR build -----------------------------------------
__global__ void k_deg_init() { g_deg[blockIdx.x * 256 + threadIdx.x] = 1; }

__global__ void k_deg(const int* __restrict__ ei) {
    int i = blockIdx.x * 256 + threadIdx.x;
    int d = (i < NE) ? ei[NE + i] : ei[i - NE];
    atomicAdd(&g_deg[d], 1);
}

__global__ void k_scan_all() {   // 1 block x 1024; 64 elems/thread
    __shared__ int wsum[32];
    int tid = threadIdx.x, lane = tid & 31, wid = tid >> 5;
    int base = tid * 64;
    int s = 0;
    for (int i = 0; i < 64; i++) s += g_deg[base + i];
    int x = s;
#pragma unroll
    for (int o = 1; o < 32; o <<= 1) {
        int y = __shfl_up_sync(0xffffffffu, x, o);
        if (lane >= o) x += y;
    }
    if (lane == 31) wsum[wid] = x;
    __syncthreads();
    if (wid == 0) {
        int t = wsum[lane];
#pragma unroll
        for (int o = 1; o < 32; o <<= 1) {
            int y = __shfl_up_sync(0xffffffffu, t, o);
            if (lane >= o) t += y;
        }
        wsum[lane] = t;
    }
    __syncthreads();
    int run = (wid ? wsum[wid - 1] : 0) + x - s;
    for (int i = 0; i < 64; i++) {
        int v = g_deg[base + i];
        g_rp[base + i] = run;
        g_cursor[base + i] = run;
        run += v;
    }
    if (tid == 0) g_rp[NN] = ETOT;
}

__global__ void k_scatter(const int* __restrict__ ei) {
    int i = blockIdx.x * 256 + threadIdx.x;
    int s, d;
    if (i < NE)        { s = ei[i];          d = ei[NE + i]; }
    else if (i < E2)   { int e = i - NE; s = ei[NE + e]; d = ei[e]; }
    else               { s = d = i - E2; }
    int pos = atomicAdd(&g_cursor[d], 1);
    g_col[pos] = s;
}

// ------------------------- root projections ----------------------------------
__global__ void k_rootproj(const float* __restrict__ root,
                           const float* __restrict__ Wc1,
                           const float* __restrict__ Wc2) {
    int b = blockIdx.x, c = threadIdx.x;
    float a1 = 0.f, a2 = 0.f;
    for (int k = 0; k < DIN; k++) {
        float rv = root[b * DIN + k];
        a1 += rv * Wc1[k * 64 + c];
        a2 += rv * Wc2[k * 64 + c];
    }
    g_hc1[b * 64 + c] = a1;
    g_hc2[b * 64 + c] = a2;
}

#define LDS 72            // padded smem row stride for k_mmc (bf16): 144B

// ------------------------- MODE0: x @ W_post1, cp.async fp32 staging ----------
// 32-k stages double-buffered; convert smem fp32 -> bf16 hi/lo planes.
// smem: Xs[2] (128x36 f32, 18432B each) | Ah,Al (128x56 bf16, 14336B each)
//       | B[2] (hi+lo 64x56 bf16, 14336B each)  -> total 94208B
#define XSTRIDE 36
#define PLDS 56
#define XS_BYTES 18432
#define OFF_AH 36864
#define OFF_AL 51200
#define OFF_B  65536
#define B_BYTES 14336

__launch_bounds__(256, 2)
__global__ void k_mm0(const float* __restrict__ Aarg) {
    extern __shared__ __align__(16) char sm[];
    int tid = threadIdx.x, lane = tid & 31, w = tid >> 5;
    int wm = (w & 1) * 64, wn = (w >> 1) * 16;
    const float* Arow = Aarg + (size_t)blockIdx.y * 128 * 512;
    __nv_bfloat16* Ah = (__nv_bfloat16*)(sm + OFF_AH);
    __nv_bfloat16* Al = (__nv_bfloat16*)(sm + OFF_AL);

    float acc[4][2][4];
#pragma unroll
    for (int a = 0; a < 4; a++)
#pragma unroll
        for (int b = 0; b < 2; b++)
#pragma unroll
            for (int c = 0; c < 4; c++) acc[a][b][c] = 0.f;

    auto stage = [&](int it, int buf) {
        int k0 = it * 32;
        float* Xs = (float*)(sm + buf * XS_BYTES);
        __nv_bfloat16* Bh = (__nv_bfloat16*)(sm + OFF_B + buf * B_BYTES);
        __nv_bfloat16* Bl = Bh + 3584;     // 7168 bytes
#pragma unroll
        for (int i = 0; i < 4; i++) {
            int idx = i * 256 + tid;
            int r = idx >> 3, c4 = (idx & 7) << 2;
            CP16(smem_u32(&Xs[r * XSTRIDE + c4]), &Arow[(size_t)r * 512 + k0 + c4]);
        }
#pragma unroll
        for (int i = 0; i < 2; i++) {
            int idx = i * 256 + tid;
            int n = (idx & 255) >> 2, c8 = (idx & 3) << 3;
            const __nv_bfloat16* src = (i == 0) ? g_wth : g_wtl;    // W_post1 off 0
            __nv_bfloat16* dst = (i == 0) ? Bh : Bl;
            CP16(smem_u32(&dst[n * PLDS + c8]), &src[(size_t)n * 512 + k0 + c8]);
        }
        CPCOMMIT();
    };

    stage(0, 0);
    for (int it = 0; it < 16; it++) {
        int buf = it & 1;
        if (it + 1 < 16) { stage(it + 1, buf ^ 1); CPWAIT1(); }
        else             { CPWAIT0(); }
        __syncthreads();
        // convert fp32 stage -> bf16 hi/lo planes
        float* Xs = (float*)(sm + buf * XS_BYTES);
#pragma unroll
        for (int i = 0; i < 4; i++) {
            int idx = i * 256 + tid;
            int r = idx >> 3, c4 = (idx & 7) << 2;
            float4 v = *(const float4*)&Xs[r * XSTRIDE + c4];
            *(uint2*)&Ah[r * PLDS + c4] = make_uint2(pack_hi(v.x, v.y), pack_hi(v.z, v.w));
            *(uint2*)&Al[r * PLDS + c4] = make_uint2(pack_lo(v.x, v.y), pack_lo(v.z, v.w));
        }
        __syncthreads();
        __nv_bfloat16* Bh = (__nv_bfloat16*)(sm + OFF_B + buf * B_BYTES);
        __nv_bfloat16* Bl = Bh + 3584;
#pragma unroll
        for (int ks = 0; ks < 2; ks++) {
            int kb = ks * 16;
            uint32_t ah[4][4], al[4][4], bh[2][2], bl[2][2];
            int arow = wm + (lane & 15);
            int acol = kb + (lane >> 4) * 8;
#pragma unroll
            for (int mf = 0; mf < 4; mf++) {
                ldmat4(ah[mf][0], ah[mf][1], ah[mf][2], ah[mf][3],
                       smem_u32(&Ah[(arow + mf * 16) * PLDS + acol]));
                ldmat4(al[mf][0], al[mf][1], al[mf][2], al[mf][3],
                       smem_u32(&Al[(arow + mf * 16) * PLDS + acol]));
            }
            int brow = wn + (lane & 7);
            int bcol = kb + ((lane >> 3) & 1) * 8;
#pragma unroll
            for (int nf = 0; nf < 2; nf++) {
                ldmat2(bh[nf][0], bh[nf][1], smem_u32(&Bh[(brow + nf * 8) * PLDS + bcol]));
                ldmat2(bl[nf][0], bl[nf][1], smem_u32(&Bl[(brow + nf * 8) * PLDS + bcol]));
            }
#pragma unroll
            for (int mf = 0; mf < 4; mf++)
#pragma unroll
                for (int nf = 0; nf < 2; nf++) {
                    mma_bf16(acc[mf][nf], ah[mf], bh[nf]);
                    mma_bf16(acc[mf][nf], ah[mf], bl[nf]);
                    mma_bf16(acc[mf][nf], al[mf], bh[nf]);
                }
        }
        __syncthreads();
    }

    // epilogue: PLA1 gate -> g_h1 planes
#pragma unroll
    for (int mf = 0; mf < 4; mf++)
#pragma unroll
        for (int nf = 0; nf < 2; nf++)
#pragma unroll
            for (int p = 0; p < 2; p++) {
                int row = blockIdx.y * 128 + wm + mf * 16 + (lane >> 2) + p * 8;
                int c   = wn + nf * 8 + (lane & 3) * 2;
                float v0 = acc[mf][nf][p * 2 + 0];
                float v1 = acc[mf][nf][p * 2 + 1];
                int gid = row >> 9;
                float hc0 = g_hc1[gid * 64 + c];
                float hc1 = g_hc1[gid * 64 + c + 1];
                float gs0 = 1.f / (1.f + __expf(-(v0 + hc0)));
                float gs1 = 1.f / (1.f + __expf(-(v1 + hc1)));
                float gv0 = gs0 * v0 + (1.f - gs0) * hc0;
                float gv1 = gs1 * v1 + (1.f - gs1) * hc1;
                size_t b0 = (size_t)row * 128 + c;
                *(uint32_t*)&g_h1h[b0]      = pack_hi(gv0, gv1);
                *(uint32_t*)&g_h1l[b0]      = pack_lo(gv0, gv1);
                *(uint32_t*)&g_h1h[b0 + 64] = pack_hi(v0, v1);
                *(uint32_t*)&g_h1l[b0 + 64] = pack_lo(v0, v1);
            }
}

// ------------------- MODE 1/2/3: pure-copy, cp.async double-buffered ----------
// MODE 1: g_h1 @ W1      (K=128) -> g_hf + fused scores   grid(4, 512)
// MODE 2: g_xr @ W_post2 (K=64)  -> PLA2 -> g_x3          grid(1, 2048)
// MODE 3: g_x3 @ W2      (K=512) -> g_hf + fused scores   grid(4, 512)
template <int MODE>
__launch_bounds__(256, 2)
__global__ void k_mmc(const float* __restrict__ as_, const float* __restrict__ ad_) {
    constexpr int K    = (MODE == 3) ? 512 : (MODE == 1 ? 128 : 64);
    constexpr int KT   = K / 64;
    constexpr int WOFF = (MODE == 1) ? 32768 : (MODE == 2) ? 65536 : 69632;
    constexpr int ASZ  = 128 * LDS;
    constexpr int BSZ  = 64 * LDS;
    constexpr int STG  = 2 * ASZ + 2 * BSZ;

    extern __shared__ __align__(16) char sm[];
    __nv_bfloat16* base = (__nv_bfloat16*)sm;

    int tid = threadIdx.x, lane = tid & 31, w = tid >> 5;
    int wm = (w & 1) * 64, wn = (w >> 1) * 16;
    int n0 = blockIdx.x * 64;

    const __nv_bfloat16* Aph = ((MODE == 1) ? g_h1h : (MODE == 2) ? g_xrh : g_x3h)
                             + (size_t)blockIdx.y * 128 * K;
    const __nv_bfloat16* Apl = ((MODE == 1) ? g_h1l : (MODE == 2) ? g_xrl : g_x3l)
                             + (size_t)blockIdx.y * 128 * K;

    float acc[4][2][4];
#pragma unroll
    for (int a = 0; a < 4; a++)
#pragma unroll
        for (int b = 0; b < 2; b++)
#pragma unroll
            for (int c = 0; c < 4; c++) acc[a][b][c] = 0.f;

    auto stage = [&](int k0, int buf) {
        __nv_bfloat16* Ah = base + buf * STG;
        __nv_bfloat16* Al = Ah + ASZ;
        __nv_bfloat16* Bh = Al + ASZ;
        __nv_bfloat16* Bl = Bh + BSZ;
#pragma unroll
        for (int i = 0; i < 4; i++) {
            int idx = i * 256 + tid;
            int r = idx >> 3, c8 = (idx & 7) << 3;
            size_t so = (size_t)r * K + k0 + c8;
            CP16(smem_u32(&Ah[r * LDS + c8]), &Aph[so]);
            CP16(smem_u32(&Al[r * LDS + c8]), &Apl[so]);
        }
#pragma unroll
        for (int i = 0; i < 2; i++) {
            int idx = i * 256 + tid;
            int n = idx >> 3, c8 = (idx & 7) << 3;
            size_t so = (size_t)WOFF + (size_t)(n0 + n) * K + k0 + c8;
            CP16(smem_u32(&Bh[n * LDS + c8]), &g_wth[so]);
            CP16(smem_u32(&Bl[n * LDS + c8]), &g_wtl[so]);
        }
        CPCOMMIT();
    };

    stage(0, 0);
    int buf = 0;
    for (int it = 0; it < KT; it++) {
        if (it + 1 < KT) { stage((it + 1) * 64, buf ^ 1); CPWAIT1(); }
        else             { CPWAIT0(); }
        __syncthreads();
        __nv_bfloat16* Ah = base + buf * STG;
        __nv_bfloat16* Al = Ah + ASZ;
        __nv_bfloat16* Bh = Al + ASZ;
        __nv_bfloat16* Bl = Bh + BSZ;
#pragma unroll
        for (int ks = 0; ks < 4; ks++) {
            int kb = ks * 16;
            uint32_t ah[4][4], al[4][4], bh[2][2], bl[2][2];
            int arow = wm + (lane & 15);
            int acol = kb + (lane >> 4) * 8;
#pragma unroll
            for (int mf = 0; mf < 4; mf++) {
                ldmat4(ah[mf][0], ah[mf][1], ah[mf][2], ah[mf][3],
                       smem_u32(&Ah[(arow + mf * 16) * LDS + acol]));
                ldmat4(al[mf][0], al[mf][1], al[mf][2], al[mf][3],
                       smem_u32(&Al[(arow + mf * 16) * LDS + acol]));
            }
            int brow = wn + (lane & 7);
            int bcol = kb + ((lane >> 3) & 1) * 8;
#pragma unroll
            for (int nf = 0; nf < 2; nf++) {
                ldmat2(bh[nf][0], bh[nf][1], smem_u32(&Bh[(brow + nf * 8) * LDS + bcol]));
                ldmat2(bl[nf][0], bl[nf][1], smem_u32(&Bl[(brow + nf * 8) * LDS + bcol]));
            }
#pragma unroll
            for (int mf = 0; mf < 4; mf++)
#pragma unroll
                for (int nf = 0; nf < 2; nf++) {
                    mma_bf16(acc[mf][nf], ah[mf], bh[nf]);
                    mma_bf16(acc[mf][nf], ah[mf], bl[nf]);
                    mma_bf16(acc[mf][nf], al[mf], bh[nf]);
                }
        }
        __syncthreads();
        buf ^= 1;
    }

    if (MODE == 1 || MODE == 3) {
        // store g_hf + fused attention-score partial dots (head = n0>>6)
#pragma unroll
        for (int mf = 0; mf < 4; mf++)
#pragma unroll
            for (int p = 0; p < 2; p++) {
                int row = blockIdx.y * 128 + wm + mf * 16 + (lane >> 2) + p * 8;
                float ps = 0.f, pd = 0.f;
#pragma unroll
                for (int nf = 0; nf < 2; nf++) {
                    int c = wn + nf * 8 + (lane & 3) * 2;
                    float v0 = acc[mf][nf][p * 2 + 0];
                    float v1 = acc[mf][nf][p * 2 + 1];
                    g_hf[(size_t)row * 256 + n0 + c]     = v0;
                    g_hf[(size_t)row * 256 + n0 + c + 1] = v1;
                    ps += v0 * as_[n0 + c] + v1 * as_[n0 + c + 1];
                    pd += v0 * ad_[n0 + c] + v1 * ad_[n0 + c + 1];
                }
                ps += __shfl_xor_sync(0xffffffffu, ps, 1);
                ps += __shfl_xor_sync(0xffffffffu, ps, 2);
                pd += __shfl_xor_sync(0xffffffffu, pd, 1);
                pd += __shfl_xor_sync(0xffffffffu, pd, 2);
                if ((lane & 3) == 0) {
                    int h = n0 >> 6;
                    atomicAdd(&g_asrc[row * 4 + h], ps);
                    atomicAdd(&g_adst[row * 4 + h], pd);
                }
            }
    } else {
#pragma unroll
        for (int mf = 0; mf < 4; mf++)
#pragma unroll
            for (int nf = 0; nf < 2; nf++)
#pragma unroll
                for (int p = 0; p < 2; p++) {
                    int row = blockIdx.y * 128 + wm + mf * 16 + (lane >> 2) + p * 8;
                    int c   = wn + nf * 8 + (lane & 3) * 2;
                    float v0 = acc[mf][nf][p * 2 + 0];
                    float v1 = acc[mf][nf][p * 2 + 1];
                    int gid = row >> 11;
                    float hc0 = g_hc2[gid * 64 + c];
                    float hc1 = g_hc2[gid * 64 + c + 1];
                    float gs0 = 1.f / (1.f + __expf(-(v0 + hc0)));
                    float gs1 = 1.f / (1.f + __expf(-(v1 + hc1)));
                    float gv0 = gs0 * v0 + (1.f - gs0) * hc0;
                    float gv1 = gs1 * v1 + (1.f - gs1) * hc1;
                    size_t b0 = (size_t)row * 128 + c;
                    *(uint32_t*)&g_x3h[b0]      = pack_hi(gv0, gv1);
                    *(uint32_t*)&g_x3l[b0]      = pack_lo(gv0, gv1);
                    *(uint32_t*)&g_x3h[b0 + 64] = pack_hi(v0, v1);
                    *(uint32_t*)&g_x3l[b0 + 64] = pack_lo(v0, v1);
                }
    }
}

// ------------------------- GAT aggregation (warp per dst) --------------------
__device__ __forceinline__ float lrelu(float x) { return x > 0.f ? x : 0.2f * x; }

template <int CONCAT>
__launch_bounds__(256)
__global__ void k_agg(const float* __restrict__ bias) {
    int n = (blockIdx.x * 256 + threadIdx.x) >> 5;
    int lane = threadIdx.x & 31;
    int rs = g_rp[n], re = g_rp[n + 1];
    float ad0 = g_adst[n * 4 + 0], ad1 = g_adst[n * 4 + 1];
    float ad2 = g_adst[n * 4 + 2], ad3 = g_adst[n * 4 + 3];

    float m0 = -1e30f, m1 = -1e30f, m2 = -1e30f, m3 = -1e30f;
    for (int j = rs + lane; j < re; j += 32) {
        int s = g_col[j];
        m0 = fmaxf(m0, lrelu(g_asrc[s * 4 + 0] + ad0));
        m1 = fmaxf(m1, lrelu(g_asrc[s * 4 + 1] + ad1));
        m2 = fmaxf(m2, lrelu(g_asrc[s * 4 + 2] + ad2));
        m3 = fmaxf(m3, lrelu(g_asrc[s * 4 + 3] + ad3));
    }
#pragma unroll
    for (int o = 16; o; o >>= 1) {
        m0 = fmaxf(m0, __shfl_xor_sync(0xffffffffu, m0, o));
        m1 = fmaxf(m1, __shfl_xor_sync(0xffffffffu, m1, o));
        m2 = fmaxf(m2, __shfl_xor_sync(0xffffffffu, m2, o));
        m3 = fmaxf(m3, __shfl_xor_sync(0xffffffffu, m3, o));
    }
    float d0 = 0.f, d1 = 0.f, d2 = 0.f, d3 = 0.f;
    for (int j = rs + lane; j < re; j += 32) {
        int s = g_col[j];
        d0 += __expf(lrelu(g_asrc[s * 4 + 0] + ad0) - m0);
        d1 += __expf(lrelu(g_asrc[s * 4 + 1] + ad1) - m1);
        d2 += __expf(lrelu(g_asrc[s * 4 + 2] + ad2) - m2);
        d3 += __expf(lrelu(g_asrc[s * 4 + 3] + ad3) - m3);
    }
#pragma unroll
    for (int o = 16; o; o >>= 1) {
        d0 += __shfl_xor_sync(0xffffffffu, d0, o);
        d1 += __shfl_xor_sync(0xffffffffu, d1, o);
        d2 += __shfl_xor_sync(0xffffffffu, d2, o);
        d3 += __shfl_xor_sync(0xffffffffu, d3, o);
    }
    float i0 = 1.f / d0, i1 = 1.f / d1, i2 = 1.f / d2, i3 = 1.f / d3;

    float acc[8] = {0, 0, 0, 0, 0, 0, 0, 0};
    for (int j = rs; j < re; j++) {
        int s = g_col[j];
        float w0 = __expf(lrelu(g_asrc[s * 4 + 0] + ad0) - m0) * i0;
        float w1 = __expf(lrelu(g_asrc[s * 4 + 1] + ad1) - m1) * i1;
        float w2 = __expf(lrelu(g_asrc[s * 4 + 2] + ad2) - m2) * i2;
        float w3 = __expf(lrelu(g_asrc[s * 4 + 3] + ad3) - m3) * i3;
        const float* hr = g_hf + (size_t)s * 256;
        acc[0] += w0 * hr[lane];       acc[1] += w0 * hr[lane + 32];
        acc[2] += w1 * hr[lane + 64];  acc[3] += w1 * hr[lane + 96];
        acc[4] += w2 * hr[lane + 128]; acc[5] += w2 * hr[lane + 160];
        acc[6] += w3 * hr[lane + 192]; acc[7] += w3 * hr[lane + 224];
    }
    if (CONCAT) {
#pragma unroll
        for (int k = 0; k < 8; k++) {
            int c = lane + 32 * k;
            float v = fmaxf(acc[k] + bias[c], 0.f);
            __nv_bfloat16 h = __float2bfloat16(v);
            g_xrh[(size_t)n * 256 + c] = h;
            g_xrl[(size_t)n * 256 + c] = __float2bfloat16(v - __bfloat162float(h));
        }
    } else {
        float o0 = 0.25f * (acc[0] + acc[2] + acc[4] + acc[6]) + bias[lane];
        float o1 = 0.25f * (acc[1] + acc[3] + acc[5] + acc[7]) + bias[lane + 32];
        g_xr2[(size_t)n * 64 + lane]      = fmaxf(o0, 0.f);
        g_xr2[(size_t)n * 64 + lane + 32] = fmaxf(o1, 0.f);
    }
}

// ------------------------- scorer head + pooling -----------------------------
__global__ void k_zero() { g_gsum[blockIdx.x * 256 + threadIdx.x] = 0.f; }

__launch_bounds__(256)
__global__ void k_final(const float* __restrict__ Wfc, const float* __restrict__ bfc) {
    extern __shared__ float Ws[];
    __shared__ float s_hc3[64];
    __shared__ float part_sh[8][64];
    __shared__ float part_ss[8][64];
    int tid = threadIdx.x, lane = tid & 31, w = tid >> 5;
    int g = blockIdx.x >> 1;

    for (int i = tid; i < 4096; i += 256)
        ((float4*)Ws)[i] = ((const float4*)Wfc)[i];
    if (tid < 64) s_hc3[tid] = g_xr2[((size_t)g << 9) * 64 + tid];
    __syncthreads();

    float bL = bfc[lane], bH = bfc[lane + 32];
    float shL = 0.f, shH = 0.f, ssL = 0.f, ssH = 0.f;
    int nbase = blockIdx.x * 256 + w * 32;

    for (int g4 = 0; g4 < 8; g4++) {
        int n0 = nbase + g4 * 4;
        float xl[4], xh[4], aL[4], aH[4];
#pragma unroll
        for (int u = 0; u < 4; u++) {
            xl[u] = g_xr2[(size_t)(n0 + u) * 64 + lane];
            xh[u] = g_xr2[(size_t)(n0 + u) * 64 + lane + 32];
            aL[u] = bL; aH[u] = bH;
        }
#pragma unroll 4
        for (int j = 0; j < 64; j++) {
            float h3 = s_hc3[j];
            float w0 = Ws[j * 64 + lane];
            float w1 = Ws[(64 + j) * 64 + lane];
            float w2 = Ws[(128 + j) * 64 + lane];
            float w3 = Ws[(192 + j) * 64 + lane];
            float v0 = Ws[j * 64 + lane + 32];
            float v1 = Ws[(64 + j) * 64 + lane + 32];
            float v2 = Ws[(128 + j) * 64 + lane + 32];
            float v3 = Ws[(192 + j) * 64 + lane + 32];
#pragma unroll
            for (int u = 0; u < 4; u++) {
                float xj = (j < 32) ? __shfl_sync(0xffffffffu, xl[u], j)
                                    : __shfl_sync(0xffffffffu, xh[u], j - 32);
                float p = xj * h3;
                float q = fabsf(h3 - xj);
                aL[u] += h3 * w0 + xj * w1 + p * w2 + q * w3;
                aH[u] += h3 * v0 + xj * v1 + p * v2 + q * v3;
            }
        }
#pragma unroll
        for (int u = 0; u < 4; u++) {
            float tL = tanhf(aL[u]), tH = tanhf(aH[u]);
            float mx = fmaxf(tL, tH);
#pragma unroll
            for (int o = 16; o; o >>= 1) mx = fmaxf(mx, __shfl_xor_sync(0xffffffffu, mx, o));
            float eL = __expf(tL - mx), eH = __expf(tH - mx);
            float sm = eL + eH;
#pragma unroll
            for (int o = 16; o; o >>= 1) sm += __shfl_xor_sync(0xffffffffu, sm, o);
            float inv = 1.f / sm;
            shL += eL * inv * xl[u]; shH += eH * inv * xh[u];
            ssL += xl[u];            ssH += xh[u];
        }
    }
    part_sh[w][lane] = shL; part_sh[w][lane + 32] = shH;
    part_ss[w][lane] = ssL; part_ss[w][lane + 32] = ssH;
    __syncthreads();
    if (tid < 128) {
        int c = tid & 63;
        float s = 0.f;
        if (tid < 64) {
            for (int ww = 0; ww < 8; ww++) s += part_sh[ww][c];
            atomicAdd(&g_gsum[g * 128 + c], s);
        } else {
            for (int ww = 0; ww < 8; ww++) s += part_ss[ww][c];
            atomicAdd(&g_gsum[g * 128 + 64 + c], s);
        }
    }
}

__global__ void k_logits(const float* __restrict__ Wc, const float* __restrict__ bc,
                         float* __restrict__ out) {
    int b = threadIdx.x;
    float l[4] = {bc[0], bc[1], bc[2], bc[3]};
    const float inv = 1.f / 512.f;
    for (int j = 0; j < 128; j++) {
        float v = g_gsum[b * 128 + j] * inv;
#pragma unroll
        for (int c = 0; c < 4; c++) l[c] += v * Wc[j * 4 + c];
    }
    float mx = fmaxf(fmaxf(l[0], l[1]), fmaxf(l[2], l[3]));
    float s = expf(l[0] - mx) + expf(l[1] - mx) + expf(l[2] - mx) + expf(l[3] - mx);
    float lse = mx + logf(s);
#pragma unroll
    for (int c = 0; c < 4; c++) out[b * 4 + c] = l[c] - lse;
}

// ------------------------- launch --------------------------------------------
extern "C" void kernel_launch(void* const* d_in, const int* in_sizes, int n_in,
                              void* d_out, int out_size) {
    const float* x        = (const float*)d_in[0];
    const float* root     = (const float*)d_in[1];
    const int*   ei       = (const int*)d_in[2];
    const float* W_post1  = (const float*)d_in[5];
    const float* W_claim1 = (const float*)d_in[6];
    const float* W1       = (const float*)d_in[7];
    const float* att_src1 = (const float*)d_in[8];
    const float* att_dst1 = (const float*)d_in[9];
    const float* b1       = (const float*)d_in[10];
    const float* W_post2  = (const float*)d_in[11];
    const float* W_claim2 = (const float*)d_in[12];
    const float* W2       = (const float*)d_in[13];
    const float* att_src2 = (const float*)d_in[14];
    const float* att_dst2 = (const float*)d_in[15];
    const float* b2       = (const float*)d_in[16];
    const float* W_fc     = (const float*)d_in[17];
    const float* b_fc     = (const float*)d_in[18];
    const float* W_clf    = (const float*)d_in[19];
    const float* b_clf    = (const float*)d_in[20];
    float* out = (float*)d_out;

    const int SMM0 = 94208;
    const int SMMC = (128 * LDS * 2 + 64 * LDS * 2) * 2 * 2;   // 110592
    cudaFuncSetAttribute(k_final,  cudaFuncAttributeMaxDynamicSharedMemorySize, 65536);
    cudaFuncSetAttribute(k_mm0,    cudaFuncAttributeMaxDynamicSharedMemorySize, SMM0);
    cudaFuncSetAttribute(k_mmc<1>, cudaFuncAttributeMaxDynamicSharedMemorySize, SMMC);
    cudaFuncSetAttribute(k_mmc<2>, cudaFuncAttributeMaxDynamicSharedMemorySize, SMMC);
    cudaFuncSetAttribute(k_mmc<3>, cudaFuncAttributeMaxDynamicSharedMemorySize, SMMC);

    k_rootproj<<<NB, 64>>>(root, W_claim1, W_claim2);                   // 0
    k_convW<<<WTOT / 256, 256>>>(W_post1, W1, W_post2, W2);             // 1 (+zero scores)
    k_mm0<<<dim3(1, NN / 128), 256, SMM0>>>(x);                         // 2  PLA1
    k_mmc<1><<<dim3(4, NN / 128), 256, SMMC>>>(att_src1, att_dst1);     // 3  GAT1 lin+scores
    k_deg_init<<<NN / 256, 256>>>();                                    // 4
    k_deg<<<E2 / 256, 256>>>(ei);                                       // 5
    k_scan_all<<<1, 1024>>>();                                          // 6
    k_scatter<<<ETOT / 256, 256>>>(ei);                                 // 7

    k_agg<1><<<NN * 32 / 256, 256>>>(b1);
    k_mmc<2><<<dim3(1, NN * 4 / 128), 256, SMMC>>>(nullptr, nullptr);   // PLA2
    k_zs<<<NN * 8 / 256, 256>>>();                                      // zero layer-2 scores
    k_mmc<3><<<dim3(4, NN / 128), 256, SMMC>>>(att_src2, att_dst2);     // GAT2 lin+scores
    k_agg<0><<<NN * 32 / 256, 256>>>(b2);

    k_zero<<<NB * 128 / 256, 256>>>();
    k_final<<<NN / 256, 256, 65536>>>(W_fc, b_fc);
    k_logits<<<1, 128>>>(W_clf, b_clf, out);
}

// round 12
// speedup vs baseline: 1.5396x; 1.2710x over previous
#include <cuda_runtime.h>
#include <cuda_bf16.h>
#include <cstdint>

#define NN 65536      // nodes
#define NB 128        // graphs
#define NE 65536      // raw directed edges
#define E2 131072     // TD + BU
#define ETOT 196608   // + self loops
#define DIN 512
#define WTOT 200704   // total weight elements (all 4 matrices)

// ------------------------- scratch (device globals; no allocs) ---------------
__device__ float g_hf [NN * 256];   // GAT lin output (reused layer1 & layer2)
__device__ float g_xr2[NN * 64];    // relu(GAT2 out)
__device__ float g_asrc[NN * 4];
__device__ float g_adst[NN * 4];
__device__ float g_hc1[NB * 64];
__device__ float g_hc2[NB * 64];
__device__ float g_gsum[NB * 128];
__device__ int   g_deg[NN];
__device__ int   g_rp [NN + 1];
__device__ int   g_cursor[NN];
__device__ int   g_col[ETOT];
// bf16 operand planes (converted exactly once)
__device__ __nv_bfloat16 g_h1b[NN * 128];   // PLA1 out (MODE1 A)
__device__ __nv_bfloat16 g_xrb[NN * 256];   // relu(GAT1) (MODE2 A)
__device__ __nv_bfloat16 g_x3b[NN * 512];   // PLA2 out (MODE3 A)
__device__ __nv_bfloat16 g_wtb[WTOT];       // transposed weights

// ------------------------- helpers -------------------------------------------
__device__ __forceinline__ uint32_t smem_u32(const void* p) {
    uint32_t a;
    asm("{ .reg .u64 t; cvta.to.shared.u64 t, %1; cvt.u32.u64 %0, t; }" : "=r"(a) : "l"(p));
    return a;
}
__device__ __forceinline__ void ldmat4(uint32_t& r0, uint32_t& r1, uint32_t& r2,
                                       uint32_t& r3, uint32_t addr) {
    asm volatile("ldmatrix.sync.aligned.m8n8.x4.shared.b16 {%0,%1,%2,%3}, [%4];"
        : "=r"(r0), "=r"(r1), "=r"(r2), "=r"(r3) : "r"(addr));
}
__device__ __forceinline__ void ldmat2(uint32_t& r0, uint32_t& r1, uint32_t addr) {
    asm volatile("ldmatrix.sync.aligned.m8n8.x2.shared.b16 {%0,%1}, [%2];"
        : "=r"(r0), "=r"(r1) : "r"(addr));
}
__device__ __forceinline__ void mma_bf16(float* c, const uint32_t* a, const uint32_t* b) {
    asm volatile("mma.sync.aligned.m16n8k16.row.col.f32.bf16.bf16.f32 "
        "{%0,%1,%2,%3}, {%4,%5,%6,%7}, {%8,%9}, {%0,%1,%2,%3};"
        : "+f"(c[0]), "+f"(c[1]), "+f"(c[2]), "+f"(c[3])
        : "r"(a[0]), "r"(a[1]), "r"(a[2]), "r"(a[3]), "r"(b[0]), "r"(b[1]));
}
__device__ __forceinline__ uint32_t pack_bf2(float a, float b) {
    __nv_bfloat162 t = __floats2bfloat162_rn(a, b);
    return *reinterpret_cast<uint32_t*>(&t);
}
#define CP16(dst, src) \
    asm volatile("cp.async.cg.shared.global [%0], [%1], 16;" :: "r"(dst), "l"(src))
#define CPCOMMIT() asm volatile("cp.async.commit_group;" ::: "memory")
#define CPWAIT0()  asm volatile("cp.async.wait_group 0;" ::: "memory")
#define CPWAIT1()  asm volatile("cp.async.wait_group 1;" ::: "memory")

// ------------------------- weight pre-conversion + score zeroing --------------
// Transposed n-major planes: dst = off + n*K + k
//   W_post1 [512][64]  -> off 0      | W1 [128][256] -> off 32768
//   W_post2 [64][64]   -> off 65536  | W2 [512][256] -> off 69632
__global__ void k_convW(const float* __restrict__ Wa, const float* __restrict__ Wb,
                        const float* __restrict__ Wc, const float* __restrict__ Wd) {
    int idx = blockIdx.x * 256 + threadIdx.x;
    const float* W; int K, N, local;
    if (idx < 32768)      { W = Wa; K = 512; N = 64;  local = idx; }
    else if (idx < 65536) { W = Wb; K = 128; N = 256; local = idx - 32768; }
    else if (idx < 69632) { W = Wc; K = 64;  N = 64;  local = idx - 65536; }
    else                  { W = Wd; K = 512; N = 256; local = idx - 69632; }
    int n = local / K, k = local - n * K;
    g_wtb[idx] = __float2bfloat16(W[(size_t)k * N + n]);
    for (int z = idx; z < NN * 4; z += WTOT) { g_asrc[z] = 0.f; g_adst[z] = 0.f; }
}

__global__ void k_zs() {   // zero scores before layer-2 GEMM
    int i = blockIdx.x * 256 + threadIdx.x;
    if (i < NN * 4) g_asrc[i] = 0.f;
    else            g_adst[i - NN * 4] = 0.f;
}

// ------------------------- CSR build -----------------------------------------
__global__ void k_deg_init() { g_deg[blockIdx.x * 256 + threadIdx.x] = 1; }

__global__ void k_deg(const int* __restrict__ ei) {
    int i = blockIdx.x * 256 + threadIdx.x;
    int d = (i < NE) ? ei[NE + i] : ei[i - NE];
    atomicAdd(&g_deg[d], 1);
}

__global__ void k_scan_all() {   // 1 block x 1024; 64 elems/thread
    __shared__ int wsum[32];
    int tid = threadIdx.x, lane = tid & 31, wid = tid >> 5;
    int base = tid * 64;
    int s = 0;
    for (int i = 0; i < 64; i++) s += g_deg[base + i];
    int x = s;
#pragma unroll
    for (int o = 1; o < 32; o <<= 1) {
        int y = __shfl_up_sync(0xffffffffu, x, o);
        if (lane >= o) x += y;
    }
    if (lane == 31) wsum[wid] = x;
    __syncthreads();
    if (wid == 0) {
        int t = wsum[lane];
#pragma unroll
        for (int o = 1; o < 32; o <<= 1) {
            int y = __shfl_up_sync(0xffffffffu, t, o);
            if (lane >= o) t += y;
        }
        wsum[lane] = t;
    }
    __syncthreads();
    int run = (wid ? wsum[wid - 1] : 0) + x - s;
    for (int i = 0; i < 64; i++) {
        int v = g_deg[base + i];
        g_rp[base + i] = run;
        g_cursor[base + i] = run;
        run += v;
    }
    if (tid == 0) g_rp[NN] = ETOT;
}

__global__ void k_scatter(const int* __restrict__ ei) {
    int i = blockIdx.x * 256 + threadIdx.x;
    int s, d;
    if (i < NE)        { s = ei[i];          d = ei[NE + i]; }
    else if (i < E2)   { int e = i - NE; s = ei[NE + e]; d = ei[e]; }
    else               { s = d = i - E2; }
    int pos = atomicAdd(&g_cursor[d], 1);
    g_col[pos] = s;
}

// ------------------------- root projections ----------------------------------
__global__ void k_rootproj(const float* __restrict__ root,
                           const float* __restrict__ Wc1,
                           const float* __restrict__ Wc2) {
    int b = blockIdx.x, c = threadIdx.x;
    float a1 = 0.f, a2 = 0.f;
    for (int k = 0; k < DIN; k++) {
        float rv = root[b * DIN + k];
        a1 += rv * Wc1[k * 64 + c];
        a2 += rv * Wc2[k * 64 + c];
    }
    g_hc1[b * 64 + c] = a1;
    g_hc2[b * 64 + c] = a2;
}

#define LDS 72            // padded smem row stride for k_mmc (bf16): 144B

// ------------------------- MODE0: x @ W_post1, cp.async fp32 staging ----------
// 32-k fp32 stages double-buffered; convert to one bf16 plane.
// smem: Xs[2] 18432B | Ab 128x56 bf16 14336B | B[2] 64x56 bf16 7168B each
#define XSTRIDE 36
#define PLDS 56
#define XS_BYTES 18432
#define OFF_AB 36864
#define OFF_B  51200
#define B_BYTES 7168
#define SMM0_TOT 65536

__launch_bounds__(256, 2)
__global__ void k_mm0(const float* __restrict__ Aarg) {
    extern __shared__ __align__(16) char sm[];
    int tid = threadIdx.x, lane = tid & 31, w = tid >> 5;
    int wm = (w & 1) * 64, wn = (w >> 1) * 16;
    const float* Arow = Aarg + (size_t)blockIdx.y * 128 * 512;
    __nv_bfloat16* Ab = (__nv_bfloat16*)(sm + OFF_AB);

    float acc[4][2][4];
#pragma unroll
    for (int a = 0; a < 4; a++)
#pragma unroll
        for (int b = 0; b < 2; b++)
#pragma unroll
            for (int c = 0; c < 4; c++) acc[a][b][c] = 0.f;

    auto stage = [&](int it, int buf) {
        int k0 = it * 32;
        float* Xs = (float*)(sm + buf * XS_BYTES);
        __nv_bfloat16* Bb = (__nv_bfloat16*)(sm + OFF_B + buf * B_BYTES);
#pragma unroll
        for (int i = 0; i < 4; i++) {
            int idx = i * 256 + tid;
            int r = idx >> 3, c4 = (idx & 7) << 2;
            CP16(smem_u32(&Xs[r * XSTRIDE + c4]), &Arow[(size_t)r * 512 + k0 + c4]);
        }
        {
            int n = tid >> 2, c8 = (tid & 3) << 3;   // 256 threads cover 64x32
            CP16(smem_u32(&Bb[n * PLDS + c8]), &g_wtb[(size_t)n * 512 + k0 + c8]);
        }
        CPCOMMIT();
    };

    stage(0, 0);
    for (int it = 0; it < 16; it++) {
        int buf = it & 1;
        if (it + 1 < 16) { stage(it + 1, buf ^ 1); CPWAIT1(); }
        else             { CPWAIT0(); }
        __syncthreads();
        float* Xs = (float*)(sm + buf * XS_BYTES);
#pragma unroll
        for (int i = 0; i < 4; i++) {
            int idx = i * 256 + tid;
            int r = idx >> 3, c4 = (idx & 7) << 2;
            float4 v = *(const float4*)&Xs[r * XSTRIDE + c4];
            *(uint2*)&Ab[r * PLDS + c4] = make_uint2(pack_bf2(v.x, v.y), pack_bf2(v.z, v.w));
        }
        __syncthreads();
        __nv_bfloat16* Bb = (__nv_bfloat16*)(sm + OFF_B + buf * B_BYTES);
#pragma unroll
        for (int ks = 0; ks < 2; ks++) {
            int kb = ks * 16;
            uint32_t ah[4][4], bh[2][2];
            int arow = wm + (lane & 15);
            int acol = kb + (lane >> 4) * 8;
#pragma unroll
            for (int mf = 0; mf < 4; mf++)
                ldmat4(ah[mf][0], ah[mf][1], ah[mf][2], ah[mf][3],
                       smem_u32(&Ab[(arow + mf * 16) * PLDS + acol]));
            int brow = wn + (lane & 7);
            int bcol = kb + ((lane >> 3) & 1) * 8;
#pragma unroll
            for (int nf = 0; nf < 2; nf++)
                ldmat2(bh[nf][0], bh[nf][1], smem_u32(&Bb[(brow + nf * 8) * PLDS + bcol]));
#pragma unroll
            for (int mf = 0; mf < 4; mf++)
#pragma unroll
                for (int nf = 0; nf < 2; nf++)
                    mma_bf16(acc[mf][nf], ah[mf], bh[nf]);
        }
        __syncthreads();
    }

    // epilogue: PLA1 gate -> g_h1b plane
#pragma unroll
    for (int mf = 0; mf < 4; mf++)
#pragma unroll
        for (int nf = 0; nf < 2; nf++)
#pragma unroll
            for (int p = 0; p < 2; p++) {
                int row = blockIdx.y * 128 + wm + mf * 16 + (lane >> 2) + p * 8;
                int c   = wn + nf * 8 + (lane & 3) * 2;
                float v0 = acc[mf][nf][p * 2 + 0];
                float v1 = acc[mf][nf][p * 2 + 1];
                int gid = row >> 9;
                float hc0 = g_hc1[gid * 64 + c];
                float hc1 = g_hc1[gid * 64 + c + 1];
                float gs0 = 1.f / (1.f + __expf(-(v0 + hc0)));
                float gs1 = 1.f / (1.f + __expf(-(v1 + hc1)));
                float gv0 = gs0 * v0 + (1.f - gs0) * hc0;
                float gv1 = gs1 * v1 + (1.f - gs1) * hc1;
                size_t b0 = (size_t)row * 128 + c;
                *(uint32_t*)&g_h1b[b0]      = pack_bf2(gv0, gv1);
                *(uint32_t*)&g_h1b[b0 + 64] = pack_bf2(v0, v1);
            }
}

// ------------------- MODE 1/2/3: pure-copy, cp.async double-buffered ----------
// MODE 1: g_h1 @ W1      (K=128) -> g_hf + fused scores   grid(4, 512)
// MODE 2: g_xr @ W_post2 (K=64)  -> PLA2 -> g_x3          grid(1, 2048)
// MODE 3: g_x3 @ W2      (K=512) -> g_hf + fused scores   grid(4, 512)
template <int MODE>
__launch_bounds__(256, 3)
__global__ void k_mmc(const float* __restrict__ as_, const float* __restrict__ ad_) {
    constexpr int K    = (MODE == 3) ? 512 : (MODE == 1 ? 128 : 64);
    constexpr int KT   = K / 64;
    constexpr int WOFF = (MODE == 1) ? 32768 : (MODE == 2) ? 65536 : 69632;
    constexpr int ASZ  = 128 * LDS;
    constexpr int BSZ  = 64 * LDS;
    constexpr int STG  = ASZ + BSZ;

    extern __shared__ __align__(16) char sm[];
    __nv_bfloat16* base = (__nv_bfloat16*)sm;

    int tid = threadIdx.x, lane = tid & 31, w = tid >> 5;
    int wm = (w & 1) * 64, wn = (w >> 1) * 16;
    int n0 = blockIdx.x * 64;

    const __nv_bfloat16* Apb = ((MODE == 1) ? g_h1b : (MODE == 2) ? g_xrb : g_x3b)
                             + (size_t)blockIdx.y * 128 * K;

    float acc[4][2][4];
#pragma unroll
    for (int a = 0; a < 4; a++)
#pragma unroll
        for (int b = 0; b < 2; b++)
#pragma unroll
            for (int c = 0; c < 4; c++) acc[a][b][c] = 0.f;

    auto stage = [&](int k0, int buf) {
        __nv_bfloat16* Ab = base + buf * STG;
        __nv_bfloat16* Bb = Ab + ASZ;
#pragma unroll
        for (int i = 0; i < 4; i++) {
            int idx = i * 256 + tid;
            int r = idx >> 3, c8 = (idx & 7) << 3;
            CP16(smem_u32(&Ab[r * LDS + c8]), &Apb[(size_t)r * K + k0 + c8]);
        }
        {
            int n = tid >> 2, c8 = (tid & 3) << 3;   // 64 rows x 32 k... need 64k
            // 64 rows x 64 k = 512 x 16B loads; 256 threads -> 2 each
            int idx0 = tid, idx1 = tid + 256;
            int n_0 = idx0 >> 3, c_0 = (idx0 & 7) << 3;
            int n_1 = idx1 >> 3, c_1 = (idx1 & 7) << 3;
            CP16(smem_u32(&Bb[n_0 * LDS + c_0]),
                 &g_wtb[(size_t)WOFF + (size_t)(n0 + n_0) * K + k0 + c_0]);
            CP16(smem_u32(&Bb[n_1 * LDS + c_1]),
                 &g_wtb[(size_t)WOFF + (size_t)(n0 + n_1) * K + k0 + c_1]);
            (void)n; (void)c8;
        }
        CPCOMMIT();
    };

    stage(0, 0);
    int buf = 0;
    for (int it = 0; it < KT; it++) {
        if (it + 1 < KT) { stage((it + 1) * 64, buf ^ 1); CPWAIT1(); }
        else             { CPWAIT0(); }
        __syncthreads();
        __nv_bfloat16* Ab = base + buf * STG;
        __nv_bfloat16* Bb = Ab + ASZ;
#pragma unroll
        for (int ks = 0; ks < 4; ks++) {
            int kb = ks * 16;
            uint32_t ah[4][4], bh[2][2];
            int arow = wm + (lane & 15);
            int acol = kb + (lane >> 4) * 8;
#pragma unroll
            for (int mf = 0; mf < 4; mf++)
                ldmat4(ah[mf][0], ah[mf][1], ah[mf][2], ah[mf][3],
                       smem_u32(&Ab[(arow + mf * 16) * LDS + acol]));
            int brow = wn + (lane & 7);
            int bcol = kb + ((lane >> 3) & 1) * 8;
#pragma unroll
            for (int nf = 0; nf < 2; nf++)
                ldmat2(bh[nf][0], bh[nf][1], smem_u32(&Bb[(brow + nf * 8) * LDS + bcol]));
#pragma unroll
            for (int mf = 0; mf < 4; mf++)
#pragma unroll
                for (int nf = 0; nf < 2; nf++)
                    mma_bf16(acc[mf][nf], ah[mf], bh[nf]);
        }
        __syncthreads();
        buf ^= 1;
    }

    if (MODE == 1 || MODE == 3) {
#pragma unroll
        for (int mf = 0; mf < 4; mf++)
#pragma unroll
            for (int p = 0; p < 2; p++) {
                int row = blockIdx.y * 128 + wm + mf * 16 + (lane >> 2) + p * 8;
                float ps = 0.f, pd = 0.f;
#pragma unroll
                for (int nf = 0; nf < 2; nf++) {
                    int c = wn + nf * 8 + (lane & 3) * 2;
                    float v0 = acc[mf][nf][p * 2 + 0];
                    float v1 = acc[mf][nf][p * 2 + 1];
                    g_hf[(size_t)row * 256 + n0 + c]     = v0;
                    g_hf[(size_t)row * 256 + n0 + c + 1] = v1;
                    ps += v0 * as_[n0 + c] + v1 * as_[n0 + c + 1];
                    pd += v0 * ad_[n0 + c] + v1 * ad_[n0 + c + 1];
                }
                ps += __shfl_xor_sync(0xffffffffu, ps, 1);
                ps += __shfl_xor_sync(0xffffffffu, ps, 2);
                pd += __shfl_xor_sync(0xffffffffu, pd, 1);
                pd += __shfl_xor_sync(0xffffffffu, pd, 2);
                if ((lane & 3) == 0) {
                    int h = n0 >> 6;
                    atomicAdd(&g_asrc[row * 4 + h], ps);
                    atomicAdd(&g_adst[row * 4 + h], pd);
                }
            }
    } else {
#pragma unroll
        for (int mf = 0; mf < 4; mf++)
#pragma unroll
            for (int nf = 0; nf < 2; nf++)
#pragma unroll
                for (int p = 0; p < 2; p++) {
                    int row = blockIdx.y * 128 + wm + mf * 16 + (lane >> 2) + p * 8;
                    int c   = wn + nf * 8 + (lane & 3) * 2;
                    float v0 = acc[mf][nf][p * 2 + 0];
                    float v1 = acc[mf][nf][p * 2 + 1];
                    int gid = row >> 11;
                    float hc0 = g_hc2[gid * 64 + c];
                    float hc1 = g_hc2[gid * 64 + c + 1];
                    float gs0 = 1.f / (1.f + __expf(-(v0 + hc0)));
                    float gs1 = 1.f / (1.f + __expf(-(v1 + hc1)));
                    float gv0 = gs0 * v0 + (1.f - gs0) * hc0;
                    float gv1 = gs1 * v1 + (1.f - gs1) * hc1;
                    size_t b0 = (size_t)row * 128 + c;
                    *(uint32_t*)&g_x3b[b0]      = pack_bf2(gv0, gv1);
                    *(uint32_t*)&g_x3b[b0 + 64] = pack_bf2(v0, v1);
                }
    }
}

// ------------------------- GAT aggregation (warp per dst) --------------------
__device__ __forceinline__ float lrelu(float x) { return x > 0.f ? x : 0.2f * x; }

template <int CONCAT>
__launch_bounds__(256)
__global__ void k_agg(const float* __restrict__ bias) {
    int n = (blockIdx.x * 256 + threadIdx.x) >> 5;
    int lane = threadIdx.x & 31;
    int rs = g_rp[n], re = g_rp[n + 1];
    float ad0 = g_adst[n * 4 + 0], ad1 = g_adst[n * 4 + 1];
    float ad2 = g_adst[n * 4 + 2], ad3 = g_adst[n * 4 + 3];

    float m0 = -1e30f, m1 = -1e30f, m2 = -1e30f, m3 = -1e30f;
    for (int j = rs + lane; j < re; j += 32) {
        int s = g_col[j];
        m0 = fmaxf(m0, lrelu(g_asrc[s * 4 + 0] + ad0));
        m1 = fmaxf(m1, lrelu(g_asrc[s * 4 + 1] + ad1));
        m2 = fmaxf(m2, lrelu(g_asrc[s * 4 + 2] + ad2));
        m3 = fmaxf(m3, lrelu(g_asrc[s * 4 + 3] + ad3));
    }
#pragma unroll
    for (int o = 16; o; o >>= 1) {
        m0 = fmaxf(m0, __shfl_xor_sync(0xffffffffu, m0, o));
        m1 = fmaxf(m1, __shfl_xor_sync(0xffffffffu, m1, o));
        m2 = fmaxf(m2, __shfl_xor_sync(0xffffffffu, m2, o));
        m3 = fmaxf(m3, __shfl_xor_sync(0xffffffffu, m3, o));
    }
    float d0 = 0.f, d1 = 0.f, d2 = 0.f, d3 = 0.f;
    for (int j = rs + lane; j < re; j += 32) {
        int s = g_col[j];
        d0 += __expf(lrelu(g_asrc[s * 4 + 0] + ad0) - m0);
        d1 += __expf(lrelu(g_asrc[s * 4 + 1] + ad1) - m1);
        d2 += __expf(lrelu(g_asrc[s * 4 + 2] + ad2) - m2);
        d3 += __expf(lrelu(g_asrc[s * 4 + 3] + ad3) - m3);
    }
#pragma unroll
    for (int o = 16; o; o >>= 1) {
        d0 += __shfl_xor_sync(0xffffffffu, d0, o);
        d1 += __shfl_xor_sync(0xffffffffu, d1, o);
        d2 += __shfl_xor_sync(0xffffffffu, d2, o);
        d3 += __shfl_xor_sync(0xffffffffu, d3, o);
    }
    float i0 = 1.f / d0, i1 = 1.f / d1, i2 = 1.f / d2, i3 = 1.f / d3;

    float acc[8] = {0, 0, 0, 0, 0, 0, 0, 0};
    for (int j = rs; j < re; j++) {
        int s = g_col[j];
        float w0 = __expf(lrelu(g_asrc[s * 4 + 0] + ad0) - m0) * i0;
        float w1 = __expf(lrelu(g_asrc[s * 4 + 1] + ad1) - m1) * i1;
        float w2 = __expf(lrelu(g_asrc[s * 4 + 2] + ad2) - m2) * i2;
        float w3 = __expf(lrelu(g_asrc[s * 4 + 3] + ad3) - m3) * i3;
        const float* hr = g_hf + (size_t)s * 256;
        acc[0] += w0 * hr[lane];       acc[1] += w0 * hr[lane + 32];
        acc[2] += w1 * hr[lane + 64];  acc[3] += w1 * hr[lane + 96];
        acc[4] += w2 * hr[lane + 128]; acc[5] += w2 * hr[lane + 160];
        acc[6] += w3 * hr[lane + 192]; acc[7] += w3 * hr[lane + 224];
    }
    if (CONCAT) {
#pragma unroll
        for (int k = 0; k < 8; k++) {
            int c = lane + 32 * k;
            float v = fmaxf(acc[k] + bias[c], 0.f);
            g_xrb[(size_t)n * 256 + c] = __float2bfloat16(v);
        }
    } else {
        float o0 = 0.25f * (acc[0] + acc[2] + acc[4] + acc[6]) + bias[lane];
        float o1 = 0.25f * (acc[1] + acc[3] + acc[5] + acc[7]) + bias[lane + 32];
        g_xr2[(size_t)n * 64 + lane]      = fmaxf(o0, 0.f);
        g_xr2[(size_t)n * 64 + lane + 32] = fmaxf(o1, 0.f);
    }
}

// ------------------------- scorer head + pooling -----------------------------
__global__ void k_zero() { g_gsum[blockIdx.x * 256 + threadIdx.x] = 0.f; }

__launch_bounds__(256)
__global__ void k_final(const float* __restrict__ Wfc, const float* __restrict__ bfc) {
    extern __shared__ float Ws[];
    __shared__ float s_hc3[64];
    __shared__ float part_sh[8][64];
    __shared__ float part_ss[8][64];
    int tid = threadIdx.x, lane = tid & 31, w = tid >> 5;
    int g = blockIdx.x >> 1;

    for (int i = tid; i < 4096; i += 256)
        ((float4*)Ws)[i] = ((const float4*)Wfc)[i];
    if (tid < 64) s_hc3[tid] = g_xr2[((size_t)g << 9) * 64 + tid];
    __syncthreads();

    float bL = bfc[lane], bH = bfc[lane + 32];
    float shL = 0.f, shH = 0.f, ssL = 0.f, ssH = 0.f;
    int nbase = blockIdx.x * 256 + w * 32;

    for (int g4 = 0; g4 < 8; g4++) {
        int n0 = nbase + g4 * 4;
        float xl[4], xh[4], aL[4], aH[4];
#pragma unroll
        for (int u = 0; u < 4; u++) {
            xl[u] = g_xr2[(size_t)(n0 + u) * 64 + lane];
            xh[u] = g_xr2[(size_t)(n0 + u) * 64 + lane + 32];
            aL[u] = bL; aH[u] = bH;
        }
#pragma unroll 4
        for (int j = 0; j < 64; j++) {
            float h3 = s_hc3[j];
            float w0 = Ws[j * 64 + lane];
            float w1 = Ws[(64 + j) * 64 + lane];
            float w2 = Ws[(128 + j) * 64 + lane];
            float w3 = Ws[(192 + j) * 64 + lane];
            float v0 = Ws[j * 64 + lane + 32];
            float v1 = Ws[(64 + j) * 64 + lane + 32];
            float v2 = Ws[(128 + j) * 64 + lane + 32];
            float v3 = Ws[(192 + j) * 64 + lane + 32];
#pragma unroll
            for (int u = 0; u < 4; u++) {
                float xj = (j < 32) ? __shfl_sync(0xffffffffu, xl[u], j)
                                    : __shfl_sync(0xffffffffu, xh[u], j - 32);
                float p = xj * h3;
                float q = fabsf(h3 - xj);
                aL[u] += h3 * w0 + xj * w1 + p * w2 + q * w3;
                aH[u] += h3 * v0 + xj * v1 + p * v2 + q * v3;
            }
        }
#pragma unroll
        for (int u = 0; u < 4; u++) {
            float tL = tanhf(aL[u]), tH = tanhf(aH[u]);
            float mx = fmaxf(tL, tH);
#pragma unroll
            for (int o = 16; o; o >>= 1) mx = fmaxf(mx, __shfl_xor_sync(0xffffffffu, mx, o));
            float eL = __expf(tL - mx), eH = __expf(tH - mx);
            float sm = eL + eH;
#pragma unroll
            for (int o = 16; o; o >>= 1) sm += __shfl_xor_sync(0xffffffffu, sm, o);
            float inv = 1.f / sm;
            shL += eL * inv * xl[u]; shH += eH * inv * xh[u];
            ssL += xl[u];            ssH += xh[u];
        }
    }
    part_sh[w][lane] = shL; part_sh[w][lane + 32] = shH;
    part_ss[w][lane] = ssL; part_ss[w][lane + 32] = ssH;
    __syncthreads();
    if (tid < 128) {
        int c = tid & 63;
        float s = 0.f;
        if (tid < 64) {
            for (int ww = 0; ww < 8; ww++) s += part_sh[ww][c];
            atomicAdd(&g_gsum[g * 128 + c], s);
        } else {
            for (int ww = 0; ww < 8; ww++) s += part_ss[ww][c];
            atomicAdd(&g_gsum[g * 128 + 64 + c], s);
        }
    }
}

__global__ void k_logits(const float* __restrict__ Wc, const float* __restrict__ bc,
                         float* __restrict__ out) {
    int b = threadIdx.x;
    float l[4] = {bc[0], bc[1], bc[2], bc[3]};
    const float inv = 1.f / 512.f;
    for (int j = 0; j < 128; j++) {
        float v = g_gsum[b * 128 + j] * inv;
#pragma unroll
        for (int c = 0; c < 4; c++) l[c] += v * Wc[j * 4 + c];
    }
    float mx = fmaxf(fmaxf(l[0], l[1]), fmaxf(l[2], l[3]));
    float s = expf(l[0] - mx) + expf(l[1] - mx) + expf(l[2] - mx) + expf(l[3] - mx);
    float lse = mx + logf(s);
#pragma unroll
    for (int c = 0; c < 4; c++) out[b * 4 + c] = l[c] - lse;
}

// ------------------------- launch --------------------------------------------
extern "C" void kernel_launch(void* const* d_in, const int* in_sizes, int n_in,
                              void* d_out, int out_size) {
    const float* x        = (const float*)d_in[0];
    const float* root     = (const float*)d_in[1];
    const int*   ei       = (const int*)d_in[2];
    const float* W_post1  = (const float*)d_in[5];
    const float* W_claim1 = (const float*)d_in[6];
    const float* W1       = (const float*)d_in[7];
    const float* att_src1 = (const float*)d_in[8];
    const float* att_dst1 = (const float*)d_in[9];
    const float* b1       = (const float*)d_in[10];
    const float* W_post2  = (const float*)d_in[11];
    const float* W_claim2 = (const float*)d_in[12];
    const float* W2       = (const float*)d_in[13];
    const float* att_src2 = (const float*)d_in[14];
    const float* att_dst2 = (const float*)d_in[15];
    const float* b2       = (const float*)d_in[16];
    const float* W_fc     = (const float*)d_in[17];
    const float* b_fc     = (const float*)d_in[18];
    const float* W_clf    = (const float*)d_in[19];
    const float* b_clf    = (const float*)d_in[20];
    float* out = (float*)d_out;

    const int SMMC = (128 * LDS + 64 * LDS) * 2 * 2;   // 55296 (2 bufs, bf16)
    cudaFuncSetAttribute(k_final,  cudaFuncAttributeMaxDynamicSharedMemorySize, 65536);
    cudaFuncSetAttribute(k_mm0,    cudaFuncAttributeMaxDynamicSharedMemorySize, SMM0_TOT);
    cudaFuncSetAttribute(k_mmc<1>, cudaFuncAttributeMaxDynamicSharedMemorySize, SMMC);
    cudaFuncSetAttribute(k_mmc<2>, cudaFuncAttributeMaxDynamicSharedMemorySize, SMMC);
    cudaFuncSetAttribute(k_mmc<3>, cudaFuncAttributeMaxDynamicSharedMemorySize, SMMC);

    k_rootproj<<<NB, 64>>>(root, W_claim1, W_claim2);                   // 0
    k_convW<<<WTOT / 256, 256>>>(W_post1, W1, W_post2, W2);             // 1 (+zero scores)
    k_mm0<<<dim3(1, NN / 128), 256, SMM0_TOT>>>(x);                     // 2  PLA1
    k_mmc<1><<<dim3(4, NN / 128), 256, SMMC>>>(att_src1, att_dst1);     // 3  GAT1 lin+scores
    k_deg_init<<<NN / 256, 256>>>();                                    // 4
    k_deg<<<E2 / 256, 256>>>(ei);                                       // 5
    k_scan_all<<<1, 1024>>>();                                          // 6
    k_scatter<<<ETOT / 256, 256>>>(ei);                                 // 7

    k_agg<1><<<NN * 32 / 256, 256>>>(b1);
    k_mmc<2><<<dim3(1, NN * 4 / 128), 256, SMMC>>>(nullptr, nullptr);   // PLA2
    k_zs<<<NN * 8 / 256, 256>>>();                                      // zero layer-2 scores
    k_mmc<3><<<dim3(4, NN / 128), 256, SMMC>>>(att_src2, att_dst2);     // GAT2 lin+scores
    k_agg<0><<<NN * 32 / 256, 256>>>(b2);

    k_zero<<<NB * 128 / 256, 256>>>();
    k_final<<<NN / 256, 256, 65536>>>(W_fc, b_fc);
    k_logits<<<1, 128>>>(W_clf, b_clf, out);
}

// round 14
// speedup vs baseline: 1.6154x; 1.0492x over previous
#include <cuda_runtime.h>
#include <cuda_bf16.h>
#include <cstdint>

#define NN 65536      // nodes
#define NB 128        // graphs
#define NE 65536      // raw directed edges
#define E2 131072     // TD + BU
#define ETOT 196608   // + self loops
#define DIN 512
#define WTOT 200704   // total weight elements (all 4 matrices)

// ------------------------- scratch (device globals; no allocs) ---------------
__device__ uint32_t g_hfw[NN * 128];  // GAT lin output, packed bf16x2 (2ch/word)
__device__ float g_xr2[NN * 64];      // relu(GAT2 out)
__device__ float g_asrc[NN * 4];
__device__ float g_adst[NN * 4];
__device__ float g_hc1[NB * 64];
__device__ float g_hc2[NB * 64];
__device__ float g_gsum[NB * 128];
__device__ int   g_deg[NN];
__device__ int   g_rp [NN + 1];
__device__ int   g_cursor[NN];
__device__ int   g_col[ETOT];
// bf16 operand planes (converted exactly once)
__device__ __nv_bfloat16 g_h1b[NN * 128];   // PLA1 out (MODE1 A)
__device__ __nv_bfloat16 g_xrb[NN * 256];   // relu(GAT1) (MODE2 A)
__device__ __nv_bfloat16 g_x3b[NN * 512];   // PLA2 out (MODE3 A)
__device__ __nv_bfloat16 g_wtb[WTOT];       // transposed weights

// ------------------------- helpers -------------------------------------------
__device__ __forceinline__ uint32_t smem_u32(const void* p) {
    uint32_t a;
    asm("{ .reg .u64 t; cvta.to.shared.u64 t, %1; cvt.u32.u64 %0, t; }" : "=r"(a) : "l"(p));
    return a;
}
__device__ __forceinline__ void ldmat4(uint32_t& r0, uint32_t& r1, uint32_t& r2,
                                       uint32_t& r3, uint32_t addr) {
    asm volatile("ldmatrix.sync.aligned.m8n8.x4.shared.b16 {%0,%1,%2,%3}, [%4];"
        : "=r"(r0), "=r"(r1), "=r"(r2), "=r"(r3) : "r"(addr));
}
__device__ __forceinline__ void mma_bf16(float* c, const uint32_t* a, const uint32_t* b) {
    asm volatile("mma.sync.aligned.m16n8k16.row.col.f32.bf16.bf16.f32 "
        "{%0,%1,%2,%3}, {%4,%5,%6,%7}, {%8,%9}, {%0,%1,%2,%3};"
        : "+f"(c[0]), "+f"(c[1]), "+f"(c[2]), "+f"(c[3])
        : "r"(a[0]), "r"(a[1]), "r"(a[2]), "r"(a[3]), "r"(b[0]), "r"(b[1]));
}
__device__ __forceinline__ uint32_t pack_bf2(float a, float b) {
    __nv_bfloat162 t = __floats2bfloat162_rn(a, b);
    return *reinterpret_cast<uint32_t*>(&t);
}
#define CP16(dst, src) \
    asm volatile("cp.async.cg.shared.global [%0], [%1], 16;" :: "r"(dst), "l"(src))
#define CPCOMMIT() asm volatile("cp.async.commit_group;" ::: "memory")
#define CPWAIT0()  asm volatile("cp.async.wait_group 0;" ::: "memory")
#define CPWAIT1()  asm volatile("cp.async.wait_group 1;" ::: "memory")

// ------------------------- weight pre-conversion + score zeroing --------------
__global__ void k_convW(const float* __restrict__ Wa, const float* __restrict__ Wb,
                        const float* __restrict__ Wc, const float* __restrict__ Wd) {
    int idx = blockIdx.x * 256 + threadIdx.x;
    const float* W; int K, N, local;
    if (idx < 32768)      { W = Wa; K = 512; N = 64;  local = idx; }
    else if (idx < 65536) { W = Wb; K = 128; N = 256; local = idx - 32768; }
    else if (idx < 69632) { W = Wc; K = 64;  N = 64;  local = idx - 65536; }
    else                  { W = Wd; K = 512; N = 256; local = idx - 69632; }
    int n = local / K, k = local - n * K;
    g_wtb[idx] = __float2bfloat16(W[(size_t)k * N + n]);
    for (int z = idx; z < NN * 4; z += WTOT) { g_asrc[z] = 0.f; g_adst[z] = 0.f; }
}

__global__ void k_zs() {
    int i = blockIdx.x * 256 + threadIdx.x;
    if (i < NN * 4) g_asrc[i] = 0.f;
    else            g_adst[i - NN * 4] = 0.f;
}

// ------------------------- CSR build -----------------------------------------
__global__ void k_deg_init() { g_deg[blockIdx.x * 256 + threadIdx.x] = 1; }

__global__ void k_deg(const int* __restrict__ ei) {
    int i = blockIdx.x * 256 + threadIdx.x;
    int d = (i < NE) ? ei[NE + i] : ei[i - NE];
    atomicAdd(&g_deg[d], 1);
}

__global__ void k_scan_all() {
    __shared__ int wsum[32];
    int tid = threadIdx.x, lane = tid & 31, wid = tid >> 5;
    int base = tid * 64;
    int s = 0;
    for (int i = 0; i < 64; i++) s += g_deg[base + i];
    int x = s;
#pragma unroll
    for (int o = 1; o < 32; o <<= 1) {
        int y = __shfl_up_sync(0xffffffffu, x, o);
        if (lane >= o) x += y;
    }
    if (lane == 31) wsum[wid] = x;
    __syncthreads();
    if (wid == 0) {
        int t = wsum[lane];
#pragma unroll
        for (int o = 1; o < 32; o <<= 1) {
            int y = __shfl_up_sync(0xffffffffu, t, o);
            if (lane >= o) t += y;
        }
        wsum[lane] = t;
    }
    __syncthreads();
    int run = (wid ? wsum[wid - 1] : 0) + x - s;
    for (int i = 0; i < 64; i++) {
        int v = g_deg[base + i];
        g_rp[base + i] = run;
        g_cursor[base + i] = run;
        run += v;
    }
    if (tid == 0) g_rp[NN] = ETOT;
}

__global__ void k_scatter(const int* __restrict__ ei) {
    int i = blockIdx.x * 256 + threadIdx.x;
    int s, d;
    if (i < NE)        { s = ei[i];          d = ei[NE + i]; }
    else if (i < E2)   { int e = i - NE; s = ei[NE + e]; d = ei[e]; }
    else               { s = d = i - E2; }
    int pos = atomicAdd(&g_cursor[d], 1);
    g_col[pos] = s;
}

// ------------------------- root projections ----------------------------------
__global__ void k_rootproj(const float* __restrict__ root,
                           const float* __restrict__ Wc1,
                           const float* __restrict__ Wc2) {
    int b = blockIdx.x, c = threadIdx.x;
    float a1 = 0.f, a2 = 0.f;
    for (int k = 0; k < DIN; k++) {
        float rv = root[b * DIN + k];
        a1 += rv * Wc1[k * 64 + c];
        a2 += rv * Wc2[k * 64 + c];
    }
    g_hc1[b * 64 + c] = a1;
    g_hc2[b * 64 + c] = a2;
}

#define LDS 72            // padded smem row stride for k_mmc (bf16): 144B

// ------------------------- MODE0: x @ W_post1, cp.async fp32 staging ----------
#define XSTRIDE 36
#define PLDS 56
#define XS_BYTES 18432
#define OFF_AB 36864
#define OFF_B  51200
#define B_BYTES 7168
#define SMM0_TOT 65536

__launch_bounds__(256, 2)
__global__ void k_mm0(const float* __restrict__ Aarg) {
    extern __shared__ __align__(16) char sm[];
    int tid = threadIdx.x, lane = tid & 31, w = tid >> 5;
    int wm = (w & 1) * 64, wn = (w >> 1) * 16;
    const float* Arow = Aarg + (size_t)blockIdx.y * 128 * 512;
    __nv_bfloat16* Ab = (__nv_bfloat16*)(sm + OFF_AB);

    float acc[4][2][4];
#pragma unroll
    for (int a = 0; a < 4; a++)
#pragma unroll
        for (int b = 0; b < 2; b++)
#pragma unroll
            for (int c = 0; c < 4; c++) acc[a][b][c] = 0.f;

    auto stage = [&](int it, int buf) {
        int k0 = it * 32;
        float* Xs = (float*)(sm + buf * XS_BYTES);
        __nv_bfloat16* Bb = (__nv_bfloat16*)(sm + OFF_B + buf * B_BYTES);
#pragma unroll
        for (int i = 0; i < 4; i++) {
            int idx = i * 256 + tid;
            int r = idx >> 3, c4 = (idx & 7) << 2;
            CP16(smem_u32(&Xs[r * XSTRIDE + c4]), &Arow[(size_t)r * 512 + k0 + c4]);
        }
        {
            int n = tid >> 2, c8 = (tid & 3) << 3;
            CP16(smem_u32(&Bb[n * PLDS + c8]), &g_wtb[(size_t)n * 512 + k0 + c8]);
        }
        CPCOMMIT();
    };

    stage(0, 0);
    for (int it = 0; it < 16; it++) {
        int buf = it & 1;
        if (it + 1 < 16) { stage(it + 1, buf ^ 1); CPWAIT1(); }
        else             { CPWAIT0(); }
        __syncthreads();
        float* Xs = (float*)(sm + buf * XS_BYTES);
#pragma unroll
        for (int i = 0; i < 4; i++) {
            int idx = i * 256 + tid;
            int r = idx >> 3, c4 = (idx & 7) << 2;
            float4 v = *(const float4*)&Xs[r * XSTRIDE + c4];
            *(uint2*)&Ab[r * PLDS + c4] = make_uint2(pack_bf2(v.x, v.y), pack_bf2(v.z, v.w));
        }
        __syncthreads();
        __nv_bfloat16* Bb = (__nv_bfloat16*)(sm + OFF_B + buf * B_BYTES);
#pragma unroll
        for (int ks = 0; ks < 2; ks++) {
            int kb = ks * 16;
            uint32_t ah[4][4], bh[2][2];
            int arow = wm + (lane & 15);
            int acol = kb + (lane >> 4) * 8;
#pragma unroll
            for (int mf = 0; mf < 4; mf++)
                ldmat4(ah[mf][0], ah[mf][1], ah[mf][2], ah[mf][3],
                       smem_u32(&Ab[(arow + mf * 16) * PLDS + acol]));
            {
                int rr = lane & 7, g = lane >> 3;
                ldmat4(bh[0][0], bh[0][1], bh[1][0], bh[1][1],
                       smem_u32(&Bb[(wn + (g >> 1) * 8 + rr) * PLDS + kb + (g & 1) * 8]));
            }
#pragma unroll
            for (int mf = 0; mf < 4; mf++)
#pragma unroll
                for (int nf = 0; nf < 2; nf++)
                    mma_bf16(acc[mf][nf], ah[mf], bh[nf]);
        }
        __syncthreads();
    }

#pragma unroll
    for (int mf = 0; mf < 4; mf++)
#pragma unroll
        for (int nf = 0; nf < 2; nf++)
#pragma unroll
            for (int p = 0; p < 2; p++) {
                int row = blockIdx.y * 128 + wm + mf * 16 + (lane >> 2) + p * 8;
                int c   = wn + nf * 8 + (lane & 3) * 2;
                float v0 = acc[mf][nf][p * 2 + 0];
                float v1 = acc[mf][nf][p * 2 + 1];
                int gid = row >> 9;
                float hc0 = g_hc1[gid * 64 + c];
                float hc1 = g_hc1[gid * 64 + c + 1];
                float gs0 = 1.f / (1.f + __expf(-(v0 + hc0)));
                float gs1 = 1.f / (1.f + __expf(-(v1 + hc1)));
                float gv0 = gs0 * v0 + (1.f - gs0) * hc0;
                float gv1 = gs1 * v1 + (1.f - gs1) * hc1;
                size_t b0 = (size_t)row * 128 + c;
                *(uint32_t*)&g_h1b[b0]      = pack_bf2(gv0, gv1);
                *(uint32_t*)&g_h1b[b0 + 64] = pack_bf2(v0, v1);
            }
}

// ------------------- MODE 1/2/3: pure-copy, cp.async double-buffered ----------
template <int MODE>
__launch_bounds__(256, 3)
__global__ void k_mmc(const float* __restrict__ as_, const float* __restrict__ ad_) {
    constexpr int K    = (MODE == 3) ? 512 : (MODE == 1 ? 128 : 64);
    constexpr int KT   = K / 64;
    constexpr int WOFF = (MODE == 1) ? 32768 : (MODE == 2) ? 65536 : 69632;
    constexpr int ASZ  = 128 * LDS;
    constexpr int BSZ  = 64 * LDS;
    constexpr int STG  = ASZ + BSZ;

    extern __shared__ __align__(16) char sm[];
    __nv_bfloat16* base = (__nv_bfloat16*)sm;

    int tid = threadIdx.x, lane = tid & 31, w = tid >> 5;
    int wm = (w & 1) * 64, wn = (w >> 1) * 16;
    int n0 = blockIdx.x * 64;

    const __nv_bfloat16* Apb = ((MODE == 1) ? g_h1b : (MODE == 2) ? g_xrb : g_x3b)
                             + (size_t)blockIdx.y * 128 * K;

    float acc[4][2][4];
#pragma unroll
    for (int a = 0; a < 4; a++)
#pragma unroll
        for (int b = 0; b < 2; b++)
#pragma unroll
            for (int c = 0; c < 4; c++) acc[a][b][c] = 0.f;

    auto stage = [&](int k0, int buf) {
        __nv_bfloat16* Ab = base + buf * STG;
        __nv_bfloat16* Bb = Ab + ASZ;
#pragma unroll
        for (int i = 0; i < 4; i++) {
            int idx = i * 256 + tid;
            int r = idx >> 3, c8 = (idx & 7) << 3;
            CP16(smem_u32(&Ab[r * LDS + c8]), &Apb[(size_t)r * K + k0 + c8]);
        }
        {
            int idx0 = tid, idx1 = tid + 256;
            int n_0 = idx0 >> 3, c_0 = (idx0 & 7) << 3;
            int n_1 = idx1 >> 3, c_1 = (idx1 & 7) << 3;
            CP16(smem_u32(&Bb[n_0 * LDS + c_0]),
                 &g_wtb[(size_t)WOFF + (size_t)(n0 + n_0) * K + k0 + c_0]);
            CP16(smem_u32(&Bb[n_1 * LDS + c_1]),
                 &g_wtb[(size_t)WOFF + (size_t)(n0 + n_1) * K + k0 + c_1]);
        }
        CPCOMMIT();
    };

    stage(0, 0);
    int buf = 0;
    for (int it = 0; it < KT; it++) {
        if (it + 1 < KT) { stage((it + 1) * 64, buf ^ 1); CPWAIT1(); }
        else             { CPWAIT0(); }
        __syncthreads();
        __nv_bfloat16* Ab = base + buf * STG;
        __nv_bfloat16* Bb = Ab + ASZ;
#pragma unroll
        for (int ks = 0; ks < 4; ks++) {
            int kb = ks * 16;
            uint32_t ah[4][4], bh[2][2];
            int arow = wm + (lane & 15);
            int acol = kb + (lane >> 4) * 8;
#pragma unroll
            for (int mf = 0; mf < 4; mf++)
                ldmat4(ah[mf][0], ah[mf][1], ah[mf][2], ah[mf][3],
                       smem_u32(&Ab[(arow + mf * 16) * LDS + acol]));
            {
                int rr = lane & 7, g = lane >> 3;
                ldmat4(bh[0][0], bh[0][1], bh[1][0], bh[1][1],
                       smem_u32(&Bb[(wn + (g >> 1) * 8 + rr) * LDS + kb + (g & 1) * 8]));
            }
#pragma unroll
            for (int mf = 0; mf < 4; mf++)
#pragma unroll
                for (int nf = 0; nf < 2; nf++)
                    mma_bf16(acc[mf][nf], ah[mf], bh[nf]);
        }
        __syncthreads();
        buf ^= 1;
    }

    if (MODE == 1 || MODE == 3) {
#pragma unroll
        for (int mf = 0; mf < 4; mf++)
#pragma unroll
            for (int p = 0; p < 2; p++) {
                int row = blockIdx.y * 128 + wm + mf * 16 + (lane >> 2) + p * 8;
                float ps = 0.f, pd = 0.f;
#pragma unroll
                for (int nf = 0; nf < 2; nf++) {
                    int c = wn + nf * 8 + (lane & 3) * 2;
                    float v0 = acc[mf][nf][p * 2 + 0];
                    float v1 = acc[mf][nf][p * 2 + 1];
                    g_hfw[(size_t)row * 128 + ((n0 + c) >> 1)] = pack_bf2(v0, v1);
                    ps += v0 * as_[n0 + c] + v1 * as_[n0 + c + 1];
                    pd += v0 * ad_[n0 + c] + v1 * ad_[n0 + c + 1];
                }
                ps += __shfl_xor_sync(0xffffffffu, ps, 1);
                ps += __shfl_xor_sync(0xffffffffu, ps, 2);
                pd += __shfl_xor_sync(0xffffffffu, pd, 1);
                pd += __shfl_xor_sync(0xffffffffu, pd, 2);
                if ((lane & 3) == 0) {
                    int h = n0 >> 6;
                    atomicAdd(&g_asrc[row * 4 + h], ps);
                    atomicAdd(&g_adst[row * 4 + h], pd);
                }
            }
    } else {
#pragma unroll
        for (int mf = 0; mf < 4; mf++)
#pragma unroll
            for (int nf = 0; nf < 2; nf++)
#pragma unroll
                for (int p = 0; p < 2; p++) {
                    int row = blockIdx.y * 128 + wm + mf * 16 + (lane >> 2) + p * 8;
                    int c   = wn + nf * 8 + (lane & 3) * 2;
                    float v0 = acc[mf][nf][p * 2 + 0];
                    float v1 = acc[mf][nf][p * 2 + 1];
                    int gid = row >> 11;
                    float hc0 = g_hc2[gid * 64 + c];
                    float hc1 = g_hc2[gid * 64 + c + 1];
                    float gs0 = 1.f / (1.f + __expf(-(v0 + hc0)));
                    float gs1 = 1.f / (1.f + __expf(-(v1 + hc1)));
                    float gv0 = gs0 * v0 + (1.f - gs0) * hc0;
                    float gv1 = gs1 * v1 + (1.f - gs1) * hc1;
                    size_t b0 = (size_t)row * 128 + c;
                    *(uint32_t*)&g_x3b[b0]      = pack_bf2(gv0, gv1);
                    *(uint32_t*)&g_x3b[b0 + 64] = pack_bf2(v0, v1);
                }
    }
}

// ------------------------- GAT aggregation (warp per dst) --------------------
__device__ __forceinline__ float lrelu(float x) { return x > 0.f ? x : 0.2f * x; }

template <int CONCAT>
__launch_bounds__(256)
__global__ void k_agg(const float* __restrict__ bias) {
    int n = (blockIdx.x * 256 + threadIdx.x) >> 5;
    int lane = threadIdx.x & 31;
    int rs = g_rp[n], re = g_rp[n + 1];
    float ad0 = g_adst[n * 4 + 0], ad1 = g_adst[n * 4 + 1];
    float ad2 = g_adst[n * 4 + 2], ad3 = g_adst[n * 4 + 3];

    float m0 = -1e30f, m1 = -1e30f, m2 = -1e30f, m3 = -1e30f;
    for (int j = rs + lane; j < re; j += 32) {
        int s = g_col[j];
        m0 = fmaxf(m0, lrelu(g_asrc[s * 4 + 0] + ad0));
        m1 = fmaxf(m1, lrelu(g_asrc[s * 4 + 1] + ad1));
        m2 = fmaxf(m2, lrelu(g_asrc[s * 4 + 2] + ad2));
        m3 = fmaxf(m3, lrelu(g_asrc[s * 4 + 3] + ad3));
    }
#pragma unroll
    for (int o = 16; o; o >>= 1) {
        m0 = fmaxf(m0, __shfl_xor_sync(0xffffffffu, m0, o));
        m1 = fmaxf(m1, __shfl_xor_sync(0xffffffffu, m1, o));
        m2 = fmaxf(m2, __shfl_xor_sync(0xffffffffu, m2, o));
        m3 = fmaxf(m3, __shfl_xor_sync(0xffffffffu, m3, o));
    }
    float d0 = 0.f, d1 = 0.f, d2 = 0.f, d3 = 0.f;
    for (int j = rs + lane; j < re; j += 32) {
        int s = g_col[j];
        d0 += __expf(lrelu(g_asrc[s * 4 + 0] + ad0) - m0);
        d1 += __expf(lrelu(g_asrc[s * 4 + 1] + ad1) - m1);
        d2 += __expf(lrelu(g_asrc[s * 4 + 2] + ad2) - m2);
        d3 += __expf(lrelu(g_asrc[s * 4 + 3] + ad3) - m3);
    }
#pragma unroll
    for (int o = 16; o; o >>= 1) {
        d0 += __shfl_xor_sync(0xffffffffu, d0, o);
        d1 += __shfl_xor_sync(0xffffffffu, d1, o);
        d2 += __shfl_xor_sync(0xffffffffu, d2, o);
        d3 += __shfl_xor_sync(0xffffffffu, d3, o);
    }
    float i0 = 1.f / d0, i1 = 1.f / d1, i2 = 1.f / d2, i3 = 1.f / d3;

    // gather pass: lane owns channels (64h + 2*lane, +1) per head h
    float aLo[4] = {0, 0, 0, 0}, aHi[4] = {0, 0, 0, 0};
    for (int j = rs; j < re; j++) {
        int s = g_col[j];
        float wv[4];
        wv[0] = __expf(lrelu(g_asrc[s * 4 + 0] + ad0) - m0) * i0;
        wv[1] = __expf(lrelu(g_asrc[s * 4 + 1] + ad1) - m1) * i1;
        wv[2] = __expf(lrelu(g_asrc[s * 4 + 2] + ad2) - m2) * i2;
        wv[3] = __expf(lrelu(g_asrc[s * 4 + 3] + ad3) - m3) * i3;
        const uint32_t* hw = g_hfw + (size_t)s * 128;
#pragma unroll
        for (int h = 0; h < 4; h++) {
            uint32_t pk = hw[h * 32 + lane];
            float2 f = __bfloat1622float2(*reinterpret_cast<__nv_bfloat162*>(&pk));
            aLo[h] += wv[h] * f.x;
            aHi[h] += wv[h] * f.y;
        }
    }
    if (CONCAT) {
#pragma unroll
        for (int h = 0; h < 4; h++) {
            int c = h * 64 + 2 * lane;
            float2 bv = *(const float2*)&bias[c];
            float v0 = fmaxf(aLo[h] + bv.x, 0.f);
            float v1 = fmaxf(aHi[h] + bv.y, 0.f);
            *(uint32_t*)&g_xrb[(size_t)n * 256 + c] = pack_bf2(v0, v1);
        }
    } else {
        float2 bv = *(const float2*)&bias[2 * lane];
        float o0 = 0.25f * (aLo[0] + aLo[1] + aLo[2] + aLo[3]) + bv.x;
        float o1 = 0.25f * (aHi[0] + aHi[1] + aHi[2] + aHi[3]) + bv.y;
        ((float2*)g_xr2)[(size_t)n * 32 + lane] =
            make_float2(fmaxf(o0, 0.f), fmaxf(o1, 0.f));
    }
}

// ------------------------- scorer head + pooling -----------------------------
__global__ void k_zero() { g_gsum[blockIdx.x * 256 + threadIdx.x] = 0.f; }

__launch_bounds__(256)
__global__ void k_final(const float* __restrict__ Wfc, const float* __restrict__ bfc) {
    extern __shared__ float Ws[];
    __shared__ float s_hc3[64];
    __shared__ float part_sh[8][64];
    __shared__ float part_ss[8][64];
    int tid = threadIdx.x, lane = tid & 31, w = tid >> 5;
    int g = blockIdx.x >> 1;

    for (int i = tid; i < 4096; i += 256)
        ((float4*)Ws)[i] = ((const float4*)Wfc)[i];
    if (tid < 64) s_hc3[tid] = g_xr2[((size_t)g << 9) * 64 + tid];
    __syncthreads();

    float bL = bfc[lane], bH = bfc[lane + 32];
    float shL = 0.f, shH = 0.f, ssL = 0.f, ssH = 0.f;
    int nbase = blockIdx.x * 256 + w * 32;

    for (int g4 = 0; g4 < 8; g4++) {
        int n0 = nbase + g4 * 4;
        float xl[4], xh[4], aL[4], aH[4];
#pragma unroll
        for (int u = 0; u < 4; u++) {
            xl[u] = g_xr2[(size_t)(n0 + u) * 64 + lane];
            xh[u] = g_xr2[(size_t)(n0 + u) * 64 + lane + 32];
            aL[u] = bL; aH[u] = bH;
        }
#pragma unroll 4
        for (int j = 0; j < 64; j++) {
            float h3 = s_hc3[j];
            float w0 = Ws[j * 64 + lane];
            float w1 = Ws[(64 + j) * 64 + lane];
            float w2 = Ws[(128 + j) * 64 + lane];
            float w3 = Ws[(192 + j) * 64 + lane];
            float v0 = Ws[j * 64 + lane + 32];
            float v1 = Ws[(64 + j) * 64 + lane + 32];
            float v2 = Ws[(128 + j) * 64 + lane + 32];
            float v3 = Ws[(192 + j) * 64 + lane + 32];
#pragma unroll
            for (int u = 0; u < 4; u++) {
                float xj = (j < 32) ? __shfl_sync(0xffffffffu, xl[u], j)
                                    : __shfl_sync(0xffffffffu, xh[u], j - 32);
                float p = xj * h3;
                float q = fabsf(h3 - xj);
                aL[u] += h3 * w0 + xj * w1 + p * w2 + q * w3;
                aH[u] += h3 * v0 + xj * v1 + p * v2 + q * v3;
            }
        }
#pragma unroll
        for (int u = 0; u < 4; u++) {
            float tL = tanhf(aL[u]), tH = tanhf(aH[u]);
            float mx = fmaxf(tL, tH);
#pragma unroll
            for (int o = 16; o; o >>= 1) mx = fmaxf(mx, __shfl_xor_sync(0xffffffffu, mx, o));
            float eL = __expf(tL - mx), eH = __expf(tH - mx);
            float sm = eL + eH;
#pragma unroll
            for (int o = 16; o; o >>= 1) sm += __shfl_xor_sync(0xffffffffu, sm, o);
            float inv = 1.f / sm;
            shL += eL * inv * xl[u]; shH += eH * inv * xh[u];
            ssL += xl[u];            ssH += xh[u];
        }
    }
    part_sh[w][lane] = shL; part_sh[w][lane + 32] = shH;
    part_ss[w][lane] = ssL; part_ss[w][lane + 32] = ssH;
    __syncthreads();
    if (tid < 128) {
        int c = tid & 63;
        float s = 0.f;
        if (tid < 64) {
            for (int ww = 0; ww < 8; ww++) s += part_sh[ww][c];
            atomicAdd(&g_gsum[g * 128 + c], s);
        } else {
            for (int ww = 0; ww < 8; ww++) s += part_ss[ww][c];
            atomicAdd(&g_gsum[g * 128 + 64 + c], s);
        }
    }
}

__global__ void k_logits(const float* __restrict__ Wc, const float* __restrict__ bc,
                         float* __restrict__ out) {
    int b = threadIdx.x;
    float l[4] = {bc[0], bc[1], bc[2], bc[3]};
    const float inv = 1.f / 512.f;
    for (int j = 0; j < 128; j++) {
        float v = g_gsum[b * 128 + j] * inv;
#pragma unroll
        for (int c = 0; c < 4; c++) l[c] += v * Wc[j * 4 + c];
    }
    float mx = fmaxf(fmaxf(l[0], l[1]), fmaxf(l[2], l[3]));
    float s = expf(l[0] - mx) + expf(l[1] - mx) + expf(l[2] - mx) + expf(l[3] - mx);
    float lse = mx + logf(s);
#pragma unroll
    for (int c = 0; c < 4; c++) out[b * 4 + c] = l[c] - lse;
}

// ------------------------- launch --------------------------------------------
extern "C" void kernel_launch(void* const* d_in, const int* in_sizes, int n_in,
                              void* d_out, int out_size) {
    const float* x        = (const float*)d_in[0];
    const float* root     = (const float*)d_in[1];
    const int*   ei       = (const int*)d_in[2];
    const float* W_post1  = (const float*)d_in[5];
    const float* W_claim1 = (const float*)d_in[6];
    const float* W1       = (const float*)d_in[7];
    const float* att_src1 = (const float*)d_in[8];
    const float* att_dst1 = (const float*)d_in[9];
    const float* b1       = (const float*)d_in[10];
    const float* W_post2  = (const float*)d_in[11];
    const float* W_claim2 = (const float*)d_in[12];
    const float* W2       = (const float*)d_in[13];
    const float* att_src2 = (const float*)d_in[14];
    const float* att_dst2 = (const float*)d_in[15];
    const float* b2       = (const float*)d_in[16];
    const float* W_fc     = (const float*)d_in[17];
    const float* b_fc     = (const float*)d_in[18];
    const float* W_clf    = (const float*)d_in[19];
    const float* b_clf    = (const float*)d_in[20];
    float* out = (float*)d_out;

    const int SMMC = (128 * LDS + 64 * LDS) * 2 * 2;   // 55296
    cudaFuncSetAttribute(k_final,  cudaFuncAttributeMaxDynamicSharedMemorySize, 65536);
    cudaFuncSetAttribute(k_mm0,    cudaFuncAttributeMaxDynamicSharedMemorySize, SMM0_TOT);
    cudaFuncSetAttribute(k_mmc<1>, cudaFuncAttributeMaxDynamicSharedMemorySize, SMMC);
    cudaFuncSetAttribute(k_mmc<2>, cudaFuncAttributeMaxDynamicSharedMemorySize, SMMC);
    cudaFuncSetAttribute(k_mmc<3>, cudaFuncAttributeMaxDynamicSharedMemorySize, SMMC);

    k_rootproj<<<NB, 64>>>(root, W_claim1, W_claim2);                   // 0
    k_convW<<<WTOT / 256, 256>>>(W_post1, W1, W_post2, W2);             // 1 (+zero scores)
    k_mm0<<<dim3(1, NN / 128), 256, SMM0_TOT>>>(x);                     // 2  PLA1
    k_mmc<1><<<dim3(4, NN / 128), 256, SMMC>>>(att_src1, att_dst1);     // 3  GAT1 lin+scores
    k_deg_init<<<NN / 256, 256>>>();                                    // 4
    k_deg<<<E2 / 256, 256>>>(ei);                                       // 5
    k_scan_all<<<1, 1024>>>();                                          // 6
    k_scatter<<<ETOT / 256, 256>>>(ei);                                 // 7

    k_agg<1><<<NN * 32 / 256, 256>>>(b1);
    k_mmc<2><<<dim3(1, NN * 4 / 128), 256, SMMC>>>(nullptr, nullptr);   // PLA2
    k_zs<<<NN * 8 / 256, 256>>>();                                      // zero layer-2 scores
    k_mmc<3><<<dim3(4, NN / 128), 256, SMMC>>>(att_src2, att_dst2);     // GAT2 lin+scores
    k_agg<0><<<NN * 32 / 256, 256>>>(b2);

    k_zero<<<NB * 128 / 256, 256>>>();
    k_final<<<NN / 256, 256, 65536>>>(W_fc, b_fc);
    k_logits<<<1, 128>>>(W_clf, b_clf, out);
}

// round 15
// speedup vs baseline: 1.7334x; 1.0730x over previous
#include <cuda_runtime.h>
#include <cuda_bf16.h>
#include <cstdint>

#define NN 65536      // nodes
#define NB 128        // graphs
#define NE 65536      // raw directed edges
#define E2 131072     // TD + BU
#define ETOT 196608   // + self loops
#define DIN 512
#define WTOT 200704   // total weight elements (all 4 matrices)

// ------------------------- scratch (device globals; no allocs) ---------------
__device__ uint32_t g_hfw[NN * 128];  // GAT lin output, packed bf16x2 (2ch/word)
__device__ float g_xr2[NN * 64];      // relu(GAT2 out)
__device__ float g_asrc[NN * 4];
__device__ float g_adst[NN * 4];
__device__ float g_hc1[NB * 64];
__device__ float g_hc2[NB * 64];
__device__ float g_gsum[NB * 128];
__device__ int   g_deg[NN];
__device__ int   g_rp [NN + 1];
__device__ int   g_cursor[NN];
__device__ int   g_col[ETOT];
// bf16 operand planes (converted exactly once)
__device__ __nv_bfloat16 g_h1b[NN * 128];   // PLA1 out (MODE1 A)
__device__ __nv_bfloat16 g_xrb[NN * 256];   // relu(GAT1) (MODE2 A)
__device__ __nv_bfloat16 g_x3b[NN * 512];   // PLA2 out (MODE3 A)
__device__ __nv_bfloat16 g_wtb[WTOT];       // transposed weights

// ------------------------- helpers -------------------------------------------
__device__ __forceinline__ uint32_t smem_u32(const void* p) {
    uint32_t a;
    asm("{ .reg .u64 t; cvta.to.shared.u64 t, %1; cvt.u32.u64 %0, t; }" : "=r"(a) : "l"(p));
    return a;
}
__device__ __forceinline__ void ldmat4(uint32_t& r0, uint32_t& r1, uint32_t& r2,
                                       uint32_t& r3, uint32_t addr) {
    asm volatile("ldmatrix.sync.aligned.m8n8.x4.shared.b16 {%0,%1,%2,%3}, [%4];"
        : "=r"(r0), "=r"(r1), "=r"(r2), "=r"(r3) : "r"(addr));
}
__device__ __forceinline__ void mma_bf16(float* c, const uint32_t* a, const uint32_t* b) {
    asm volatile("mma.sync.aligned.m16n8k16.row.col.f32.bf16.bf16.f32 "
        "{%0,%1,%2,%3}, {%4,%5,%6,%7}, {%8,%9}, {%0,%1,%2,%3};"
        : "+f"(c[0]), "+f"(c[1]), "+f"(c[2]), "+f"(c[3])
        : "r"(a[0]), "r"(a[1]), "r"(a[2]), "r"(a[3]), "r"(b[0]), "r"(b[1]));
}
__device__ __forceinline__ uint32_t pack_bf2(float a, float b) {
    __nv_bfloat162 t = __floats2bfloat162_rn(a, b);
    return *reinterpret_cast<uint32_t*>(&t);
}
#define CP16(dst, src) \
    asm volatile("cp.async.cg.shared.global [%0], [%1], 16;" :: "r"(dst), "l"(src))
#define CPCOMMIT() asm volatile("cp.async.commit_group;" ::: "memory")
#define CPWAIT0()  asm volatile("cp.async.wait_group 0;" ::: "memory")
#define CPWAIT1()  asm volatile("cp.async.wait_group 1;" ::: "memory")

// ------------------------- weight pre-conversion + score zeroing --------------
__global__ void k_convW(const float* __restrict__ Wa, const float* __restrict__ Wb,
                        const float* __restrict__ Wc, const float* __restrict__ Wd) {
    int idx = blockIdx.x * 256 + threadIdx.x;
    const float* W; int K, N, local;
    if (idx < 32768)      { W = Wa; K = 512; N = 64;  local = idx; }
    else if (idx < 65536) { W = Wb; K = 128; N = 256; local = idx - 32768; }
    else if (idx < 69632) { W = Wc; K = 64;  N = 64;  local = idx - 65536; }
    else                  { W = Wd; K = 512; N = 256; local = idx - 69632; }
    int n = local / K, k = local - n * K;
    g_wtb[idx] = __float2bfloat16(W[(size_t)k * N + n]);
    for (int z = idx; z < NN * 4; z += WTOT) { g_asrc[z] = 0.f; g_adst[z] = 0.f; }
}

__global__ void k_zs() {
    int i = blockIdx.x * 256 + threadIdx.x;
    if (i < NN * 4) g_asrc[i] = 0.f;
    else            g_adst[i - NN * 4] = 0.f;
}

// ------------------------- CSR build -----------------------------------------
__global__ void k_deg_init() { g_deg[blockIdx.x * 256 + threadIdx.x] = 1; }

__global__ void k_deg(const int* __restrict__ ei) {
    int i = blockIdx.x * 256 + threadIdx.x;
    int d = (i < NE) ? ei[NE + i] : ei[i - NE];
    atomicAdd(&g_deg[d], 1);
}

__global__ void k_scan_all() {
    __shared__ int wsum[32];
    int tid = threadIdx.x, lane = tid & 31, wid = tid >> 5;
    int base = tid * 64;
    int s = 0;
    for (int i = 0; i < 64; i++) s += g_deg[base + i];
    int x = s;
#pragma unroll
    for (int o = 1; o < 32; o <<= 1) {
        int y = __shfl_up_sync(0xffffffffu, x, o);
        if (lane >= o) x += y;
    }
    if (lane == 31) wsum[wid] = x;
    __syncthreads();
    if (wid == 0) {
        int t = wsum[lane];
#pragma unroll
        for (int o = 1; o < 32; o <<= 1) {
            int y = __shfl_up_sync(0xffffffffu, t, o);
            if (lane >= o) t += y;
        }
        wsum[lane] = t;
    }
    __syncthreads();
    int run = (wid ? wsum[wid - 1] : 0) + x - s;
    for (int i = 0; i < 64; i++) {
        int v = g_deg[base + i];
        g_rp[base + i] = run;
        g_cursor[base + i] = run;
        run += v;
    }
    if (tid == 0) g_rp[NN] = ETOT;
}

__global__ void k_scatter(const int* __restrict__ ei) {
    int i = blockIdx.x * 256 + threadIdx.x;
    int s, d;
    if (i < NE)        { s = ei[i];          d = ei[NE + i]; }
    else if (i < E2)   { int e = i - NE; s = ei[NE + e]; d = ei[e]; }
    else               { s = d = i - E2; }
    int pos = atomicAdd(&g_cursor[d], 1);
    g_col[pos] = s;
}

// ------------------------- root projections (4-way split-K) -------------------
__global__ void k_rootproj(const float* __restrict__ root,
                           const float* __restrict__ Wc1,
                           const float* __restrict__ Wc2) {
    __shared__ float p1[256], p2[256];
    int b = blockIdx.x, t = threadIdx.x;
    int c = t & 63, kq = t >> 6;          // 4 k-quarters
    float a1 = 0.f, a2 = 0.f;
    for (int k = kq * 128; k < kq * 128 + 128; k++) {
        float rv = root[b * DIN + k];
        a1 += rv * Wc1[k * 64 + c];
        a2 += rv * Wc2[k * 64 + c];
    }
    p1[t] = a1; p2[t] = a2;
    __syncthreads();
    if (t < 64) {
        g_hc1[b * 64 + t] = p1[t] + p1[t + 64] + p1[t + 128] + p1[t + 192];
        g_hc2[b * 64 + t] = p2[t] + p2[t + 64] + p2[t + 128] + p2[t + 192];
    }
}

#define LDS 72            // padded smem row stride for k_mmc (bf16): 144B

// ------------------------- MODE0: x @ W_post1, cp.async fp32 staging ----------
#define XSTRIDE 36
#define PLDS 56
#define XS_BYTES 18432
#define OFF_AB 36864
#define OFF_B  51200
#define B_BYTES 7168
#define SMM0_TOT 65536

__launch_bounds__(256, 2)
__global__ void k_mm0(const float* __restrict__ Aarg) {
    extern __shared__ __align__(16) char sm[];
    int tid = threadIdx.x, lane = tid & 31, w = tid >> 5;
    int wm = (w & 1) * 64, wn = (w >> 1) * 16;
    const float* Arow = Aarg + (size_t)blockIdx.y * 128 * 512;
    __nv_bfloat16* Ab = (__nv_bfloat16*)(sm + OFF_AB);

    float acc[4][2][4];
#pragma unroll
    for (int a = 0; a < 4; a++)
#pragma unroll
        for (int b = 0; b < 2; b++)
#pragma unroll
            for (int c = 0; c < 4; c++) acc[a][b][c] = 0.f;

    auto stage = [&](int it, int buf) {
        int k0 = it * 32;
        float* Xs = (float*)(sm + buf * XS_BYTES);
        __nv_bfloat16* Bb = (__nv_bfloat16*)(sm + OFF_B + buf * B_BYTES);
#pragma unroll
        for (int i = 0; i < 4; i++) {
            int idx = i * 256 + tid;
            int r = idx >> 3, c4 = (idx & 7) << 2;
            CP16(smem_u32(&Xs[r * XSTRIDE + c4]), &Arow[(size_t)r * 512 + k0 + c4]);
        }
        {
            int n = tid >> 2, c8 = (tid & 3) << 3;
            CP16(smem_u32(&Bb[n * PLDS + c8]), &g_wtb[(size_t)n * 512 + k0 + c8]);
        }
        CPCOMMIT();
    };

    stage(0, 0);
    for (int it = 0; it < 16; it++) {
        int buf = it & 1;
        if (it + 1 < 16) { stage(it + 1, buf ^ 1); CPWAIT1(); }
        else             { CPWAIT0(); }
        __syncthreads();
        float* Xs = (float*)(sm + buf * XS_BYTES);
#pragma unroll
        for (int i = 0; i < 4; i++) {
            int idx = i * 256 + tid;
            int r = idx >> 3, c4 = (idx & 7) << 2;
            float4 v = *(const float4*)&Xs[r * XSTRIDE + c4];
            *(uint2*)&Ab[r * PLDS + c4] = make_uint2(pack_bf2(v.x, v.y), pack_bf2(v.z, v.w));
        }
        __syncthreads();
        __nv_bfloat16* Bb = (__nv_bfloat16*)(sm + OFF_B + buf * B_BYTES);
#pragma unroll
        for (int ks = 0; ks < 2; ks++) {
            int kb = ks * 16;
            uint32_t ah[4][4], bh[2][2];
            int arow = wm + (lane & 15);
            int acol = kb + (lane >> 4) * 8;
#pragma unroll
            for (int mf = 0; mf < 4; mf++)
                ldmat4(ah[mf][0], ah[mf][1], ah[mf][2], ah[mf][3],
                       smem_u32(&Ab[(arow + mf * 16) * PLDS + acol]));
            {
                int rr = lane & 7, g = lane >> 3;
                ldmat4(bh[0][0], bh[0][1], bh[1][0], bh[1][1],
                       smem_u32(&Bb[(wn + (g >> 1) * 8 + rr) * PLDS + kb + (g & 1) * 8]));
            }
#pragma unroll
            for (int mf = 0; mf < 4; mf++)
#pragma unroll
                for (int nf = 0; nf < 2; nf++)
                    mma_bf16(acc[mf][nf], ah[mf], bh[nf]);
        }
        __syncthreads();
    }

#pragma unroll
    for (int mf = 0; mf < 4; mf++)
#pragma unroll
        for (int nf = 0; nf < 2; nf++)
#pragma unroll
            for (int p = 0; p < 2; p++) {
                int row = blockIdx.y * 128 + wm + mf * 16 + (lane >> 2) + p * 8;
                int c   = wn + nf * 8 + (lane & 3) * 2;
                float v0 = acc[mf][nf][p * 2 + 0];
                float v1 = acc[mf][nf][p * 2 + 1];
                int gid = row >> 9;
                float hc0 = g_hc1[gid * 64 + c];
                float hc1 = g_hc1[gid * 64 + c + 1];
                float gs0 = 1.f / (1.f + __expf(-(v0 + hc0)));
                float gs1 = 1.f / (1.f + __expf(-(v1 + hc1)));
                float gv0 = gs0 * v0 + (1.f - gs0) * hc0;
                float gv1 = gs1 * v1 + (1.f - gs1) * hc1;
                size_t b0 = (size_t)row * 128 + c;
                *(uint32_t*)&g_h1b[b0]      = pack_bf2(gv0, gv1);
                *(uint32_t*)&g_h1b[b0 + 64] = pack_bf2(v0, v1);
            }
}

// ------------------- MODE 1/2/3: pure-copy, cp.async double-buffered ----------
template <int MODE>
__launch_bounds__(256, 3)
__global__ void k_mmc(const float* __restrict__ as_, const float* __restrict__ ad_) {
    constexpr int K    = (MODE == 3) ? 512 : (MODE == 1 ? 128 : 64);
    constexpr int KT   = K / 64;
    constexpr int WOFF = (MODE == 1) ? 32768 : (MODE == 2) ? 65536 : 69632;
    constexpr int ASZ  = 128 * LDS;
    constexpr int BSZ  = 64 * LDS;
    constexpr int STG  = ASZ + BSZ;

    extern __shared__ __align__(16) char sm[];
    __nv_bfloat16* base = (__nv_bfloat16*)sm;

    int tid = threadIdx.x, lane = tid & 31, w = tid >> 5;
    int wm = (w & 1) * 64, wn = (w >> 1) * 16;
    int n0 = blockIdx.x * 64;

    const __nv_bfloat16* Apb = ((MODE == 1) ? g_h1b : (MODE == 2) ? g_xrb : g_x3b)
                             + (size_t)blockIdx.y * 128 * K;

    float acc[4][2][4];
#pragma unroll
    for (int a = 0; a < 4; a++)
#pragma unroll
        for (int b = 0; b < 2; b++)
#pragma unroll
            for (int c = 0; c < 4; c++) acc[a][b][c] = 0.f;

    auto stage = [&](int k0, int buf) {
        __nv_bfloat16* Ab = base + buf * STG;
        __nv_bfloat16* Bb = Ab + ASZ;
#pragma unroll
        for (int i = 0; i < 4; i++) {
            int idx = i * 256 + tid;
            int r = idx >> 3, c8 = (idx & 7) << 3;
            CP16(smem_u32(&Ab[r * LDS + c8]), &Apb[(size_t)r * K + k0 + c8]);
        }
        {
            int idx0 = tid, idx1 = tid + 256;
            int n_0 = idx0 >> 3, c_0 = (idx0 & 7) << 3;
            int n_1 = idx1 >> 3, c_1 = (idx1 & 7) << 3;
            CP16(smem_u32(&Bb[n_0 * LDS + c_0]),
                 &g_wtb[(size_t)WOFF + (size_t)(n0 + n_0) * K + k0 + c_0]);
            CP16(smem_u32(&Bb[n_1 * LDS + c_1]),
                 &g_wtb[(size_t)WOFF + (size_t)(n0 + n_1) * K + k0 + c_1]);
        }
        CPCOMMIT();
    };

    stage(0, 0);
    int buf = 0;
    for (int it = 0; it < KT; it++) {
        if (it + 1 < KT) { stage((it + 1) * 64, buf ^ 1); CPWAIT1(); }
        else             { CPWAIT0(); }
        __syncthreads();
        __nv_bfloat16* Ab = base + buf * STG;
        __nv_bfloat16* Bb = Ab + ASZ;
#pragma unroll
        for (int ks = 0; ks < 4; ks++) {
            int kb = ks * 16;
            uint32_t ah[4][4], bh[2][2];
            int arow = wm + (lane & 15);
            int acol = kb + (lane >> 4) * 8;
#pragma unroll
            for (int mf = 0; mf < 4; mf++)
                ldmat4(ah[mf][0], ah[mf][1], ah[mf][2], ah[mf][3],
                       smem_u32(&Ab[(arow + mf * 16) * LDS + acol]));
            {
                int rr = lane & 7, g = lane >> 3;
                ldmat4(bh[0][0], bh[0][1], bh[1][0], bh[1][1],
                       smem_u32(&Bb[(wn + (g >> 1) * 8 + rr) * LDS + kb + (g & 1) * 8]));
            }
#pragma unroll
            for (int mf = 0; mf < 4; mf++)
#pragma unroll
                for (int nf = 0; nf < 2; nf++)
                    mma_bf16(acc[mf][nf], ah[mf], bh[nf]);
        }
        __syncthreads();
        buf ^= 1;
    }

    if (MODE == 1 || MODE == 3) {
#pragma unroll
        for (int mf = 0; mf < 4; mf++)
#pragma unroll
            for (int p = 0; p < 2; p++) {
                int row = blockIdx.y * 128 + wm + mf * 16 + (lane >> 2) + p * 8;
                float ps = 0.f, pd = 0.f;
#pragma unroll
                for (int nf = 0; nf < 2; nf++) {
                    int c = wn + nf * 8 + (lane & 3) * 2;
                    float v0 = acc[mf][nf][p * 2 + 0];
                    float v1 = acc[mf][nf][p * 2 + 1];
                    g_hfw[(size_t)row * 128 + ((n0 + c) >> 1)] = pack_bf2(v0, v1);
                    ps += v0 * as_[n0 + c] + v1 * as_[n0 + c + 1];
                    pd += v0 * ad_[n0 + c] + v1 * ad_[n0 + c + 1];
                }
                ps += __shfl_xor_sync(0xffffffffu, ps, 1);
                ps += __shfl_xor_sync(0xffffffffu, ps, 2);
                pd += __shfl_xor_sync(0xffffffffu, pd, 1);
                pd += __shfl_xor_sync(0xffffffffu, pd, 2);
                if ((lane & 3) == 0) {
                    int h = n0 >> 6;
                    atomicAdd(&g_asrc[row * 4 + h], ps);
                    atomicAdd(&g_adst[row * 4 + h], pd);
                }
            }
    } else {
#pragma unroll
        for (int mf = 0; mf < 4; mf++)
#pragma unroll
            for (int nf = 0; nf < 2; nf++)
#pragma unroll
                for (int p = 0; p < 2; p++) {
                    int row = blockIdx.y * 128 + wm + mf * 16 + (lane >> 2) + p * 8;
                    int c   = wn + nf * 8 + (lane & 3) * 2;
                    float v0 = acc[mf][nf][p * 2 + 0];
                    float v1 = acc[mf][nf][p * 2 + 1];
                    int gid = row >> 11;
                    float hc0 = g_hc2[gid * 64 + c];
                    float hc1 = g_hc2[gid * 64 + c + 1];
                    float gs0 = 1.f / (1.f + __expf(-(v0 + hc0)));
                    float gs1 = 1.f / (1.f + __expf(-(v1 + hc1)));
                    float gv0 = gs0 * v0 + (1.f - gs0) * hc0;
                    float gv1 = gs1 * v1 + (1.f - gs1) * hc1;
                    size_t b0 = (size_t)row * 128 + c;
                    *(uint32_t*)&g_x3b[b0]      = pack_bf2(gv0, gv1);
                    *(uint32_t*)&g_x3b[b0 + 64] = pack_bf2(v0, v1);
                }
    }
}

// ------------------------- GAT aggregation (warp per dst) --------------------
__device__ __forceinline__ float lrelu(float x) { return x > 0.f ? x : 0.2f * x; }

template <int CONCAT>
__launch_bounds__(256)
__global__ void k_agg(const float* __restrict__ bias) {
    int n = (blockIdx.x * 256 + threadIdx.x) >> 5;
    int lane = threadIdx.x & 31;
    int rs = g_rp[n], re = g_rp[n + 1];
    int deg = re - rs;
    float ad0 = g_adst[n * 4 + 0], ad1 = g_adst[n * 4 + 1];
    float ad2 = g_adst[n * 4 + 2], ad3 = g_adst[n * 4 + 3];

    float aLo[4] = {0, 0, 0, 0}, aHi[4] = {0, 0, 0, 0};

    if (deg <= 32) {
        // ---- fast path: lane j caches edge j; single score pass ----
        int sj = -1;
        float e0 = -1e30f, e1 = -1e30f, e2 = -1e30f, e3 = -1e30f;
        if (lane < deg) {
            sj = g_col[rs + lane];
            e0 = lrelu(g_asrc[sj * 4 + 0] + ad0);
            e1 = lrelu(g_asrc[sj * 4 + 1] + ad1);
            e2 = lrelu(g_asrc[sj * 4 + 2] + ad2);
            e3 = lrelu(g_asrc[sj * 4 + 3] + ad3);
        }
        float m0 = e0, m1 = e1, m2 = e2, m3 = e3;
#pragma unroll
        for (int o = 16; o; o >>= 1) {
            m0 = fmaxf(m0, __shfl_xor_sync(0xffffffffu, m0, o));
            m1 = fmaxf(m1, __shfl_xor_sync(0xffffffffu, m1, o));
            m2 = fmaxf(m2, __shfl_xor_sync(0xffffffffu, m2, o));
            m3 = fmaxf(m3, __shfl_xor_sync(0xffffffffu, m3, o));
        }
        float x0 = (lane < deg) ? __expf(e0 - m0) : 0.f;
        float x1 = (lane < deg) ? __expf(e1 - m1) : 0.f;
        float x2 = (lane < deg) ? __expf(e2 - m2) : 0.f;
        float x3 = (lane < deg) ? __expf(e3 - m3) : 0.f;
        float d0 = x0, d1 = x1, d2 = x2, d3 = x3;
#pragma unroll
        for (int o = 16; o; o >>= 1) {
            d0 += __shfl_xor_sync(0xffffffffu, d0, o);
            d1 += __shfl_xor_sync(0xffffffffu, d1, o);
            d2 += __shfl_xor_sync(0xffffffffu, d2, o);
            d3 += __shfl_xor_sync(0xffffffffu, d3, o);
        }
        float w0 = x0 / d0, w1 = x1 / d1, w2 = x2 / d2, w3 = x3 / d3;

        for (int j = 0; j < deg; j++) {
            int s = __shfl_sync(0xffffffffu, sj, j);
            float wv0 = __shfl_sync(0xffffffffu, w0, j);
            float wv1 = __shfl_sync(0xffffffffu, w1, j);
            float wv2 = __shfl_sync(0xffffffffu, w2, j);
            float wv3 = __shfl_sync(0xffffffffu, w3, j);
            const uint32_t* hw = g_hfw + (size_t)s * 128;
            uint32_t p0 = hw[lane],      p1 = hw[32 + lane];
            uint32_t p2 = hw[64 + lane], p3 = hw[96 + lane];
            float2 f0 = __bfloat1622float2(*reinterpret_cast<__nv_bfloat162*>(&p0));
            float2 f1 = __bfloat1622float2(*reinterpret_cast<__nv_bfloat162*>(&p1));
            float2 f2 = __bfloat1622float2(*reinterpret_cast<__nv_bfloat162*>(&p2));
            float2 f3 = __bfloat1622float2(*reinterpret_cast<__nv_bfloat162*>(&p3));
            aLo[0] += wv0 * f0.x; aHi[0] += wv0 * f0.y;
            aLo[1] += wv1 * f1.x; aHi[1] += wv1 * f1.y;
            aLo[2] += wv2 * f2.x; aHi[2] += wv2 * f2.y;
            aLo[3] += wv3 * f3.x; aHi[3] += wv3 * f3.y;
        }
    } else {
        // ---- fallback: generic 3-pass (rare) ----
        float m0 = -1e30f, m1 = -1e30f, m2 = -1e30f, m3 = -1e30f;
        for (int j = rs + lane; j < re; j += 32) {
            int s = g_col[j];
            m0 = fmaxf(m0, lrelu(g_asrc[s * 4 + 0] + ad0));
            m1 = fmaxf(m1, lrelu(g_asrc[s * 4 + 1] + ad1));
            m2 = fmaxf(m2, lrelu(g_asrc[s * 4 + 2] + ad2));
            m3 = fmaxf(m3, lrelu(g_asrc[s * 4 + 3] + ad3));
        }
#pragma unroll
        for (int o = 16; o; o >>= 1) {
            m0 = fmaxf(m0, __shfl_xor_sync(0xffffffffu, m0, o));
            m1 = fmaxf(m1, __shfl_xor_sync(0xffffffffu, m1, o));
            m2 = fmaxf(m2, __shfl_xor_sync(0xffffffffu, m2, o));
            m3 = fmaxf(m3, __shfl_xor_sync(0xffffffffu, m3, o));
        }
        float d0 = 0.f, d1 = 0.f, d2 = 0.f, d3 = 0.f;
        for (int j = rs + lane; j < re; j += 32) {
            int s = g_col[j];
            d0 += __expf(lrelu(g_asrc[s * 4 + 0] + ad0) - m0);
            d1 += __expf(lrelu(g_asrc[s * 4 + 1] + ad1) - m1);
            d2 += __expf(lrelu(g_asrc[s * 4 + 2] + ad2) - m2);
            d3 += __expf(lrelu(g_asrc[s * 4 + 3] + ad3) - m3);
        }
#pragma unroll
        for (int o = 16; o; o >>= 1) {
            d0 += __shfl_xor_sync(0xffffffffu, d0, o);
            d1 += __shfl_xor_sync(0xffffffffu, d1, o);
            d2 += __shfl_xor_sync(0xffffffffu, d2, o);
            d3 += __shfl_xor_sync(0xffffffffu, d3, o);
        }
        float i0 = 1.f / d0, i1 = 1.f / d1, i2 = 1.f / d2, i3 = 1.f / d3;
        for (int j = rs; j < re; j++) {
            int s = g_col[j];
            float wv0 = __expf(lrelu(g_asrc[s * 4 + 0] + ad0) - m0) * i0;
            float wv1 = __expf(lrelu(g_asrc[s * 4 + 1] + ad1) - m1) * i1;
            float wv2 = __expf(lrelu(g_asrc[s * 4 + 2] + ad2) - m2) * i2;
            float wv3 = __expf(lrelu(g_asrc[s * 4 + 3] + ad3) - m3) * i3;
            const uint32_t* hw = g_hfw + (size_t)s * 128;
            uint32_t p0 = hw[lane],      p1 = hw[32 + lane];
            uint32_t p2 = hw[64 + lane], p3 = hw[96 + lane];
            float2 f0 = __bfloat1622float2(*reinterpret_cast<__nv_bfloat162*>(&p0));
            float2 f1 = __bfloat1622float2(*reinterpret_cast<__nv_bfloat162*>(&p1));
            float2 f2 = __bfloat1622float2(*reinterpret_cast<__nv_bfloat162*>(&p2));
            float2 f3 = __bfloat1622float2(*reinterpret_cast<__nv_bfloat162*>(&p3));
            aLo[0] += wv0 * f0.x; aHi[0] += wv0 * f0.y;
            aLo[1] += wv1 * f1.x; aHi[1] += wv1 * f1.y;
            aLo[2] += wv2 * f2.x; aHi[2] += wv2 * f2.y;
            aLo[3] += wv3 * f3.x; aHi[3] += wv3 * f3.y;
        }
    }

    if (CONCAT) {
#pragma unroll
        for (int h = 0; h < 4; h++) {
            int c = h * 64 + 2 * lane;
            float2 bv = *(const float2*)&bias[c];
            float v0 = fmaxf(aLo[h] + bv.x, 0.f);
            float v1 = fmaxf(aHi[h] + bv.y, 0.f);
            *(uint32_t*)&g_xrb[(size_t)n * 256 + c] = pack_bf2(v0, v1);
        }
    } else {
        float2 bv = *(const float2*)&bias[2 * lane];
        float o0 = 0.25f * (aLo[0] + aLo[1] + aLo[2] + aLo[3]) + bv.x;
        float o1 = 0.25f * (aHi[0] + aHi[1] + aHi[2] + aHi[3]) + bv.y;
        ((float2*)g_xr2)[(size_t)n * 32 + lane] =
            make_float2(fmaxf(o0, 0.f), fmaxf(o1, 0.f));
    }
}

// ------------------------- scorer head + pooling -----------------------------
__global__ void k_zero() { g_gsum[blockIdx.x * 256 + threadIdx.x] = 0.f; }

__launch_bounds__(256)
__global__ void k_final(const float* __restrict__ Wfc, const float* __restrict__ bfc) {
    extern __shared__ float Ws[];
    __shared__ float s_hc3[64];
    __shared__ float part_sh[8][64];
    __shared__ float part_ss[8][64];
    int tid = threadIdx.x, lane = tid & 31, w = tid >> 5;
    int g = blockIdx.x >> 1;

    for (int i = tid; i < 4096; i += 256)
        ((float4*)Ws)[i] = ((const float4*)Wfc)[i];
    if (tid < 64) s_hc3[tid] = g_xr2[((size_t)g << 9) * 64 + tid];
    __syncthreads();

    float bL = bfc[lane], bH = bfc[lane + 32];
    float shL = 0.f, shH = 0.f, ssL = 0.f, ssH = 0.f;
    int nbase = blockIdx.x * 256 + w * 32;

    for (int g4 = 0; g4 < 8; g4++) {
        int n0 = nbase + g4 * 4;
        float xl[4], xh[4], aL[4], aH[4];
#pragma unroll
        for (int u = 0; u < 4; u++) {
            xl[u] = g_xr2[(size_t)(n0 + u) * 64 + lane];
            xh[u] = g_xr2[(size_t)(n0 + u) * 64 + lane + 32];
            aL[u] = bL; aH[u] = bH;
        }
#pragma unroll 4
        for (int j = 0; j < 64; j++) {
            float h3 = s_hc3[j];
            float w0 = Ws[j * 64 + lane];
            float w1 = Ws[(64 + j) * 64 + lane];
            float w2 = Ws[(128 + j) * 64 + lane];
            float w3 = Ws[(192 + j) * 64 + lane];
            float v0 = Ws[j * 64 + lane + 32];
            float v1 = Ws[(64 + j) * 64 + lane + 32];
            float v2 = Ws[(128 + j) * 64 + lane + 32];
            float v3 = Ws[(192 + j) * 64 + lane + 32];
#pragma unroll
            for (int u = 0; u < 4; u++) {
                float xj = (j < 32) ? __shfl_sync(0xffffffffu, xl[u], j)
                                    : __shfl_sync(0xffffffffu, xh[u], j - 32);
                float p = xj * h3;
                float q = fabsf(h3 - xj);
                aL[u] += h3 * w0 + xj * w1 + p * w2 + q * w3;
                aH[u] += h3 * v0 + xj * v1 + p * v2 + q * v3;
            }
        }
#pragma unroll
        for (int u = 0; u < 4; u++) {
            float tL = tanhf(aL[u]), tH = tanhf(aH[u]);
            float mx = fmaxf(tL, tH);
#pragma unroll
            for (int o = 16; o; o >>= 1) mx = fmaxf(mx, __shfl_xor_sync(0xffffffffu, mx, o));
            float eL = __expf(tL - mx), eH = __expf(tH - mx);
            float sm = eL + eH;
#pragma unroll
            for (int o = 16; o; o >>= 1) sm += __shfl_xor_sync(0xffffffffu, sm, o);
            float inv = 1.f / sm;
            shL += eL * inv * xl[u]; shH += eH * inv * xh[u];
            ssL += xl[u];            ssH += xh[u];
        }
    }
    part_sh[w][lane] = shL; part_sh[w][lane + 32] = shH;
    part_ss[w][lane] = ssL; part_ss[w][lane + 32] = ssH;
    __syncthreads();
    if (tid < 128) {
        int c = tid & 63;
        float s = 0.f;
        if (tid < 64) {
            for (int ww = 0; ww < 8; ww++) s += part_sh[ww][c];
            atomicAdd(&g_gsum[g * 128 + c], s);
        } else {
            for (int ww = 0; ww < 8; ww++) s += part_ss[ww][c];
            atomicAdd(&g_gsum[g * 128 + 64 + c], s);
        }
    }
}

__global__ void k_logits(const float* __restrict__ Wc, const float* __restrict__ bc,
                         float* __restrict__ out) {
    int b = threadIdx.x;
    float l[4] = {bc[0], bc[1], bc[2], bc[3]};
    const float inv = 1.f / 512.f;
    for (int j = 0; j < 128; j++) {
        float v = g_gsum[b * 128 + j] * inv;
#pragma unroll
        for (int c = 0; c < 4; c++) l[c] += v * Wc[j * 4 + c];
    }
    float mx = fmaxf(fmaxf(l[0], l[1]), fmaxf(l[2], l[3]));
    float s = expf(l[0] - mx) + expf(l[1] - mx) + expf(l[2] - mx) + expf(l[3] - mx);
    float lse = mx + logf(s);
#pragma unroll
    for (int c = 0; c < 4; c++) out[b * 4 + c] = l[c] - lse;
}

// ------------------------- launch --------------------------------------------
extern "C" void kernel_launch(void* const* d_in, const int* in_sizes, int n_in,
                              void* d_out, int out_size) {
    const float* x        = (const float*)d_in[0];
    const float* root     = (const float*)d_in[1];
    const int*   ei       = (const int*)d_in[2];
    const float* W_post1  = (const float*)d_in[5];
    const float* W_claim1 = (const float*)d_in[6];
    const float* W1       = (const float*)d_in[7];
    const float* att_src1 = (const float*)d_in[8];
    const float* att_dst1 = (const float*)d_in[9];
    const float* b1       = (const float*)d_in[10];
    const float* W_post2  = (const float*)d_in[11];
    const float* W_claim2 = (const float*)d_in[12];
    const float* W2       = (const float*)d_in[13];
    const float* att_src2 = (const float*)d_in[14];
    const float* att_dst2 = (const float*)d_in[15];
    const float* b2       = (const float*)d_in[16];
    const float* W_fc     = (const float*)d_in[17];
    const float* b_fc     = (const float*)d_in[18];
    const float* W_clf    = (const float*)d_in[19];
    const float* b_clf    = (const float*)d_in[20];
    float* out = (float*)d_out;

    const int SMMC = (128 * LDS + 64 * LDS) * 2 * 2;   // 55296
    cudaFuncSetAttribute(k_final,  cudaFuncAttributeMaxDynamicSharedMemorySize, 65536);
    cudaFuncSetAttribute(k_mm0,    cudaFuncAttributeMaxDynamicSharedMemorySize, SMM0_TOT);
    cudaFuncSetAttribute(k_mmc<1>, cudaFuncAttributeMaxDynamicSharedMemorySize, SMMC);
    cudaFuncSetAttribute(k_mmc<2>, cudaFuncAttributeMaxDynamicSharedMemorySize, SMMC);
    cudaFuncSetAttribute(k_mmc<3>, cudaFuncAttributeMaxDynamicSharedMemorySize, SMMC);

    k_rootproj<<<NB, 256>>>(root, W_claim1, W_claim2);                  // 0
    k_convW<<<WTOT / 256, 256>>>(W_post1, W1, W_post2, W2);             // 1 (+zero scores)
    k_mm0<<<dim3(1, NN / 128), 256, SMM0_TOT>>>(x);                     // 2  PLA1
    k_mmc<1><<<dim3(4, NN / 128), 256, SMMC>>>(att_src1, att_dst1);     // 3  GAT1 lin+scores
    k_deg_init<<<NN / 256, 256>>>();                                    // 4
    k_deg<<<E2 / 256, 256>>>(ei);                                       // 5
    k_scan_all<<<1, 1024>>>();                                          // 6
    k_scatter<<<ETOT / 256, 256>>>(ei);                                 // 7

    k_agg<1><<<NN * 32 / 256, 256>>>(b1);
    k_mmc<2><<<dim3(1, NN * 4 / 128), 256, SMMC>>>(nullptr, nullptr);   // PLA2
    k_zs<<<NN * 8 / 256, 256>>>();                                      // zero layer-2 scores
    k_mmc<3><<<dim3(4, NN / 128), 256, SMMC>>>(att_src2, att_dst2);     // GAT2 lin+scores
    k_agg<0><<<NN * 32 / 256, 256>>>(b2);

    k_zero<<<NB * 128 / 256, 256>>>();
    k_final<<<NN / 256, 256, 65536>>>(W_fc, b_fc);
    k_logits<<<1, 128>>>(W_clf, b_clf, out);
}

// round 17
// speedup vs baseline: 1.8103x; 1.0444x over previous
#include <cuda_runtime.h>
#include <cuda_bf16.h>
#include <cstdint>

#define NN 65536      // nodes
#define NB 128        // graphs
#define NE 65536      // raw directed edges
#define E2 131072     // TD + BU
#define ETOT 196608   // + self loops
#define DIN 512
#define WTOT 200704   // total weight elements (all 4 matrices)

// ------------------------- scratch (device globals; no allocs) ---------------
__device__ uint32_t g_hfw[NN * 128];  // GAT lin output, packed bf16x2 (2ch/word)
__device__ float g_xr2[NN * 64];      // relu(GAT2 out)
__device__ float g_asrc[NN * 4];
__device__ float g_adst[NN * 4];
__device__ float g_hc1[NB * 64];
__device__ float g_hc2[NB * 64];
__device__ float g_gsum[NB * 128];
__device__ int   g_deg[NN];
__device__ int   g_rp [NN + 1];
__device__ int   g_cursor[NN];
__device__ int   g_col[ETOT];
// bf16 operand planes (converted exactly once)
__device__ __nv_bfloat16 g_h1b[NN * 128];   // PLA1 out (MODE1 A)
__device__ __nv_bfloat16 g_xrb[NN * 256];   // relu(GAT1) (MODE2 A)
__device__ __nv_bfloat16 g_x3b[NN * 512];   // PLA2 out (MODE3 A)
__device__ __nv_bfloat16 g_wtb[WTOT];       // transposed weights

// ------------------------- helpers -------------------------------------------
__device__ __forceinline__ uint32_t smem_u32(const void* p) {
    uint32_t a;
    asm("{ .reg .u64 t; cvta.to.shared.u64 t, %1; cvt.u32.u64 %0, t; }" : "=r"(a) : "l"(p));
    return a;
}
__device__ __forceinline__ void ldmat4(uint32_t& r0, uint32_t& r1, uint32_t& r2,
                                       uint32_t& r3, uint32_t addr) {
    asm volatile("ldmatrix.sync.aligned.m8n8.x4.shared.b16 {%0,%1,%2,%3}, [%4];"
        : "=r"(r0), "=r"(r1), "=r"(r2), "=r"(r3) : "r"(addr));
}
__device__ __forceinline__ void mma_bf16(float* c, const uint32_t* a, const uint32_t* b) {
    asm volatile("mma.sync.aligned.m16n8k16.row.col.f32.bf16.bf16.f32 "
        "{%0,%1,%2,%3}, {%4,%5,%6,%7}, {%8,%9}, {%0,%1,%2,%3};"
        : "+f"(c[0]), "+f"(c[1]), "+f"(c[2]), "+f"(c[3])
        : "r"(a[0]), "r"(a[1]), "r"(a[2]), "r"(a[3]), "r"(b[0]), "r"(b[1]));
}
__device__ __forceinline__ uint32_t pack_bf2(float a, float b) {
    __nv_bfloat162 t = __floats2bfloat162_rn(a, b);
    return *reinterpret_cast<uint32_t*>(&t);
}
#define CP16(dst, src) \
    asm volatile("cp.async.cg.shared.global [%0], [%1], 16;" :: "r"(dst), "l"(src))
#define CPCOMMIT() asm volatile("cp.async.commit_group;" ::: "memory")
#define CPWAIT0()  asm volatile("cp.async.wait_group 0;" ::: "memory")
#define CPWAIT1()  asm volatile("cp.async.wait_group 1;" ::: "memory")

// ------------------- weight pre-conversion + score zero + deg init ------------
__global__ void k_convW(const float* __restrict__ Wa, const float* __restrict__ Wb,
                        const float* __restrict__ Wc, const float* __restrict__ Wd) {
    int idx = blockIdx.x * 256 + threadIdx.x;
    const float* W; int K, N, local;
    if (idx < 32768)      { W = Wa; K = 512; N = 64;  local = idx; }
    else if (idx < 65536) { W = Wb; K = 128; N = 256; local = idx - 32768; }
    else if (idx < 69632) { W = Wc; K = 64;  N = 64;  local = idx - 65536; }
    else                  { W = Wd; K = 512; N = 256; local = idx - 69632; }
    int n = local / K, k = local - n * K;
    g_wtb[idx] = __float2bfloat16(W[(size_t)k * N + n]);
    if (idx < NN) g_deg[idx] = 1;                       // self loop
    for (int z = idx; z < NN * 4; z += WTOT) { g_asrc[z] = 0.f; g_adst[z] = 0.f; }
}

// ------------------------- CSR build -----------------------------------------
__global__ void k_deg(const int* __restrict__ ei) {
    int i = blockIdx.x * 256 + threadIdx.x;
    int d = (i < NE) ? ei[NE + i] : ei[i - NE];
    atomicAdd(&g_deg[d], 1);
}

__global__ void k_scan_all() {
    __shared__ int wsum[32];
    int tid = threadIdx.x, lane = tid & 31, wid = tid >> 5;
    int base = tid * 64;
    int s = 0;
    for (int i = 0; i < 64; i++) s += g_deg[base + i];
    int x = s;
#pragma unroll
    for (int o = 1; o < 32; o <<= 1) {
        int y = __shfl_up_sync(0xffffffffu, x, o);
        if (lane >= o) x += y;
    }
    if (lane == 31) wsum[wid] = x;
    __syncthreads();
    if (wid == 0) {
        int t = wsum[lane];
#pragma unroll
        for (int o = 1; o < 32; o <<= 1) {
            int y = __shfl_up_sync(0xffffffffu, t, o);
            if (lane >= o) t += y;
        }
        wsum[lane] = t;
    }
    __syncthreads();
    int run = (wid ? wsum[wid - 1] : 0) + x - s;
    for (int i = 0; i < 64; i++) {
        int v = g_deg[base + i];
        g_rp[base + i] = run;
        g_cursor[base + i] = run;
        run += v;
    }
    if (tid == 0) g_rp[NN] = ETOT;
}

__global__ void k_scatter(const int* __restrict__ ei) {
    int i = blockIdx.x * 256 + threadIdx.x;
    int s, d;
    if (i < NE)        { s = ei[i];          d = ei[NE + i]; }
    else if (i < E2)   { int e = i - NE; s = ei[NE + e]; d = ei[e]; }
    else               { s = d = i - E2; }
    int pos = atomicAdd(&g_cursor[d], 1);
    g_col[pos] = s;
}

// ------------------------- root projections (4-way split-K) -------------------
__global__ void k_rootproj(const float* __restrict__ root,
                           const float* __restrict__ Wc1,
                           const float* __restrict__ Wc2) {
    __shared__ float p1[256], p2[256];
    int b = blockIdx.x, t = threadIdx.x;
    int c = t & 63, kq = t >> 6;
    float a1 = 0.f, a2 = 0.f;
    for (int k = kq * 128; k < kq * 128 + 128; k++) {
        float rv = root[b * DIN + k];
        a1 += rv * Wc1[k * 64 + c];
        a2 += rv * Wc2[k * 64 + c];
    }
    p1[t] = a1; p2[t] = a2;
    __syncthreads();
    if (t < 64) {
        g_hc1[b * 64 + t] = p1[t] + p1[t + 64] + p1[t + 128] + p1[t + 192];
        g_hc2[b * 64 + t] = p2[t] + p2[t + 64] + p2[t + 128] + p2[t + 192];
    }
}

#define LDS 72            // padded smem row stride for k_mmc (bf16): 144B

// ------------------------- MODE0: x @ W_post1, cp.async fp32 staging ----------
#define XSTRIDE 36
#define PLDS 56
#define XS_BYTES 18432
#define OFF_AB 36864
#define OFF_B  51200
#define B_BYTES 7168
#define SMM0_TOT 65536

__launch_bounds__(256, 2)
__global__ void k_mm0(const float* __restrict__ Aarg) {
    extern __shared__ __align__(16) char sm[];
    int tid = threadIdx.x, lane = tid & 31, w = tid >> 5;
    int wm = (w & 1) * 64, wn = (w >> 1) * 16;
    const float* Arow = Aarg + (size_t)blockIdx.y * 128 * 512;
    __nv_bfloat16* Ab = (__nv_bfloat16*)(sm + OFF_AB);

    float acc[4][2][4];
#pragma unroll
    for (int a = 0; a < 4; a++)
#pragma unroll
        for (int b = 0; b < 2; b++)
#pragma unroll
            for (int c = 0; c < 4; c++) acc[a][b][c] = 0.f;

    auto stage = [&](int it, int buf) {
        int k0 = it * 32;
        float* Xs = (float*)(sm + buf * XS_BYTES);
        __nv_bfloat16* Bb = (__nv_bfloat16*)(sm + OFF_B + buf * B_BYTES);
#pragma unroll
        for (int i = 0; i < 4; i++) {
            int idx = i * 256 + tid;
            int r = idx >> 3, c4 = (idx & 7) << 2;
            CP16(smem_u32(&Xs[r * XSTRIDE + c4]), &Arow[(size_t)r * 512 + k0 + c4]);
        }
        {
            int n = tid >> 2, c8 = (tid & 3) << 3;
            CP16(smem_u32(&Bb[n * PLDS + c8]), &g_wtb[(size_t)n * 512 + k0 + c8]);
        }
        CPCOMMIT();
    };

    stage(0, 0);
    for (int it = 0; it < 16; it++) {
        int buf = it & 1;
        if (it + 1 < 16) { stage(it + 1, buf ^ 1); CPWAIT1(); }
        else             { CPWAIT0(); }
        __syncthreads();
        float* Xs = (float*)(sm + buf * XS_BYTES);
#pragma unroll
        for (int i = 0; i < 4; i++) {
            int idx = i * 256 + tid;
            int r = idx >> 3, c4 = (idx & 7) << 2;
            float4 v = *(const float4*)&Xs[r * XSTRIDE + c4];
            *(uint2*)&Ab[r * PLDS + c4] = make_uint2(pack_bf2(v.x, v.y), pack_bf2(v.z, v.w));
        }
        __syncthreads();
        __nv_bfloat16* Bb = (__nv_bfloat16*)(sm + OFF_B + buf * B_BYTES);
#pragma unroll
        for (int ks = 0; ks < 2; ks++) {
            int kb = ks * 16;
            uint32_t ah[4][4], bh[2][2];
            int arow = wm + (lane & 15);
            int acol = kb + (lane >> 4) * 8;
#pragma unroll
            for (int mf = 0; mf < 4; mf++)
                ldmat4(ah[mf][0], ah[mf][1], ah[mf][2], ah[mf][3],
                       smem_u32(&Ab[(arow + mf * 16) * PLDS + acol]));
            {
                int rr = lane & 7, g = lane >> 3;
                ldmat4(bh[0][0], bh[0][1], bh[1][0], bh[1][1],
                       smem_u32(&Bb[(wn + (g >> 1) * 8 + rr) * PLDS + kb + (g & 1) * 8]));
            }
#pragma unroll
            for (int mf = 0; mf < 4; mf++)
#pragma unroll
                for (int nf = 0; nf < 2; nf++)
                    mma_bf16(acc[mf][nf], ah[mf], bh[nf]);
        }
        __syncthreads();
    }

#pragma unroll
    for (int mf = 0; mf < 4; mf++)
#pragma unroll
        for (int nf = 0; nf < 2; nf++)
#pragma unroll
            for (int p = 0; p < 2; p++) {
                int row = blockIdx.y * 128 + wm + mf * 16 + (lane >> 2) + p * 8;
                int c   = wn + nf * 8 + (lane & 3) * 2;
                float v0 = acc[mf][nf][p * 2 + 0];
                float v1 = acc[mf][nf][p * 2 + 1];
                int gid = row >> 9;
                float hc0 = g_hc1[gid * 64 + c];
                float hc1 = g_hc1[gid * 64 + c + 1];
                float gs0 = 1.f / (1.f + __expf(-(v0 + hc0)));
                float gs1 = 1.f / (1.f + __expf(-(v1 + hc1)));
                float gv0 = gs0 * v0 + (1.f - gs0) * hc0;
                float gv1 = gs1 * v1 + (1.f - gs1) * hc1;
                size_t b0 = (size_t)row * 128 + c;
                *(uint32_t*)&g_h1b[b0]      = pack_bf2(gv0, gv1);
                *(uint32_t*)&g_h1b[b0 + 64] = pack_bf2(v0, v1);
            }
}

// ------------------- MODE 1/2/3: pure-copy, cp.async double-buffered ----------
// MODE 1: g_h1 @ W1      (K=128, NT=128) -> g_hfw + scores  grid(2, 512)
// MODE 2: g_xr @ W_post2 (K=64,  NT=64)  -> PLA2 -> g_x3b   grid(1, 2048) (+zs)
// MODE 3: g_x3 @ W2      (K=512, NT=128) -> g_hfw + scores  grid(2, 512)
template <int MODE>
__launch_bounds__(256, (MODE == 2) ? 3 : 2)
__global__ void k_mmc(const float* __restrict__ as_, const float* __restrict__ ad_) {
    constexpr int K    = (MODE == 3) ? 512 : (MODE == 1 ? 128 : 64);
    constexpr int KT   = K / 64;
    constexpr int WOFF = (MODE == 1) ? 32768 : (MODE == 2) ? 65536 : 69632;
    constexpr int NT   = (MODE == 2) ? 64 : 128;
    constexpr int NF   = NT / 32;            // 2 or 4
    constexpr int ASZ  = 128 * LDS;
    constexpr int BSZ  = NT * LDS;
    constexpr int STG  = ASZ + BSZ;

    extern __shared__ __align__(16) char sm[];
    __nv_bfloat16* base = (__nv_bfloat16*)sm;

    int tid = threadIdx.x, lane = tid & 31, w = tid >> 5;
    int wm = (w & 1) * 64, wn = (w >> 1) * (NT / 4);
    int n0 = blockIdx.x * NT;

    const __nv_bfloat16* Apb = ((MODE == 1) ? g_h1b : (MODE == 2) ? g_xrb : g_x3b)
                             + (size_t)blockIdx.y * 128 * K;

    float acc[4][NF][4];
#pragma unroll
    for (int a = 0; a < 4; a++)
#pragma unroll
        for (int b = 0; b < NF; b++)
#pragma unroll
            for (int c = 0; c < 4; c++) acc[a][b][c] = 0.f;

    auto stage = [&](int k0, int buf) {
        __nv_bfloat16* Ab = base + buf * STG;
        __nv_bfloat16* Bb = Ab + ASZ;
#pragma unroll
        for (int i = 0; i < 4; i++) {
            int idx = i * 256 + tid;
            int r = idx >> 3, c8 = (idx & 7) << 3;
            CP16(smem_u32(&Ab[r * LDS + c8]), &Apb[(size_t)r * K + k0 + c8]);
        }
#pragma unroll
        for (int i = 0; i < NT / 32; i++) {
            int idx = i * 256 + tid;
            int n = idx >> 3, c8 = (idx & 7) << 3;
            CP16(smem_u32(&Bb[n * LDS + c8]),
                 &g_wtb[(size_t)WOFF + (size_t)(n0 + n) * K + k0 + c8]);
        }
        CPCOMMIT();
    };

    stage(0, 0);
    int buf = 0;
    for (int it = 0; it < KT; it++) {
        if (it + 1 < KT) { stage((it + 1) * 64, buf ^ 1); CPWAIT1(); }
        else             { CPWAIT0(); }
        __syncthreads();
        __nv_bfloat16* Ab = base + buf * STG;
        __nv_bfloat16* Bb = Ab + ASZ;
#pragma unroll
        for (int ks = 0; ks < 4; ks++) {
            int kb = ks * 16;
            uint32_t ah[4][4], bh[NF][2];
            int arow = wm + (lane & 15);
            int acol = kb + (lane >> 4) * 8;
#pragma unroll
            for (int mf = 0; mf < 4; mf++)
                ldmat4(ah[mf][0], ah[mf][1], ah[mf][2], ah[mf][3],
                       smem_u32(&Ab[(arow + mf * 16) * LDS + acol]));
            {
                int rr = lane & 7, g = lane >> 3;
#pragma unroll
                for (int p = 0; p < NF / 2; p++)
                    ldmat4(bh[p * 2][0], bh[p * 2][1], bh[p * 2 + 1][0], bh[p * 2 + 1][1],
                           smem_u32(&Bb[(wn + p * 16 + (g >> 1) * 8 + rr) * LDS
                                        + kb + (g & 1) * 8]));
            }
#pragma unroll
            for (int mf = 0; mf < 4; mf++)
#pragma unroll
                for (int nf = 0; nf < NF; nf++)
                    mma_bf16(acc[mf][nf], ah[mf], bh[nf]);
        }
        __syncthreads();
        buf ^= 1;
    }

    if (MODE == 1 || MODE == 3) {
        int h = (n0 + wn) >> 6;   // warp's 32-channel span stays in one head
#pragma unroll
        for (int mf = 0; mf < 4; mf++)
#pragma unroll
            for (int p = 0; p < 2; p++) {
                int row = blockIdx.y * 128 + wm + mf * 16 + (lane >> 2) + p * 8;
                float ps = 0.f, pd = 0.f;
#pragma unroll
                for (int nf = 0; nf < NF; nf++) {
                    int c = wn + nf * 8 + (lane & 3) * 2;
                    float v0 = acc[mf][nf][p * 2 + 0];
                    float v1 = acc[mf][nf][p * 2 + 1];
                    g_hfw[(size_t)row * 128 + ((n0 + c) >> 1)] = pack_bf2(v0, v1);
                    ps += v0 * as_[n0 + c] + v1 * as_[n0 + c + 1];
                    pd += v0 * ad_[n0 + c] + v1 * ad_[n0 + c + 1];
                }
                ps += __shfl_xor_sync(0xffffffffu, ps, 1);
                ps += __shfl_xor_sync(0xffffffffu, ps, 2);
                pd += __shfl_xor_sync(0xffffffffu, pd, 1);
                pd += __shfl_xor_sync(0xffffffffu, pd, 2);
                if ((lane & 3) == 0) {
                    atomicAdd(&g_asrc[row * 4 + h], ps);
                    atomicAdd(&g_adst[row * 4 + h], pd);
                }
            }
    } else {
#pragma unroll
        for (int mf = 0; mf < 4; mf++)
#pragma unroll
            for (int nf = 0; nf < NF; nf++)
#pragma unroll
                for (int p = 0; p < 2; p++) {
                    int row = blockIdx.y * 128 + wm + mf * 16 + (lane >> 2) + p * 8;
                    int c   = wn + nf * 8 + (lane & 3) * 2;
                    float v0 = acc[mf][nf][p * 2 + 0];
                    float v1 = acc[mf][nf][p * 2 + 1];
                    int gid = row >> 11;
                    float hc0 = g_hc2[gid * 64 + c];
                    float hc1 = g_hc2[gid * 64 + c + 1];
                    float gs0 = 1.f / (1.f + __expf(-(v0 + hc0)));
                    float gs1 = 1.f / (1.f + __expf(-(v1 + hc1)));
                    float gv0 = gs0 * v0 + (1.f - gs0) * hc0;
                    float gv1 = gs1 * v1 + (1.f - gs1) * hc1;
                    size_t b0 = (size_t)row * 128 + c;
                    *(uint32_t*)&g_x3b[b0]      = pack_bf2(gv0, gv1);
                    *(uint32_t*)&g_x3b[b0 + 64] = pack_bf2(v0, v1);
                }
        // fused score zeroing for layer 2 (2048 blocks x 128 entries each)
        int zb = blockIdx.y * 128;
        if (tid < 128)      g_asrc[zb + tid] = 0.f;
        else                g_adst[zb + tid - 128] = 0.f;
    }
}

// ------------------------- GAT aggregation (warp per dst) --------------------
__device__ __forceinline__ float lrelu(float x) { return x > 0.f ? x : 0.2f * x; }

template <int CONCAT>
__launch_bounds__(256)
__global__ void k_agg(const float* __restrict__ bias) {
    int n = (blockIdx.x * 256 + threadIdx.x) >> 5;
    int lane = threadIdx.x & 31;
    int rs = g_rp[n], re = g_rp[n + 1];
    int deg = re - rs;
    float ad0 = g_adst[n * 4 + 0], ad1 = g_adst[n * 4 + 1];
    float ad2 = g_adst[n * 4 + 2], ad3 = g_adst[n * 4 + 3];

    float aLo[4] = {0, 0, 0, 0}, aHi[4] = {0, 0, 0, 0};

    if (deg <= 32) {
        int sj = -1;
        float e0 = -1e30f, e1 = -1e30f, e2 = -1e30f, e3 = -1e30f;
        if (lane < deg) {
            sj = g_col[rs + lane];
            e0 = lrelu(g_asrc[sj * 4 + 0] + ad0);
            e1 = lrelu(g_asrc[sj * 4 + 1] + ad1);
            e2 = lrelu(g_asrc[sj * 4 + 2] + ad2);
            e3 = lrelu(g_asrc[sj * 4 + 3] + ad3);
        }
        float m0 = e0, m1 = e1, m2 = e2, m3 = e3;
#pragma unroll
        for (int o = 16; o; o >>= 1) {
            m0 = fmaxf(m0, __shfl_xor_sync(0xffffffffu, m0, o));
            m1 = fmaxf(m1, __shfl_xor_sync(0xffffffffu, m1, o));
            m2 = fmaxf(m2, __shfl_xor_sync(0xffffffffu, m2, o));
            m3 = fmaxf(m3, __shfl_xor_sync(0xffffffffu, m3, o));
        }
        float x0 = (lane < deg) ? __expf(e0 - m0) : 0.f;
        float x1 = (lane < deg) ? __expf(e1 - m1) : 0.f;
        float x2 = (lane < deg) ? __expf(e2 - m2) : 0.f;
        float x3 = (lane < deg) ? __expf(e3 - m3) : 0.f;
        float d0 = x0, d1 = x1, d2 = x2, d3 = x3;
#pragma unroll
        for (int o = 16; o; o >>= 1) {
            d0 += __shfl_xor_sync(0xffffffffu, d0, o);
            d1 += __shfl_xor_sync(0xffffffffu, d1, o);
            d2 += __shfl_xor_sync(0xffffffffu, d2, o);
            d3 += __shfl_xor_sync(0xffffffffu, d3, o);
        }
        float w0 = x0 / d0, w1 = x1 / d1, w2 = x2 / d2, w3 = x3 / d3;

        for (int j = 0; j < deg; j++) {
            int s = __shfl_sync(0xffffffffu, sj, j);
            float wv0 = __shfl_sync(0xffffffffu, w0, j);
            float wv1 = __shfl_sync(0xffffffffu, w1, j);
            float wv2 = __shfl_sync(0xffffffffu, w2, j);
            float wv3 = __shfl_sync(0xffffffffu, w3, j);
            const uint32_t* hw = g_hfw + (size_t)s * 128;
            uint32_t p0 = hw[lane],      p1 = hw[32 + lane];
            uint32_t p2 = hw[64 + lane], p3 = hw[96 + lane];
            float2 f0 = __bfloat1622float2(*reinterpret_cast<__nv_bfloat162*>(&p0));
            float2 f1 = __bfloat1622float2(*reinterpret_cast<__nv_bfloat162*>(&p1));
            float2 f2 = __bfloat1622float2(*reinterpret_cast<__nv_bfloat162*>(&p2));
            float2 f3 = __bfloat1622float2(*reinterpret_cast<__nv_bfloat162*>(&p3));
            aLo[0] += wv0 * f0.x; aHi[0] += wv0 * f0.y;
            aLo[1] += wv1 * f1.x; aHi[1] += wv1 * f1.y;
            aLo[2] += wv2 * f2.x; aHi[2] += wv2 * f2.y;
            aLo[3] += wv3 * f3.x; aHi[3] += wv3 * f3.y;
        }
    } else {
        float m0 = -1e30f, m1 = -1e30f, m2 = -1e30f, m3 = -1e30f;
        for (int j = rs + lane; j < re; j += 32) {
            int s = g_col[j];
            m0 = fmaxf(m0, lrelu(g_asrc[s * 4 + 0] + ad0));
            m1 = fmaxf(m1, lrelu(g_asrc[s * 4 + 1] + ad1));
            m2 = fmaxf(m2, lrelu(g_asrc[s * 4 + 2] + ad2));
            m3 = fmaxf(m3, lrelu(g_asrc[s * 4 + 3] + ad3));
        }
#pragma unroll
        for (int o = 16; o; o >>= 1) {
            m0 = fmaxf(m0, __shfl_xor_sync(0xffffffffu, m0, o));
            m1 = fmaxf(m1, __shfl_xor_sync(0xffffffffu, m1, o));
            m2 = fmaxf(m2, __shfl_xor_sync(0xffffffffu, m2, o));
            m3 = fmaxf(m3, __shfl_xor_sync(0xffffffffu, m3, o));
        }
        float d0 = 0.f, d1 = 0.f, d2 = 0.f, d3 = 0.f;
        for (int j = rs + lane; j < re; j += 32) {
            int s = g_col[j];
            d0 += __expf(lrelu(g_asrc[s * 4 + 0] + ad0) - m0);
            d1 += __expf(lrelu(g_asrc[s * 4 + 1] + ad1) - m1);
            d2 += __expf(lrelu(g_asrc[s * 4 + 2] + ad2) - m2);
            d3 += __expf(lrelu(g_asrc[s * 4 + 3] + ad3) - m3);
        }
#pragma unroll
        for (int o = 16; o; o >>= 1) {
            d0 += __shfl_xor_sync(0xffffffffu, d0, o);
            d1 += __shfl_xor_sync(0xffffffffu, d1, o);
            d2 += __shfl_xor_sync(0xffffffffu, d2, o);
            d3 += __shfl_xor_sync(0xffffffffu, d3, o);
        }
        float i0 = 1.f / d0, i1 = 1.f / d1, i2 = 1.f / d2, i3 = 1.f / d3;
        for (int j = rs; j < re; j++) {
            int s = g_col[j];
            float wv0 = __expf(lrelu(g_asrc[s * 4 + 0] + ad0) - m0) * i0;
            float wv1 = __expf(lrelu(g_asrc[s * 4 + 1] + ad1) - m1) * i1;
            float wv2 = __expf(lrelu(g_asrc[s * 4 + 2] + ad2) - m2) * i2;
            float wv3 = __expf(lrelu(g_asrc[s * 4 + 3] + ad3) - m3) * i3;
            const uint32_t* hw = g_hfw + (size_t)s * 128;
            uint32_t p0 = hw[lane],      p1 = hw[32 + lane];
            uint32_t p2 = hw[64 + lane], p3 = hw[96 + lane];
            float2 f0 = __bfloat1622float2(*reinterpret_cast<__nv_bfloat162*>(&p0));
            float2 f1 = __bfloat1622float2(*reinterpret_cast<__nv_bfloat162*>(&p1));
            float2 f2 = __bfloat1622float2(*reinterpret_cast<__nv_bfloat162*>(&p2));
            float2 f3 = __bfloat1622float2(*reinterpret_cast<__nv_bfloat162*>(&p3));
            aLo[0] += wv0 * f0.x; aHi[0] += wv0 * f0.y;
            aLo[1] += wv1 * f1.x; aHi[1] += wv1 * f1.y;
            aLo[2] += wv2 * f2.x; aHi[2] += wv2 * f2.y;
            aLo[3] += wv3 * f3.x; aHi[3] += wv3 * f3.y;
        }
    }

    if (CONCAT) {
#pragma unroll
        for (int h = 0; h < 4; h++) {
            int c = h * 64 + 2 * lane;
            float2 bv = *(const float2*)&bias[c];
            float v0 = fmaxf(aLo[h] + bv.x, 0.f);
            float v1 = fmaxf(aHi[h] + bv.y, 0.f);
            *(uint32_t*)&g_xrb[(size_t)n * 256 + c] = pack_bf2(v0, v1);
        }
    } else {
        float2 bv = *(const float2*)&bias[2 * lane];
        float o0 = 0.25f * (aLo[0] + aLo[1] + aLo[2] + aLo[3]) + bv.x;
        float o1 = 0.25f * (aHi[0] + aHi[1] + aHi[2] + aHi[3]) + bv.y;
        ((float2*)g_xr2)[(size_t)n * 32 + lane] =
            make_float2(fmaxf(o0, 0.f), fmaxf(o1, 0.f));
    }
}

// ------------------------- scorer head + pooling -----------------------------
__global__ void k_zero() { g_gsum[blockIdx.x * 256 + threadIdx.x] = 0.f; }

__launch_bounds__(256)
__global__ void k_final(const float* __restrict__ Wfc, const float* __restrict__ bfc) {
    extern __shared__ float Ws[];
    __shared__ float s_hc3[64];
    __shared__ float part_sh[8][64];
    __shared__ float part_ss[8][64];
    int tid = threadIdx.x, lane = tid & 31, w = tid >> 5;
    int g = blockIdx.x >> 1;

    for (int i = tid; i < 4096; i += 256)
        ((float4*)Ws)[i] = ((const float4*)Wfc)[i];
    if (tid < 64) s_hc3[tid] = g_xr2[((size_t)g << 9) * 64 + tid];
    __syncthreads();

    float bL = bfc[lane], bH = bfc[lane + 32];
    float shL = 0.f, shH = 0.f, ssL = 0.f, ssH = 0.f;
    int nbase = blockIdx.x * 256 + w * 32;

    for (int g4 = 0; g4 < 8; g4++) {
        int n0 = nbase + g4 * 4;
        float xl[4], xh[4], aL[4], aH[4];
#pragma unroll
        for (int u = 0; u < 4; u++) {
            xl[u] = g_xr2[(size_t)(n0 + u) * 64 + lane];
            xh[u] = g_xr2[(size_t)(n0 + u) * 64 + lane + 32];
            aL[u] = bL; aH[u] = bH;
        }
#pragma unroll 4
        for (int j = 0; j < 64; j++) {
            float h3 = s_hc3[j];
            float w0 = Ws[j * 64 + lane];
            float w1 = Ws[(64 + j) * 64 + lane];
            float w2 = Ws[(128 + j) * 64 + lane];
            float w3 = Ws[(192 + j) * 64 + lane];
            float v0 = Ws[j * 64 + lane + 32];
            float v1 = Ws[(64 + j) * 64 + lane + 32];
            float v2 = Ws[(128 + j) * 64 + lane + 32];
            float v3 = Ws[(192 + j) * 64 + lane + 32];
#pragma unroll
            for (int u = 0; u < 4; u++) {
                float xj = (j < 32) ? __shfl_sync(0xffffffffu, xl[u], j)
                                    : __shfl_sync(0xffffffffu, xh[u], j - 32);
                float p = xj * h3;
                float q = fabsf(h3 - xj);
                aL[u] += h3 * w0 + xj * w1 + p * w2 + q * w3;
                aH[u] += h3 * v0 + xj * v1 + p * v2 + q * v3;
            }
        }
#pragma unroll
        for (int u = 0; u < 4; u++) {
            float tL = tanhf(aL[u]), tH = tanhf(aH[u]);
            float mx = fmaxf(tL, tH);
#pragma unroll
            for (int o = 16; o; o >>= 1) mx = fmaxf(mx, __shfl_xor_sync(0xffffffffu, mx, o));
            float eL = __expf(tL - mx), eH = __expf(tH - mx);
            float sm = eL + eH;
#pragma unroll
            for (int o = 16; o; o >>= 1) sm += __shfl_xor_sync(0xffffffffu, sm, o);
            float inv = 1.f / sm;
            shL += eL * inv * xl[u]; shH += eH * inv * xh[u];
            ssL += xl[u];            ssH += xh[u];
        }
    }
    part_sh[w][lane] = shL; part_sh[w][lane + 32] = shH;
    part_ss[w][lane] = ssL; part_ss[w][lane + 32] = ssH;
    __syncthreads();
    if (tid < 128) {
        int c = tid & 63;
        float s = 0.f;
        if (tid < 64) {
            for (int ww = 0; ww < 8; ww++) s += part_sh[ww][c];
            atomicAdd(&g_gsum[g * 128 + c], s);
        } else {
            for (int ww = 0; ww < 8; ww++) s += part_ss[ww][c];
            atomicAdd(&g_gsum[g * 128 + 64 + c], s);
        }
    }
}

__global__ void k_logits(const float* __restrict__ Wc, const float* __restrict__ bc,
                         float* __restrict__ out) {
    int b = threadIdx.x;
    float l[4] = {bc[0], bc[1], bc[2], bc[3]};
    const float inv = 1.f / 512.f;
    for (int j = 0; j < 128; j++) {
        float v = g_gsum[b * 128 + j] * inv;
#pragma unroll
        for (int c = 0; c < 4; c++) l[c] += v * Wc[j * 4 + c];
    }
    float mx = fmaxf(fmaxf(l[0], l[1]), fmaxf(l[2], l[3]));
    float s = expf(l[0] - mx) + expf(l[1] - mx) + expf(l[2] - mx) + expf(l[3] - mx);
    float lse = mx + logf(s);
#pragma unroll
    for (int c = 0; c < 4; c++) out[b * 4 + c] = l[c] - lse;
}

// ------------------------- launch --------------------------------------------
extern "C" void kernel_launch(void* const* d_in, const int* in_sizes, int n_in,
                              void* d_out, int out_size) {
    const float* x        = (const float*)d_in[0];
    const float* root     = (const float*)d_in[1];
    const int*   ei       = (const int*)d_in[2];
    const float* W_post1  = (const float*)d_in[5];
    const float* W_claim1 = (const float*)d_in[6];
    const float* W1       = (const float*)d_in[7];
    const float* att_src1 = (const float*)d_in[8];
    const float* att_dst1 = (const float*)d_in[9];
    const float* b1       = (const float*)d_in[10];
    const float* W_post2  = (const float*)d_in[11];
    const float* W_claim2 = (const float*)d_in[12];
    const float* W2       = (const float*)d_in[13];
    const float* att_src2 = (const float*)d_in[14];
    const float* att_dst2 = (const float*)d_in[15];
    const float* b2       = (const float*)d_in[16];
    const float* W_fc     = (const float*)d_in[17];
    const float* b_fc     = (const float*)d_in[18];
    const float* W_clf    = (const float*)d_in[19];
    const float* b_clf    = (const float*)d_in[20];
    float* out = (float*)d_out;

    const int SMM2 = (128 + 64)  * LDS * 2 * 2;   // 55296 (NT=64)
    const int SMMW = (128 + 128) * LDS * 2 * 2;   // 73728 (NT=128)
    cudaFuncSetAttribute(k_final,  cudaFuncAttributeMaxDynamicSharedMemorySize, 65536);
    cudaFuncSetAttribute(k_mm0,    cudaFuncAttributeMaxDynamicSharedMemorySize, SMM0_TOT);
    cudaFuncSetAttribute(k_mmc<1>, cudaFuncAttributeMaxDynamicSharedMemorySize, SMMW);
    cudaFuncSetAttribute(k_mmc<2>, cudaFuncAttributeMaxDynamicSharedMemorySize, SMM2);
    cudaFuncSetAttribute(k_mmc<3>, cudaFuncAttributeMaxDynamicSharedMemorySize, SMMW);

    k_rootproj<<<NB, 256>>>(root, W_claim1, W_claim2);                  // 0
    k_convW<<<WTOT / 256, 256>>>(W_post1, W1, W_post2, W2);             // 1 (+deg+zs)
    k_mm0<<<dim3(1, NN / 128), 256, SMM0_TOT>>>(x);                     // 2  PLA1
    k_mmc<1><<<dim3(2, NN / 128), 256, SMMW>>>(att_src1, att_dst1);     // 3  GAT1 lin+scores
    k_deg<<<E2 / 256, 256>>>(ei);                                       // 4
    k_scan_all<<<1, 1024>>>();                                          // 5
    k_scatter<<<ETOT / 256, 256>>>(ei);                                 // 6

    k_agg<1><<<NN * 32 / 256, 256>>>(b1);
    k_mmc<2><<<dim3(1, NN * 4 / 128), 256, SMM2>>>(nullptr, nullptr);   // PLA2 (+zs)
    k_mmc<3><<<dim3(2, NN / 128), 256, SMMW>>>(att_src2, att_dst2);     // GAT2 lin+scores
    k_agg<0><<<NN * 32 / 256, 256>>>(b2);

    k_zero<<<NB * 128 / 256, 256>>>();
    k_final<<<NN / 256, 256, 65536>>>(W_fc, b_fc);
    k_logits<<<1, 128>>>(W_clf, b_clf, out);
}